// round 6
// baseline (speedup 1.0000x reference)
#include <cuda_runtime.h>
#include <math.h>

// ------------------------- problem constants -------------------------
constexpr int kNI = 8192, kND = 4096, kNT = 12288, kD = 256, kH = 4, kDH = 64;
constexpr int kB = 8, kKP = 768;
constexpr int kEC = 65536, kEI = 32768, kEO = 32768, kEK = 8192;
constexpr long LXD = (long)kNT * kD;          // full node-feature buffer
constexpr long LPD = (long)kB * kKP * kD;     // pooled buffer

// ------------------------- scratch (static device memory) -------------------------
struct Scratch {
    float x[LXD], yF[LXD], yR[LXD], Kb[LXD], Qb[LXD], Vb[LXD], agg[LXD];
    float Krel[4L * kNI * kD], Vrel[4L * kNI * kD];
    float S[(long)kB * kH * kKP * kKP];
    float xp[LPD], qb[LPD], kb[LPD], vb[LPD], oh[LPD], yb[LPD], ga[LPD];
    float hv[kNT], sc[kNT];
    float sv[kB * kKP];
    int   si[kB * kKP];
    float u[2 * kB * 512];
    int rpf0[kNI + 1], rpf1[kND + 1], rpr0[kNI + 1], rpr1[kND + 1], rph[kNT + 1];
    int ef0[kEC + kEI + kEK], ef1[kEO], er0[kEC + kEO + kEK], er1[kEI];
    int eh[kEC + kEI + kEO + kEK + kNT];
    int cnt[kNT], cur[kNT];
};
__device__ Scratch SC;

// ------------------------- reductions -------------------------
__device__ __forceinline__ float wsum(float v) {
#pragma unroll
    for (int o = 16; o; o >>= 1) v += __shfl_xor_sync(0xffffffffu, v, o);
    return v;
}
__device__ __forceinline__ float bsum(float v) {
    __shared__ float sh[32];
    int lane = threadIdx.x & 31, w = threadIdx.x >> 5;
    v = wsum(v);
    if (!lane) sh[w] = v;
    __syncthreads();
    int nw = blockDim.x >> 5;
    float s = (threadIdx.x < nw) ? sh[threadIdx.x] : 0.f;
    if (w == 0) s = wsum(s);
    if (threadIdx.x == 0) sh[0] = s;
    __syncthreads();
    float r = sh[0];
    __syncthreads();
    return r;
}
__device__ __forceinline__ float bmax(float v) {
    __shared__ float sh[32];
    int lane = threadIdx.x & 31, w = threadIdx.x >> 5;
#pragma unroll
    for (int o = 16; o; o >>= 1) v = fmaxf(v, __shfl_xor_sync(0xffffffffu, v, o));
    if (!lane) sh[w] = v;
    __syncthreads();
    int nw = blockDim.x >> 5;
    float s = (threadIdx.x < nw) ? sh[threadIdx.x] : -INFINITY;
    if (w == 0)
#pragma unroll
        for (int o = 16; o; o >>= 1) s = fmaxf(s, __shfl_xor_sync(0xffffffffu, s, o));
    if (threadIdx.x == 0) sh[0] = s;
    __syncthreads();
    float r = sh[0];
    __syncthreads();
    return r;
}

// ------------------------- f32x2 packed-FMA GEMM -------------------------
// C = epilogue(alpha * A @ B(^T)); z-batched: z -> (zb = z/ZH, zh = z%ZH).
// BM=128, BK=8, BN template in {128, 64}. 256 threads.
// Per-thread microtile: TM rows x 8 cols, accumulated as 4 packed f32x2.
// mode 0: C = v
// mode 1: C = g*v + (1-g)*Add,  g = sigmoid(*gptr)
// mode 2: C = v + Add
template <int BN, bool TB>
__global__ void __launch_bounds__(256) gemm_k(
    const float* __restrict__ A, int lda, long Ab, long Ah,
    const float* __restrict__ Bm, int ldb, long Bb, long Bh,
    float* __restrict__ C, int ldc, long Cb, long Ch,
    const float* __restrict__ Add, int ldadd, const float* __restrict__ gptr,
    int Kdim, int ZH, float alpha, int mode)
{
    constexpr int BM = 128, BK = 8;
    constexpr int TX = BN / 8;                 // column groups (8 cols each)
    constexpr int TM = (BM * BN) / (256 * 8);  // rows per thread (8 or 4)
    __shared__ __align__(16) float As[BK][BM + 4];
    __shared__ __align__(16) float Bs[BK][BN + 4];

    int z = blockIdx.z, zb = z / ZH, zh = z - zb * ZH;
    A  += zb * Ab + zh * Ah;
    Bm += zb * Bb + zh * Bh;
    C  += zb * Cb + zh * Ch;
    int m0 = blockIdx.x * BM, n0 = blockIdx.y * BN;
    int tid = threadIdx.x;
    int tx = tid % TX, ty = tid / TX;

    unsigned long long acc[TM][4] = {};

    int aR = tid >> 1, aC = (tid & 1) * 4;

    for (int k0 = 0; k0 < Kdim; k0 += BK) {
        // A tile: 128 x 8, stored transposed As[k][m]
        {
            float4 av = *(const float4*)(A + (long)(m0 + aR) * lda + k0 + aC);
            As[aC + 0][aR] = av.x; As[aC + 1][aR] = av.y;
            As[aC + 2][aR] = av.z; As[aC + 3][aR] = av.w;
        }
        // B tile: Bs[k][n]
        if (TB) {
            if (BN == 128) {
                int bR = tid >> 1, bC = (tid & 1) * 4;
                float4 bv = *(const float4*)(Bm + (long)(n0 + bR) * ldb + k0 + bC);
                Bs[bC + 0][bR] = bv.x; Bs[bC + 1][bR] = bv.y;
                Bs[bC + 2][bR] = bv.z; Bs[bC + 3][bR] = bv.w;
            } else if (tid < 128) {
                int bR = tid >> 1, bC = (tid & 1) * 4;
                float4 bv = *(const float4*)(Bm + (long)(n0 + bR) * ldb + k0 + bC);
                Bs[bC + 0][bR] = bv.x; Bs[bC + 1][bR] = bv.y;
                Bs[bC + 2][bR] = bv.z; Bs[bC + 3][bR] = bv.w;
            }
        } else {
            if (BN == 128) {
                int bR = tid >> 5, bC = (tid & 31) * 4;
                *(float4*)&Bs[bR][bC] =
                    *(const float4*)(Bm + (long)(k0 + bR) * ldb + n0 + bC);
            } else if (tid < 128) {
                int bR = tid >> 4, bC = (tid & 15) * 4;
                *(float4*)&Bs[bR][bC] =
                    *(const float4*)(Bm + (long)(k0 + bR) * ldb + n0 + bC);
            }
        }
        __syncthreads();
#pragma unroll
        for (int kk = 0; kk < BK; kk++) {
            float a[TM];
#pragma unroll
            for (int i = 0; i < TM; i += 4)
                *(float4*)&a[i] = *(const float4*)&As[kk][ty * TM + i];
            ulonglong2 b01 = *(const ulonglong2*)&Bs[kk][tx * 8];
            ulonglong2 b23 = *(const ulonglong2*)&Bs[kk][tx * 8 + 4];
            unsigned long long bb0 = b01.x, bb1 = b01.y, bb2 = b23.x, bb3 = b23.y;
#pragma unroll
            for (int i = 0; i < TM; i++) {
                unsigned long long a2;
                asm("mov.b64 %0, {%1, %1};" : "=l"(a2) : "r"(__float_as_uint(a[i])));
                asm("fma.rn.f32x2 %0, %1, %2, %0;" : "+l"(acc[i][0]) : "l"(a2), "l"(bb0));
                asm("fma.rn.f32x2 %0, %1, %2, %0;" : "+l"(acc[i][1]) : "l"(a2), "l"(bb1));
                asm("fma.rn.f32x2 %0, %1, %2, %0;" : "+l"(acc[i][2]) : "l"(a2), "l"(bb2));
                asm("fma.rn.f32x2 %0, %1, %2, %0;" : "+l"(acc[i][3]) : "l"(a2), "l"(bb3));
            }
        }
        __syncthreads();
    }

    float g = 1.f;
    if (mode == 1) g = 1.f / (1.f + expf(-gptr[0]));
#pragma unroll
    for (int i = 0; i < TM; i++) {
        long r = m0 + ty * TM + i;
#pragma unroll
        for (int j = 0; j < 4; j++) {
            long c = n0 + tx * 8 + j * 2;
            float vx, vy;
            asm("mov.b64 {%0, %1}, %2;" : "=f"(vx), "=f"(vy) : "l"(acc[i][j]));
            vx *= alpha; vy *= alpha;
            if (mode == 1) {
                float2 ad = *(const float2*)(Add + r * ldadd + c);
                vx = g * vx + (1.f - g) * ad.x;
                vy = g * vy + (1.f - g) * ad.y;
            } else if (mode == 2) {
                float2 ad = *(const float2*)(Add + r * ldadd + c);
                vx += ad.x; vy += ad.y;
            }
            float2 o; o.x = vx; o.y = vy;
            *(float2*)(C + r * ldc + c) = o;
        }
    }
}

// ------------------------- elementwise kernels -------------------------
__global__ void gelu_k(const float* __restrict__ in, float* __restrict__ out, long n) {
    long i = (long)blockIdx.x * blockDim.x + threadIdx.x;
    if (i < n) {
        float v = in[i];
        out[i] = 0.5f * v * (1.f + erff(v * 0.7071067811865475f));
    }
}
__global__ void comb_relu_k(const float* __restrict__ a, const float* __restrict__ b,
                            float* __restrict__ x, long n) {
    long i = (long)blockIdx.x * blockDim.x + threadIdx.x;
    if (i < n) {
        float v = 0.5f * a[i] + 0.5f * b[i];
        x[i] = v > 0.f ? v : 0.f;
    }
}

// ------------------------- CSR construction -------------------------
__global__ void zero_k(int* p, int n) {
    int i = blockIdx.x * blockDim.x + threadIdx.x;
    if (i < n) p[i] = 0;
}
__global__ void count_k(const int* __restrict__ dst, int E, int doff, int* cnt) {
    int i = blockIdx.x * blockDim.x + threadIdx.x;
    if (i < E) atomicAdd(&cnt[dst[i] + doff], 1);
}
__global__ void loop_count_k(int* cnt, int n) {
    int i = blockIdx.x * blockDim.x + threadIdx.x;
    if (i < n) cnt[i] += 1;
}
__global__ void scan_k(const int* __restrict__ cnt, int* __restrict__ rp, int n) {
    __shared__ int sh[1024];
    int t = threadIdx.x;
    int c = (n + 1023) >> 10;
    int beg = t * c, end = min(beg + c, n);
    int s = 0;
    for (int i = beg; i < end; i++) s += cnt[i];
    sh[t] = s;
    __syncthreads();
    for (int off = 1; off < 1024; off <<= 1) {
        int v = (t >= off) ? sh[t - off] : 0;
        __syncthreads();
        sh[t] += v;
        __syncthreads();
    }
    int run = t ? sh[t - 1] : 0;
    for (int i = beg; i < end; i++) { rp[i] = run; run += cnt[i]; }
    if (t == 1023) rp[n] = sh[1023];
}
__global__ void copy_k(const int* a, int* b, int n) {
    int i = blockIdx.x * blockDim.x + threadIdx.x;
    if (i < n) b[i] = a[i];
}
__global__ void fill_k(const int* __restrict__ src, const int* __restrict__ dst, int E,
                       int soff, int doff, int tag, int* cur, int* __restrict__ ent) {
    int i = blockIdx.x * blockDim.x + threadIdx.x;
    if (i < E) {
        int pos = atomicAdd(&cur[dst[i] + doff], 1);
        ent[pos] = (tag << 16) | (src[i] + soff);
    }
}
__global__ void loop_fill_k(int n, int* cur, int* __restrict__ ent) {
    int i = blockIdx.x * blockDim.x + threadIdx.x;
    if (i < n) {
        int pos = atomicAdd(&cur[i], 1);
        ent[pos] = i;
    }
}

// ------------------------- HGT softmax aggregation -------------------------
// One block per dst node; warp h handles head h (online softmax over incoming edges).
__global__ void hgt_agg_k(const float* __restrict__ Q, const float* __restrict__ Krel,
                          const float* __restrict__ Vrel, const int* __restrict__ rp,
                          const int* __restrict__ ent, const float* __restrict__ prel,
                          float* __restrict__ agg, int dstBase)
{
    int node = blockIdx.x;
    int h = threadIdx.x >> 5, lane = threadIdx.x & 31;
    const float* q = Q + (long)(dstBase + node) * kD + h * kDH;
    float q0 = q[lane], q1 = q[lane + 32];
    float pr0 = prel[0 * kH + h], pr1 = prel[1 * kH + h];
    float pr2 = prel[2 * kH + h], pr3 = prel[3 * kH + h];
    int s = rp[node], e1 = rp[node + 1];
    float m = -INFINITY, den = 0.f, a0 = 0.f, a1 = 0.f;
    for (int e = s; e < e1; e++) {
        int pk = ent[e];
        int r = pk >> 16, src = pk & 0xffff;
        const float* kr = Krel + ((long)r * kNI + src) * kD + h * kDH;
        float d0 = q0 * kr[lane] + q1 * kr[lane + 32];
        d0 = wsum(d0);
        float pr = (r == 0) ? pr0 : (r == 1) ? pr1 : (r == 2) ? pr2 : pr3;
        float sc2 = d0 * pr * 0.125f;
        float mn = fmaxf(m, sc2);
        float cc = expf(m - mn), w = expf(sc2 - mn);
        const float* vr = Vrel + ((long)r * kNI + src) * kD + h * kDH;
        den = den * cc + w;
        a0 = a0 * cc + w * vr[lane];
        a1 = a1 * cc + w * vr[lane + 32];
        m = mn;
    }
    float inv = 1.f / (den + 1e-16f);
    float* o = agg + (long)(dstBase + node) * kD + h * kDH;
    o[lane] = a0 * inv;
    o[lane + 32] = a1 * inv;
}

// ------------------------- pooling -------------------------
__global__ void hv_k(const float* __restrict__ x, const float* __restrict__ pw,
                     float* __restrict__ hv) {
    int node = blockIdx.x * 8 + (threadIdx.x >> 5);
    int lane = threadIdx.x & 31;
    if (node >= kNT) return;
    float s = 0.f;
    for (int d = lane; d < kD; d += 32) s += x[(long)node * kD + d] * pw[d];
    s = wsum(s);
    if (!lane) hv[node] = s;
}
__global__ void gat_score_k(const float* __restrict__ hv, const int* __restrict__ rp,
                            const int* __restrict__ ent, const float* __restrict__ att,
                            const float* __restrict__ bias, float* __restrict__ sc) {
    int i = blockIdx.x * blockDim.x + threadIdx.x;
    if (i >= kNT) return;
    float A0 = att[0], A1 = att[1];
    float hi = hv[i];
    int s = rp[i], e1 = rp[i + 1];
    float m = -INFINITY, den = 0.f, acc = 0.f;
    for (int e = s; e < e1; e++) {
        int src = ent[e] & 0xffff;
        float hs = hv[src];
        float ee = A0 * hs + A1 * hi;
        ee = ee >= 0.f ? ee : 0.2f * ee;
        float mn = fmaxf(m, ee);
        float c = expf(m - mn), w = expf(ee - mn);
        den = den * c + w;
        acc = acc * c + w * hs;
        m = mn;
    }
    sc[i] = acc / (den + 1e-16f) + bias[0];
}

// Bitonic sort of 1536 (padded to 2048) per graph; descending, ties -> lower index.
__global__ void topk_sort_k(const float* __restrict__ sc, float* __restrict__ sv,
                            int* __restrict__ si) {
    int b = blockIdx.x, t = threadIdx.x;
    __shared__ float v[2048];
    __shared__ int ix[2048];
    for (int p = t; p < 2048; p += 1024) {
        float val = -INFINITY;
        if (p < 1536) {
            int node = p < 1024 ? b * 1024 + p : kNI + b * 512 + (p - 1024);
            val = sc[node];
        }
        v[p] = val;
        ix[p] = p;
    }
    __syncthreads();
    for (int k = 2; k <= 2048; k <<= 1)
        for (int j = k >> 1; j > 0; j >>= 1) {
#pragma unroll
            for (int pass = 0; pass < 2; pass++) {
                int i = t + pass * 1024;
                int l = i ^ j;
                if (l > i) {
                    bool up = ((i & k) == 0);
                    float vi = v[i], vl = v[l];
                    int ii = ix[i], il = ix[l];
                    bool before = (vi > vl) || (vi == vl && ii < il);
                    if (up != before) {
                        v[i] = vl; v[l] = vi;
                        ix[i] = il; ix[l] = ii;
                    }
                }
            }
            __syncthreads();
        }
    if (t < kKP) {
        sv[b * kKP + t] = v[t];
        si[b * kKP + t] = ix[t];
    }
}
__global__ void gather_k(const float* __restrict__ x, const float* __restrict__ sv,
                         const int* __restrict__ si, float* __restrict__ xp) {
    int q = blockIdx.x, b = blockIdx.y, d = threadIdx.x;
    int j = si[b * kKP + q];
    float tv = tanhf(sv[b * kKP + q]);
    int node = j < 1024 ? b * 1024 + j : kNI + b * 512 + (j - 1024);
    xp[((long)(b * kKP + q)) * kD + d] = x[(long)node * kD + d] * tv;
}

// ------------------------- transformer pieces -------------------------
__global__ void softmax_k(float* __restrict__ S) {
    long row = blockIdx.x;
    float* p = S + row * kKP;
    int t = threadIdx.x;
    float m = -INFINITY;
    for (int i = t; i < kKP; i += 256) m = fmaxf(m, p[i]);
    m = bmax(m);
    float s = 0.f;
    for (int i = t; i < kKP; i += 256) {
        float e = expf(p[i] - m);
        p[i] = e;
        s += e;
    }
    s = bsum(s);
    float inv = 1.f / s;
    for (int i = t; i < kKP; i += 256) p[i] *= inv;
}
__global__ void ln_k(const float* __restrict__ y, const float* __restrict__ g,
                     const float* __restrict__ bta, float* __restrict__ out) {
    long row = blockIdx.x;
    int d = threadIdx.x;
    float v = y[row * kD + d];
    float mu = bsum(v) * (1.f / kD);
    float df = v - mu;
    float var = bsum(df * df) * (1.f / kD);
    out[row * kD + d] = g[d] * df * rsqrtf(var + 1e-5f) + bta[d];
}
__global__ void featsum_k(const float* __restrict__ xp, const float* __restrict__ ga,
                          float* __restrict__ u) {
    int b = blockIdx.x, d = threadIdx.x;
    float s1 = 0.f, s2 = 0.f;
    for (int q = 0; q < kKP; q++) {
        long o = ((long)(b * kKP + q)) * kD + d;
        s1 += xp[o];
        s2 += ga[o];
    }
    u[b * 512 + d] = s1;
    u[b * 512 + 256 + d] = s2;
}
__global__ void cos_k(const float* __restrict__ u, float* __restrict__ out) {
    int b = blockIdx.x, t = threadIdx.x;
    float a = u[b * 512 + t];
    float c = u[(kB + b) * 512 + t];
    float dot = bsum(a * c);
    float na = bsum(a * a);
    float nc = bsum(c * c);
    if (t == 0)
        out[b] = dot / (fmaxf(sqrtf(na), 1e-8f) * fmaxf(sqrtf(nc), 1e-8f));
}

// ------------------------- host orchestration -------------------------
static inline void gemm(bool tb, const float* A, int lda, long Ab, long Ah,
                        const float* Bm, int ldb, long Bb, long Bh,
                        float* C, int ldc, long Cb, long Ch,
                        const float* Add, int ldadd, const float* gptr,
                        int M, int N, int K, int ZB, int ZH, float alpha, int mode) {
    if (N % 128 == 0) {
        dim3 g(M / 128, N / 128, ZB * ZH), blk(256);
        if (tb)
            gemm_k<128, true><<<g, blk>>>(A, lda, Ab, Ah, Bm, ldb, Bb, Bh, C, ldc, Cb, Ch,
                                          Add, ldadd, gptr, K, ZH, alpha, mode);
        else
            gemm_k<128, false><<<g, blk>>>(A, lda, Ab, Ah, Bm, ldb, Bb, Bh, C, ldc, Cb, Ch,
                                           Add, ldadd, gptr, K, ZH, alpha, mode);
    } else {
        dim3 g(M / 128, N / 64, ZB * ZH), blk(256);
        if (tb)
            gemm_k<64, true><<<g, blk>>>(A, lda, Ab, Ah, Bm, ldb, Bb, Bh, C, ldc, Cb, Ch,
                                         Add, ldadd, gptr, K, ZH, alpha, mode);
        else
            gemm_k<64, false><<<g, blk>>>(A, lda, Ab, Ah, Bm, ldb, Bb, Bh, C, ldc, Cb, Ch,
                                          Add, ldadd, gptr, K, ZH, alpha, mode);
    }
}

struct EdgeSpec { const int* src; const int* dst; int E, soff, doff, tag; };

static void build_csr(int n, int* rp, int* ent, int* cnt, int* cur,
                      const EdgeSpec* es, int ns, bool loops) {
    zero_k<<<(n + 255) / 256, 256>>>(cnt, n);
    for (int i = 0; i < ns; i++)
        count_k<<<(es[i].E + 255) / 256, 256>>>(es[i].dst, es[i].E, es[i].doff, cnt);
    if (loops) loop_count_k<<<(n + 255) / 256, 256>>>(cnt, n);
    scan_k<<<1, 1024>>>(cnt, rp, n);
    copy_k<<<(n + 255) / 256, 256>>>(rp, cur, n);
    for (int i = 0; i < ns; i++)
        fill_k<<<(es[i].E + 255) / 256, 256>>>(es[i].src, es[i].dst, es[i].E,
                                               es[i].soff, es[i].doff, es[i].tag, cur, ent);
    if (loops) loop_fill_k<<<(n + 255) / 256, 256>>>(n, cur, ent);
}

static void run_branch(Scratch* sp, const float* xi, const float* xd,
                       const int* ec, const int* ei, const int* eo, const int* ek,
                       const float* Wk, const float* Wq, const float* Wv, const float* Wo,
                       const float* arel, const float* mrel, const float* prel,
                       const float* skip, const float* poolW, const float* poolAtt,
                       const float* poolBias, const float* tWq, const float* tWk,
                       const float* tWv, const float* tWo, const float* lng,
                       const float* lnb, int branch)
{
    const long DD = (long)kD * kD;
    const long T1 = (long)kNI * kD;    // type-1 offset in node buffers

    // assemble x = [x_inst ; x_data]
    cudaMemcpyAsync(sp->x, xi, T1 * sizeof(float), cudaMemcpyDeviceToDevice, 0);
    cudaMemcpyAsync(sp->x + T1, xd, (long)kND * kD * sizeof(float),
                    cudaMemcpyDeviceToDevice, 0);

    const int *rc = ec, *cc = ec + kEC;
    const int *ri = ei, *ci = ei + kEI;
    const int *ro = eo, *co = eo + kEO;
    const int *rk = ek, *ck = ek + kEK;

    // HGT CSRs (type-local indices; tag = relation id)
    { EdgeSpec e[3] = { {rc, cc, kEC, 0, 0, 0}, {ri, ci, kEI, 0, 0, 1}, {rk, ck, kEK, 0, 0, 3} };
      build_csr(kNI, sp->rpf0, sp->ef0, sp->cnt, sp->cur, e, 3, false); }
    { EdgeSpec e[1] = { {ro, co, kEO, 0, 0, 2} };
      build_csr(kND, sp->rpf1, sp->ef1, sp->cnt, sp->cur, e, 1, false); }
    { EdgeSpec e[3] = { {cc, rc, kEC, 0, 0, 0}, {co, ro, kEO, 0, 0, 2}, {ck, rk, kEK, 0, 0, 3} };
      build_csr(kNI, sp->rpr0, sp->er0, sp->cnt, sp->cur, e, 3, false); }
    { EdgeSpec e[1] = { {ci, ri, kEI, 0, 0, 1} };
      build_csr(kND, sp->rpr1, sp->er1, sp->cnt, sp->cur, e, 1, false); }
    // homogeneous CSR for pooling GAT (inst first, data offset +kNI, self-loops)
    { EdgeSpec e[4] = { {rc, cc, kEC, 0, 0, 0}, {ri, ci, kEI, kNI, 0, 0},
                        {ro, co, kEO, 0, kNI, 0}, {rk, ck, kEK, 0, 0, 0} };
      build_csr(kNT, sp->rph, sp->eh, sp->cnt, sp->cur, e, 4, true); }

    static const int fwdsrc[4] = {0, 1, 0, 0};
    static const int revsrc[4] = {0, 0, 1, 0};

    for (int l = 0; l < 2; l++) {
        for (int dir = 0; dir < 2; dir++) {
            long wOff = (long)((l * 2 + dir) * 2) * DD;
            // K, Q, V per node type
            for (int t = 0; t < 2; t++) {
                const float* xb = sp->x + (t ? T1 : 0);
                int M = t ? kND : kNI;
                long tOff = t ? T1 : 0;
                gemm(false, xb, kD, 0, 0, Wk + wOff + t * DD, kD, 0, 0,
                     sp->Kb + tOff, kD, 0, 0, nullptr, 0, nullptr,
                     M, kD, kD, 1, 1, 1.f, 0);
                gemm(false, xb, kD, 0, 0, Wq + wOff + t * DD, kD, 0, 0,
                     sp->Qb + tOff, kD, 0, 0, nullptr, 0, nullptr,
                     M, kD, kD, 1, 1, 1.f, 0);
                gemm(false, xb, kD, 0, 0, Wv + wOff + t * DD, kD, 0, 0,
                     sp->Vb + tOff, kD, 0, 0, nullptr, 0, nullptr,
                     M, kD, kD, 1, 1, 1.f, 0);
            }
            // Krel / Vrel (per-relation per-head 64x64 transforms, z-batched over heads)
            for (int r = 0; r < 4; r++) {
                int st = dir ? revsrc[r] : fwdsrc[r];
                int M = st ? kND : kNI;
                long sOff = st ? T1 : 0;
                long relOff = (long)(((l * 2 + dir) * 4 + r) * kH) * kDH * kDH;
                gemm(false, sp->Kb + sOff, kD, 0, 64, arel + relOff, kDH, 0, (long)kDH * kDH,
                     sp->Krel + (long)r * kNI * kD, kD, 0, 64, nullptr, 0, nullptr,
                     M, kDH, kDH, 1, kH, 1.f, 0);
                gemm(false, sp->Vb + sOff, kD, 0, 64, mrel + relOff, kDH, 0, (long)kDH * kDH,
                     sp->Vrel + (long)r * kNI * kD, kD, 0, 64, nullptr, 0, nullptr,
                     M, kDH, kDH, 1, kH, 1.f, 0);
            }
            // aggregation
            const float* prelp = prel + (long)((l * 2 + dir) * 4) * kH;
            if (dir == 0) {
                hgt_agg_k<<<kNI, 128>>>(sp->Qb, sp->Krel, sp->Vrel, sp->rpf0, sp->ef0,
                                        prelp, sp->agg, 0);
                hgt_agg_k<<<kND, 128>>>(sp->Qb, sp->Krel, sp->Vrel, sp->rpf1, sp->ef1,
                                        prelp, sp->agg, kNI);
            } else {
                hgt_agg_k<<<kNI, 128>>>(sp->Qb, sp->Krel, sp->Vrel, sp->rpr0, sp->er0,
                                        prelp, sp->agg, 0);
                hgt_agg_k<<<kND, 128>>>(sp->Qb, sp->Krel, sp->Vrel, sp->rpr1, sp->er1,
                                        prelp, sp->agg, kNI);
            }
            // gelu -> Kb (Kb no longer needed), then Wo with sigmoid-skip blend
            gelu_k<<<(int)(LXD / 256), 256>>>(sp->agg, sp->Kb, LXD);
            float* yD = dir ? sp->yR : sp->yF;
            for (int t = 0; t < 2; t++) {
                int M = t ? kND : kNI;
                long tOff = t ? T1 : 0;
                gemm(false, sp->Kb + tOff, kD, 0, 0, Wo + wOff + t * DD, kD, 0, 0,
                     yD + tOff, kD, 0, 0, sp->x + tOff, kD,
                     skip + (l * 2 + dir) * 2 + t, M, kD, kD, 1, 1, 1.f, 1);
            }
        }
        comb_relu_k<<<(int)(LXD / 256), 256>>>(sp->yF, sp->yR, sp->x, LXD);
    }

    // pooling
    hv_k<<<kNT / 8, 256>>>(sp->x, poolW, sp->hv);
    gat_score_k<<<(kNT + 255) / 256, 256>>>(sp->hv, sp->rph, sp->eh, poolAtt, poolBias, sp->sc);
    topk_sort_k<<<kB, 1024>>>(sp->sc, sp->sv, sp->si);
    gather_k<<<dim3(kKP, kB), kD>>>(sp->x, sp->sv, sp->si, sp->xp);

    // transformer attention over pooled nodes
    int Mp = kB * kKP;
    gemm(false, sp->xp, kD, 0, 0, tWq, kD, 0, 0, sp->qb, kD, 0, 0,
         nullptr, 0, nullptr, Mp, kD, kD, 1, 1, 1.f, 0);
    gemm(false, sp->xp, kD, 0, 0, tWk, kD, 0, 0, sp->kb, kD, 0, 0,
         nullptr, 0, nullptr, Mp, kD, kD, 1, 1, 1.f, 0);
    gemm(false, sp->xp, kD, 0, 0, tWv, kD, 0, 0, sp->vb, kD, 0, 0,
         nullptr, 0, nullptr, Mp, kD, kD, 1, 1, 1.f, 0);
    long pb = (long)kKP * kD;              // per-graph stride in pooled buffers
    long sb = (long)kH * kKP * kKP;        // per-graph stride in S
    gemm(true, sp->qb, kD, pb, kDH, sp->kb, kD, pb, kDH,
         sp->S, kKP, sb, (long)kKP * kKP, nullptr, 0, nullptr,
         kKP, kKP, kDH, kB, kH, 0.125f, 0);
    softmax_k<<<kB * kH * kKP, 256>>>(sp->S);
    gemm(false, sp->S, kKP, sb, (long)kKP * kKP, sp->vb, kD, pb, kDH,
         sp->oh, kD, pb, kDH, nullptr, 0, nullptr,
         kKP, kDH, kKP, kB, kH, 1.f, 0);
    gemm(false, sp->oh, kD, 0, 0, tWo, kD, 0, 0, sp->yb, kD, 0, 0,
         sp->xp, kD, nullptr, Mp, kD, kD, 1, 1, 1.f, 2);
    ln_k<<<Mp, kD>>>(sp->yb, lng, lnb, sp->ga);
    featsum_k<<<kB, kD>>>(sp->xp, sp->ga, sp->u + (long)branch * kB * 512);
}

extern "C" void kernel_launch(void* const* d_in, const int* in_sizes, int n_in,
                              void* d_out, int out_size) {
    Scratch* sp = nullptr;
    cudaGetSymbolAddress((void**)&sp, SC);

    const float* Wk    = (const float*)d_in[12];
    const float* Wq    = (const float*)d_in[13];
    const float* Wv    = (const float*)d_in[14];
    const float* Wo    = (const float*)d_in[15];
    const float* arel  = (const float*)d_in[16];
    const float* mrel  = (const float*)d_in[17];
    const float* prel  = (const float*)d_in[18];
    const float* skip  = (const float*)d_in[19];
    const float* poolW = (const float*)d_in[20];
    const float* poolA = (const float*)d_in[21];
    const float* poolB = (const float*)d_in[22];
    const float* tWq   = (const float*)d_in[23];
    const float* tWk   = (const float*)d_in[24];
    const float* tWv   = (const float*)d_in[25];
    const float* tWo   = (const float*)d_in[26];
    const float* lng   = (const float*)d_in[27];
    const float* lnb   = (const float*)d_in[28];

    for (int g = 0; g < 2; g++) {
        int base = g * 6;
        run_branch(sp,
                   (const float*)d_in[base + 0], (const float*)d_in[base + 1],
                   (const int*)d_in[base + 2], (const int*)d_in[base + 3],
                   (const int*)d_in[base + 4], (const int*)d_in[base + 5],
                   Wk, Wq, Wv, Wo, arel, mrel, prel, skip,
                   poolW, poolA, poolB, tWq, tWk, tWv, tWo, lng, lnb, g);
    }
    cos_k<<<kB, 512>>>(sp->u, (float*)d_out);
}

// round 7
// speedup vs baseline: 1.0200x; 1.0200x over previous
#include <cuda_runtime.h>
#include <math.h>

// ------------------------- problem constants -------------------------
constexpr int kNI = 8192, kND = 4096, kNT = 12288, kD = 256, kH = 4, kDH = 64;
constexpr int kB = 8, kKP = 768;
constexpr int kEC = 65536, kEI = 32768, kEO = 32768, kEK = 8192;
constexpr long LXD = (long)kNT * kD;          // full node-feature buffer
constexpr long LPD = (long)kB * kKP * kD;     // pooled buffer

// ------------------------- scratch (static device memory) -------------------------
struct Scratch {
    float x[LXD], yF[LXD], yR[LXD], Kb[LXD], Qb[LXD], Vb[LXD], agg[LXD];
    float Krel[4L * kNI * kD], Vrel[4L * kNI * kD];
    float S[(long)kB * kH * kKP * kKP];
    float xp[LPD], qb[LPD], kb[LPD], vb[LPD], oh[LPD], yb[LPD], ga[LPD];
    float hv[kNT], sc[kNT];
    float sv[kB * kKP];
    int   si[kB * kKP];
    float u[2 * kB * 512];
    int rpf0[kNI + 1], rpf1[kND + 1], rpr0[kNI + 1], rpr1[kND + 1], rph[kNT + 1];
    int ef0[kEC + kEI + kEK], ef1[kEO], er0[kEC + kEO + kEK], er1[kEI];
    int eh[kEC + kEI + kEO + kEK + kNT];
    int cnt[kNT], cur[kNT];
};
__device__ Scratch SC;

// ------------------------- reductions -------------------------
__device__ __forceinline__ float wsum(float v) {
#pragma unroll
    for (int o = 16; o; o >>= 1) v += __shfl_xor_sync(0xffffffffu, v, o);
    return v;
}
__device__ __forceinline__ float bsum(float v) {
    __shared__ float sh[32];
    int lane = threadIdx.x & 31, w = threadIdx.x >> 5;
    v = wsum(v);
    if (!lane) sh[w] = v;
    __syncthreads();
    int nw = blockDim.x >> 5;
    float s = (threadIdx.x < nw) ? sh[threadIdx.x] : 0.f;
    if (w == 0) s = wsum(s);
    if (threadIdx.x == 0) sh[0] = s;
    __syncthreads();
    float r = sh[0];
    __syncthreads();
    return r;
}
__device__ __forceinline__ float bmax(float v) {
    __shared__ float sh[32];
    int lane = threadIdx.x & 31, w = threadIdx.x >> 5;
#pragma unroll
    for (int o = 16; o; o >>= 1) v = fmaxf(v, __shfl_xor_sync(0xffffffffu, v, o));
    if (!lane) sh[w] = v;
    __syncthreads();
    int nw = blockDim.x >> 5;
    float s = (threadIdx.x < nw) ? sh[threadIdx.x] : -INFINITY;
    if (w == 0)
#pragma unroll
        for (int o = 16; o; o >>= 1) s = fmaxf(s, __shfl_xor_sync(0xffffffffu, s, o));
    if (threadIdx.x == 0) sh[0] = s;
    __syncthreads();
    float r = sh[0];
    __syncthreads();
    return r;
}

// ------------------------- 128x(128|64)x8 scalar-FFMA GEMM -------------------------
// C = epilogue(alpha * A @ B(^T)); z-batched: z -> (zb = z/ZH, zh = z%ZH).
// 256 threads; per-thread microtile TM rows x 8 cols (TM = 8 for BN=128, 4 for BN=64).
// mode 0: C = v
// mode 1: C = g*v + (1-g)*Add,  g = sigmoid(*gptr)
// mode 2: C = v + Add
template <int BN, bool TB>
__global__ void __launch_bounds__(256) gemm_k(
    const float* __restrict__ A, int lda, long Ab, long Ah,
    const float* __restrict__ Bm, int ldb, long Bb, long Bh,
    float* __restrict__ C, int ldc, long Cb, long Ch,
    const float* __restrict__ Add, int ldadd, const float* __restrict__ gptr,
    int Kdim, int ZH, float alpha, int mode)
{
    constexpr int BM = 128, BK = 8;
    constexpr int TX = BN / 8;                 // column groups (8 cols each)
    constexpr int TM = (BM * BN) / (256 * 8);  // rows per thread (8 or 4)
    __shared__ __align__(16) float As[BK][BM + 4];
    __shared__ __align__(16) float Bs[BK][BN + 4];

    int z = blockIdx.z, zb = z / ZH, zh = z - zb * ZH;
    A  += zb * Ab + zh * Ah;
    Bm += zb * Bb + zh * Bh;
    C  += zb * Cb + zh * Ch;
    int m0 = blockIdx.x * BM, n0 = blockIdx.y * BN;
    int tid = threadIdx.x;
    int tx = tid % TX, ty = tid / TX;

    float acc[TM][8] = {};

    int aR = tid >> 1, aC = (tid & 1) * 4;

    for (int k0 = 0; k0 < Kdim; k0 += BK) {
        // A tile: 128 x 8, stored transposed As[k][m]
        {
            float4 av = *(const float4*)(A + (long)(m0 + aR) * lda + k0 + aC);
            As[aC + 0][aR] = av.x; As[aC + 1][aR] = av.y;
            As[aC + 2][aR] = av.z; As[aC + 3][aR] = av.w;
        }
        // B tile: Bs[k][n]
        if (TB) {
            if (BN == 128 || tid < 128) {
                int bR = tid >> 1, bC = (tid & 1) * 4;
                float4 bv = *(const float4*)(Bm + (long)(n0 + bR) * ldb + k0 + bC);
                Bs[bC + 0][bR] = bv.x; Bs[bC + 1][bR] = bv.y;
                Bs[bC + 2][bR] = bv.z; Bs[bC + 3][bR] = bv.w;
            }
        } else {
            if (BN == 128) {
                int bR = tid >> 5, bC = (tid & 31) * 4;
                *(float4*)&Bs[bR][bC] =
                    *(const float4*)(Bm + (long)(k0 + bR) * ldb + n0 + bC);
            } else if (tid < 128) {
                int bR = tid >> 4, bC = (tid & 15) * 4;
                *(float4*)&Bs[bR][bC] =
                    *(const float4*)(Bm + (long)(k0 + bR) * ldb + n0 + bC);
            }
        }
        __syncthreads();
#pragma unroll
        for (int kk = 0; kk < BK; kk++) {
            float a[TM], b[8];
#pragma unroll
            for (int i = 0; i < TM; i += 4)
                *(float4*)&a[i] = *(const float4*)&As[kk][ty * TM + i];
            *(float4*)&b[0] = *(const float4*)&Bs[kk][tx * 8];
            *(float4*)&b[4] = *(const float4*)&Bs[kk][tx * 8 + 4];
#pragma unroll
            for (int i = 0; i < TM; i++)
#pragma unroll
                for (int j = 0; j < 8; j++)
                    acc[i][j] += a[i] * b[j];
        }
        __syncthreads();
    }

    float g = 1.f;
    if (mode == 1) g = 1.f / (1.f + expf(-gptr[0]));
#pragma unroll
    for (int i = 0; i < TM; i++) {
        long r = m0 + ty * TM + i;
        long c0 = n0 + tx * 8;
#pragma unroll
        for (int h = 0; h < 2; h++) {
            float4 v;
            v.x = alpha * acc[i][h * 4 + 0];
            v.y = alpha * acc[i][h * 4 + 1];
            v.z = alpha * acc[i][h * 4 + 2];
            v.w = alpha * acc[i][h * 4 + 3];
            if (mode == 1) {
                float4 ad = *(const float4*)(Add + r * ldadd + c0 + h * 4);
                v.x = g * v.x + (1.f - g) * ad.x;
                v.y = g * v.y + (1.f - g) * ad.y;
                v.z = g * v.z + (1.f - g) * ad.z;
                v.w = g * v.w + (1.f - g) * ad.w;
            } else if (mode == 2) {
                float4 ad = *(const float4*)(Add + r * ldadd + c0 + h * 4);
                v.x += ad.x; v.y += ad.y; v.z += ad.z; v.w += ad.w;
            }
            *(float4*)(C + r * ldc + c0 + h * 4) = v;
        }
    }
}

// ------------------------- elementwise kernels -------------------------
__global__ void gelu_k(const float* __restrict__ in, float* __restrict__ out, long n) {
    long i = (long)blockIdx.x * blockDim.x + threadIdx.x;
    if (i < n) {
        float v = in[i];
        out[i] = 0.5f * v * (1.f + erff(v * 0.7071067811865475f));
    }
}
__global__ void comb_relu_k(const float* __restrict__ a, const float* __restrict__ b,
                            float* __restrict__ x, long n) {
    long i = (long)blockIdx.x * blockDim.x + threadIdx.x;
    if (i < n) {
        float v = 0.5f * a[i] + 0.5f * b[i];
        x[i] = v > 0.f ? v : 0.f;
    }
}

// ------------------------- CSR construction -------------------------
__global__ void zero_k(int* p, int n) {
    int i = blockIdx.x * blockDim.x + threadIdx.x;
    if (i < n) p[i] = 0;
}
__global__ void count_k(const int* __restrict__ dst, int E, int doff, int* cnt) {
    int i = blockIdx.x * blockDim.x + threadIdx.x;
    if (i < E) atomicAdd(&cnt[dst[i] + doff], 1);
}
__global__ void loop_count_k(int* cnt, int n) {
    int i = blockIdx.x * blockDim.x + threadIdx.x;
    if (i < n) cnt[i] += 1;
}
__global__ void scan_k(const int* __restrict__ cnt, int* __restrict__ rp, int n) {
    __shared__ int sh[1024];
    int t = threadIdx.x;
    int c = (n + 1023) >> 10;
    int beg = t * c, end = min(beg + c, n);
    int s = 0;
    for (int i = beg; i < end; i++) s += cnt[i];
    sh[t] = s;
    __syncthreads();
    for (int off = 1; off < 1024; off <<= 1) {
        int v = (t >= off) ? sh[t - off] : 0;
        __syncthreads();
        sh[t] += v;
        __syncthreads();
    }
    int run = t ? sh[t - 1] : 0;
    for (int i = beg; i < end; i++) { rp[i] = run; run += cnt[i]; }
    if (t == 1023) rp[n] = sh[1023];
}
__global__ void copy_k(const int* a, int* b, int n) {
    int i = blockIdx.x * blockDim.x + threadIdx.x;
    if (i < n) b[i] = a[i];
}
__global__ void fill_k(const int* __restrict__ src, const int* __restrict__ dst, int E,
                       int soff, int doff, int tag, int* cur, int* __restrict__ ent) {
    int i = blockIdx.x * blockDim.x + threadIdx.x;
    if (i < E) {
        int pos = atomicAdd(&cur[dst[i] + doff], 1);
        ent[pos] = (tag << 16) | (src[i] + soff);
    }
}
__global__ void loop_fill_k(int n, int* cur, int* __restrict__ ent) {
    int i = blockIdx.x * blockDim.x + threadIdx.x;
    if (i < n) {
        int pos = atomicAdd(&cur[i], 1);
        ent[pos] = i;
    }
}

// ------------------------- HGT softmax aggregation -------------------------
// One block per dst node; warp h handles head h (online softmax over incoming edges).
__global__ void hgt_agg_k(const float* __restrict__ Q, const float* __restrict__ Krel,
                          const float* __restrict__ Vrel, const int* __restrict__ rp,
                          const int* __restrict__ ent, const float* __restrict__ prel,
                          float* __restrict__ agg, int dstBase)
{
    int node = blockIdx.x;
    int h = threadIdx.x >> 5, lane = threadIdx.x & 31;
    const float* q = Q + (long)(dstBase + node) * kD + h * kDH;
    float q0 = q[lane], q1 = q[lane + 32];
    float pr0 = prel[0 * kH + h], pr1 = prel[1 * kH + h];
    float pr2 = prel[2 * kH + h], pr3 = prel[3 * kH + h];
    int s = rp[node], e1 = rp[node + 1];
    float m = -INFINITY, den = 0.f, a0 = 0.f, a1 = 0.f;
    for (int e = s; e < e1; e++) {
        int pk = ent[e];
        int r = pk >> 16, src = pk & 0xffff;
        const float* kr = Krel + ((long)r * kNI + src) * kD + h * kDH;
        float d0 = q0 * kr[lane] + q1 * kr[lane + 32];
        d0 = wsum(d0);
        float pr = (r == 0) ? pr0 : (r == 1) ? pr1 : (r == 2) ? pr2 : pr3;
        float sc2 = d0 * pr * 0.125f;
        float mn = fmaxf(m, sc2);
        float cc = expf(m - mn), w = expf(sc2 - mn);
        const float* vr = Vrel + ((long)r * kNI + src) * kD + h * kDH;
        den = den * cc + w;
        a0 = a0 * cc + w * vr[lane];
        a1 = a1 * cc + w * vr[lane + 32];
        m = mn;
    }
    float inv = 1.f / (den + 1e-16f);
    float* o = agg + (long)(dstBase + node) * kD + h * kDH;
    o[lane] = a0 * inv;
    o[lane + 32] = a1 * inv;
}

// ------------------------- pooling -------------------------
__global__ void hv_k(const float* __restrict__ x, const float* __restrict__ pw,
                     float* __restrict__ hv) {
    int node = blockIdx.x * 8 + (threadIdx.x >> 5);
    int lane = threadIdx.x & 31;
    if (node >= kNT) return;
    float s = 0.f;
    for (int d = lane; d < kD; d += 32) s += x[(long)node * kD + d] * pw[d];
    s = wsum(s);
    if (!lane) hv[node] = s;
}
__global__ void gat_score_k(const float* __restrict__ hv, const int* __restrict__ rp,
                            const int* __restrict__ ent, const float* __restrict__ att,
                            const float* __restrict__ bias, float* __restrict__ sc) {
    int i = blockIdx.x * blockDim.x + threadIdx.x;
    if (i >= kNT) return;
    float A0 = att[0], A1 = att[1];
    float hi = hv[i];
    int s = rp[i], e1 = rp[i + 1];
    float m = -INFINITY, den = 0.f, acc = 0.f;
    for (int e = s; e < e1; e++) {
        int src = ent[e] & 0xffff;
        float hs = hv[src];
        float ee = A0 * hs + A1 * hi;
        ee = ee >= 0.f ? ee : 0.2f * ee;
        float mn = fmaxf(m, ee);
        float c = expf(m - mn), w = expf(ee - mn);
        den = den * c + w;
        acc = acc * c + w * hs;
        m = mn;
    }
    sc[i] = acc / (den + 1e-16f) + bias[0];
}

// Bitonic sort of 1536 (padded to 2048) per graph; descending, ties -> lower index.
__global__ void topk_sort_k(const float* __restrict__ sc, float* __restrict__ sv,
                            int* __restrict__ si) {
    int b = blockIdx.x, t = threadIdx.x;
    __shared__ float v[2048];
    __shared__ int ix[2048];
    for (int p = t; p < 2048; p += 1024) {
        float val = -INFINITY;
        if (p < 1536) {
            int node = p < 1024 ? b * 1024 + p : kNI + b * 512 + (p - 1024);
            val = sc[node];
        }
        v[p] = val;
        ix[p] = p;
    }
    __syncthreads();
    for (int k = 2; k <= 2048; k <<= 1)
        for (int j = k >> 1; j > 0; j >>= 1) {
#pragma unroll
            for (int pass = 0; pass < 2; pass++) {
                int i = t + pass * 1024;
                int l = i ^ j;
                if (l > i) {
                    bool up = ((i & k) == 0);
                    float vi = v[i], vl = v[l];
                    int ii = ix[i], il = ix[l];
                    bool before = (vi > vl) || (vi == vl && ii < il);
                    if (up != before) {
                        v[i] = vl; v[l] = vi;
                        ix[i] = il; ix[l] = ii;
                    }
                }
            }
            __syncthreads();
        }
    if (t < kKP) {
        sv[b * kKP + t] = v[t];
        si[b * kKP + t] = ix[t];
    }
}
__global__ void gather_k(const float* __restrict__ x, const float* __restrict__ sv,
                         const int* __restrict__ si, float* __restrict__ xp) {
    int q = blockIdx.x, b = blockIdx.y, d = threadIdx.x;
    int j = si[b * kKP + q];
    float tv = tanhf(sv[b * kKP + q]);
    int node = j < 1024 ? b * 1024 + j : kNI + b * 512 + (j - 1024);
    xp[((long)(b * kKP + q)) * kD + d] = x[(long)node * kD + d] * tv;
}

// ------------------------- transformer pieces -------------------------
__global__ void softmax_k(float* __restrict__ S) {
    long row = blockIdx.x;
    float* p = S + row * kKP;
    int t = threadIdx.x;
    float m = -INFINITY;
    for (int i = t; i < kKP; i += 256) m = fmaxf(m, p[i]);
    m = bmax(m);
    float s = 0.f;
    for (int i = t; i < kKP; i += 256) {
        float e = expf(p[i] - m);
        p[i] = e;
        s += e;
    }
    s = bsum(s);
    float inv = 1.f / s;
    for (int i = t; i < kKP; i += 256) p[i] *= inv;
}
__global__ void ln_k(const float* __restrict__ y, const float* __restrict__ g,
                     const float* __restrict__ bta, float* __restrict__ out) {
    long row = blockIdx.x;
    int d = threadIdx.x;
    float v = y[row * kD + d];
    float mu = bsum(v) * (1.f / kD);
    float df = v - mu;
    float var = bsum(df * df) * (1.f / kD);
    out[row * kD + d] = g[d] * df * rsqrtf(var + 1e-5f) + bta[d];
}
__global__ void featsum_k(const float* __restrict__ xp, const float* __restrict__ ga,
                          float* __restrict__ u) {
    int b = blockIdx.x, d = threadIdx.x;
    float s1 = 0.f, s2 = 0.f;
    for (int q = 0; q < kKP; q++) {
        long o = ((long)(b * kKP + q)) * kD + d;
        s1 += xp[o];
        s2 += ga[o];
    }
    u[b * 512 + d] = s1;
    u[b * 512 + 256 + d] = s2;
}
__global__ void cos_k(const float* __restrict__ u, float* __restrict__ out) {
    int b = blockIdx.x, t = threadIdx.x;
    float a = u[b * 512 + t];
    float c = u[(kB + b) * 512 + t];
    float dot = bsum(a * c);
    float na = bsum(a * a);
    float nc = bsum(c * c);
    if (t == 0)
        out[b] = dot / (fmaxf(sqrtf(na), 1e-8f) * fmaxf(sqrtf(nc), 1e-8f));
}

// ------------------------- host orchestration -------------------------
static inline void gemm(bool tb, const float* A, int lda, long Ab, long Ah,
                        const float* Bm, int ldb, long Bb, long Bh,
                        float* C, int ldc, long Cb, long Ch,
                        const float* Add, int ldadd, const float* gptr,
                        int M, int N, int K, int ZB, int ZH, float alpha, int mode) {
    if (N % 128 == 0) {
        dim3 g(M / 128, N / 128, ZB * ZH), blk(256);
        if (tb)
            gemm_k<128, true><<<g, blk>>>(A, lda, Ab, Ah, Bm, ldb, Bb, Bh, C, ldc, Cb, Ch,
                                          Add, ldadd, gptr, K, ZH, alpha, mode);
        else
            gemm_k<128, false><<<g, blk>>>(A, lda, Ab, Ah, Bm, ldb, Bb, Bh, C, ldc, Cb, Ch,
                                           Add, ldadd, gptr, K, ZH, alpha, mode);
    } else {
        dim3 g(M / 128, N / 64, ZB * ZH), blk(256);
        if (tb)
            gemm_k<64, true><<<g, blk>>>(A, lda, Ab, Ah, Bm, ldb, Bb, Bh, C, ldc, Cb, Ch,
                                         Add, ldadd, gptr, K, ZH, alpha, mode);
        else
            gemm_k<64, false><<<g, blk>>>(A, lda, Ab, Ah, Bm, ldb, Bb, Bh, C, ldc, Cb, Ch,
                                          Add, ldadd, gptr, K, ZH, alpha, mode);
    }
}

struct EdgeSpec { const int* src; const int* dst; int E, soff, doff, tag; };

static void build_csr(int n, int* rp, int* ent, int* cnt, int* cur,
                      const EdgeSpec* es, int ns, bool loops) {
    zero_k<<<(n + 255) / 256, 256>>>(cnt, n);
    for (int i = 0; i < ns; i++)
        count_k<<<(es[i].E + 255) / 256, 256>>>(es[i].dst, es[i].E, es[i].doff, cnt);
    if (loops) loop_count_k<<<(n + 255) / 256, 256>>>(cnt, n);
    scan_k<<<1, 1024>>>(cnt, rp, n);
    copy_k<<<(n + 255) / 256, 256>>>(rp, cur, n);
    for (int i = 0; i < ns; i++)
        fill_k<<<(es[i].E + 255) / 256, 256>>>(es[i].src, es[i].dst, es[i].E,
                                               es[i].soff, es[i].doff, es[i].tag, cur, ent);
    if (loops) loop_fill_k<<<(n + 255) / 256, 256>>>(n, cur, ent);
}

static void run_branch(Scratch* sp, const float* xi, const float* xd,
                       const int* ec, const int* ei, const int* eo, const int* ek,
                       const float* Wk, const float* Wq, const float* Wv, const float* Wo,
                       const float* arel, const float* mrel, const float* prel,
                       const float* skip, const float* poolW, const float* poolAtt,
                       const float* poolBias, const float* tWq, const float* tWk,
                       const float* tWv, const float* tWo, const float* lng,
                       const float* lnb, int branch)
{
    const long DD = (long)kD * kD;
    const long T1 = (long)kNI * kD;    // type-1 offset in node buffers

    // assemble x = [x_inst ; x_data]
    cudaMemcpyAsync(sp->x, xi, T1 * sizeof(float), cudaMemcpyDeviceToDevice, 0);
    cudaMemcpyAsync(sp->x + T1, xd, (long)kND * kD * sizeof(float),
                    cudaMemcpyDeviceToDevice, 0);

    const int *rc = ec, *cc = ec + kEC;
    const int *ri = ei, *ci = ei + kEI;
    const int *ro = eo, *co = eo + kEO;
    const int *rk = ek, *ck = ek + kEK;

    // HGT CSRs (type-local indices; tag = relation id)
    { EdgeSpec e[3] = { {rc, cc, kEC, 0, 0, 0}, {ri, ci, kEI, 0, 0, 1}, {rk, ck, kEK, 0, 0, 3} };
      build_csr(kNI, sp->rpf0, sp->ef0, sp->cnt, sp->cur, e, 3, false); }
    { EdgeSpec e[1] = { {ro, co, kEO, 0, 0, 2} };
      build_csr(kND, sp->rpf1, sp->ef1, sp->cnt, sp->cur, e, 1, false); }
    { EdgeSpec e[3] = { {cc, rc, kEC, 0, 0, 0}, {co, ro, kEO, 0, 0, 2}, {ck, rk, kEK, 0, 0, 3} };
      build_csr(kNI, sp->rpr0, sp->er0, sp->cnt, sp->cur, e, 3, false); }
    { EdgeSpec e[1] = { {ci, ri, kEI, 0, 0, 1} };
      build_csr(kND, sp->rpr1, sp->er1, sp->cnt, sp->cur, e, 1, false); }
    // homogeneous CSR for pooling GAT (inst first, data offset +kNI, self-loops)
    { EdgeSpec e[4] = { {rc, cc, kEC, 0, 0, 0}, {ri, ci, kEI, kNI, 0, 0},
                        {ro, co, kEO, 0, kNI, 0}, {rk, ck, kEK, 0, 0, 0} };
      build_csr(kNT, sp->rph, sp->eh, sp->cnt, sp->cur, e, 4, true); }

    static const int fwdsrc[4] = {0, 1, 0, 0};
    static const int revsrc[4] = {0, 0, 1, 0};

    for (int l = 0; l < 2; l++) {
        for (int dir = 0; dir < 2; dir++) {
            long wOff = (long)((l * 2 + dir) * 2) * DD;
            // K, Q, V per node type
            for (int t = 0; t < 2; t++) {
                const float* xb = sp->x + (t ? T1 : 0);
                int M = t ? kND : kNI;
                long tOff = t ? T1 : 0;
                gemm(false, xb, kD, 0, 0, Wk + wOff + t * DD, kD, 0, 0,
                     sp->Kb + tOff, kD, 0, 0, nullptr, 0, nullptr,
                     M, kD, kD, 1, 1, 1.f, 0);
                gemm(false, xb, kD, 0, 0, Wq + wOff + t * DD, kD, 0, 0,
                     sp->Qb + tOff, kD, 0, 0, nullptr, 0, nullptr,
                     M, kD, kD, 1, 1, 1.f, 0);
                gemm(false, xb, kD, 0, 0, Wv + wOff + t * DD, kD, 0, 0,
                     sp->Vb + tOff, kD, 0, 0, nullptr, 0, nullptr,
                     M, kD, kD, 1, 1, 1.f, 0);
            }
            // Krel / Vrel (per-relation per-head 64x64 transforms, z-batched over heads)
            for (int r = 0; r < 4; r++) {
                int st = dir ? revsrc[r] : fwdsrc[r];
                int M = st ? kND : kNI;
                long sOff = st ? T1 : 0;
                long relOff = (long)(((l * 2 + dir) * 4 + r) * kH) * kDH * kDH;
                gemm(false, sp->Kb + sOff, kD, 0, 64, arel + relOff, kDH, 0, (long)kDH * kDH,
                     sp->Krel + (long)r * kNI * kD, kD, 0, 64, nullptr, 0, nullptr,
                     M, kDH, kDH, 1, kH, 1.f, 0);
                gemm(false, sp->Vb + sOff, kD, 0, 64, mrel + relOff, kDH, 0, (long)kDH * kDH,
                     sp->Vrel + (long)r * kNI * kD, kD, 0, 64, nullptr, 0, nullptr,
                     M, kDH, kDH, 1, kH, 1.f, 0);
            }
            // aggregation
            const float* prelp = prel + (long)((l * 2 + dir) * 4) * kH;
            if (dir == 0) {
                hgt_agg_k<<<kNI, 128>>>(sp->Qb, sp->Krel, sp->Vrel, sp->rpf0, sp->ef0,
                                        prelp, sp->agg, 0);
                hgt_agg_k<<<kND, 128>>>(sp->Qb, sp->Krel, sp->Vrel, sp->rpf1, sp->ef1,
                                        prelp, sp->agg, kNI);
            } else {
                hgt_agg_k<<<kNI, 128>>>(sp->Qb, sp->Krel, sp->Vrel, sp->rpr0, sp->er0,
                                        prelp, sp->agg, 0);
                hgt_agg_k<<<kND, 128>>>(sp->Qb, sp->Krel, sp->Vrel, sp->rpr1, sp->er1,
                                        prelp, sp->agg, kNI);
            }
            // gelu -> Kb (Kb no longer needed), then Wo with sigmoid-skip blend
            gelu_k<<<(int)(LXD / 256), 256>>>(sp->agg, sp->Kb, LXD);
            float* yD = dir ? sp->yR : sp->yF;
            for (int t = 0; t < 2; t++) {
                int M = t ? kND : kNI;
                long tOff = t ? T1 : 0;
                gemm(false, sp->Kb + tOff, kD, 0, 0, Wo + wOff + t * DD, kD, 0, 0,
                     yD + tOff, kD, 0, 0, sp->x + tOff, kD,
                     skip + (l * 2 + dir) * 2 + t, M, kD, kD, 1, 1, 1.f, 1);
            }
        }
        comb_relu_k<<<(int)(LXD / 256), 256>>>(sp->yF, sp->yR, sp->x, LXD);
    }

    // pooling
    hv_k<<<kNT / 8, 256>>>(sp->x, poolW, sp->hv);
    gat_score_k<<<(kNT + 255) / 256, 256>>>(sp->hv, sp->rph, sp->eh, poolAtt, poolBias, sp->sc);
    topk_sort_k<<<kB, 1024>>>(sp->sc, sp->sv, sp->si);
    gather_k<<<dim3(kKP, kB), kD>>>(sp->x, sp->sv, sp->si, sp->xp);

    // transformer attention over pooled nodes
    int Mp = kB * kKP;
    gemm(false, sp->xp, kD, 0, 0, tWq, kD, 0, 0, sp->qb, kD, 0, 0,
         nullptr, 0, nullptr, Mp, kD, kD, 1, 1, 1.f, 0);
    gemm(false, sp->xp, kD, 0, 0, tWk, kD, 0, 0, sp->kb, kD, 0, 0,
         nullptr, 0, nullptr, Mp, kD, kD, 1, 1, 1.f, 0);
    gemm(false, sp->xp, kD, 0, 0, tWv, kD, 0, 0, sp->vb, kD, 0, 0,
         nullptr, 0, nullptr, Mp, kD, kD, 1, 1, 1.f, 0);
    long pb = (long)kKP * kD;              // per-graph stride in pooled buffers
    long sb = (long)kH * kKP * kKP;        // per-graph stride in S
    gemm(true, sp->qb, kD, pb, kDH, sp->kb, kD, pb, kDH,
         sp->S, kKP, sb, (long)kKP * kKP, nullptr, 0, nullptr,
         kKP, kKP, kDH, kB, kH, 0.125f, 0);
    softmax_k<<<kB * kH * kKP, 256>>>(sp->S);
    gemm(false, sp->S, kKP, sb, (long)kKP * kKP, sp->vb, kD, pb, kDH,
         sp->oh, kD, pb, kDH, nullptr, 0, nullptr,
         kKP, kDH, kKP, kB, kH, 1.f, 0);
    gemm(false, sp->oh, kD, 0, 0, tWo, kD, 0, 0, sp->yb, kD, 0, 0,
         sp->xp, kD, nullptr, Mp, kD, kD, 1, 1, 1.f, 2);
    ln_k<<<Mp, kD>>>(sp->yb, lng, lnb, sp->ga);
    featsum_k<<<kB, kD>>>(sp->xp, sp->ga, sp->u + (long)branch * kB * 512);
}

extern "C" void kernel_launch(void* const* d_in, const int* in_sizes, int n_in,
                              void* d_out, int out_size) {
    Scratch* sp = nullptr;
    cudaGetSymbolAddress((void**)&sp, SC);

    const float* Wk    = (const float*)d_in[12];
    const float* Wq    = (const float*)d_in[13];
    const float* Wv    = (const float*)d_in[14];
    const float* Wo    = (const float*)d_in[15];
    const float* arel  = (const float*)d_in[16];
    const float* mrel  = (const float*)d_in[17];
    const float* prel  = (const float*)d_in[18];
    const float* skip  = (const float*)d_in[19];
    const float* poolW = (const float*)d_in[20];
    const float* poolA = (const float*)d_in[21];
    const float* poolB = (const float*)d_in[22];
    const float* tWq   = (const float*)d_in[23];
    const float* tWk   = (const float*)d_in[24];
    const float* tWv   = (const float*)d_in[25];
    const float* tWo   = (const float*)d_in[26];
    const float* lng   = (const float*)d_in[27];
    const float* lnb   = (const float*)d_in[28];

    for (int g = 0; g < 2; g++) {
        int base = g * 6;
        run_branch(sp,
                   (const float*)d_in[base + 0], (const float*)d_in[base + 1],
                   (const int*)d_in[base + 2], (const int*)d_in[base + 3],
                   (const int*)d_in[base + 4], (const int*)d_in[base + 5],
                   Wk, Wq, Wv, Wo, arel, mrel, prel, skip,
                   poolW, poolA, poolB, tWq, tWk, tWv, tWo, lng, lnb, g);
    }
    cos_k<<<kB, 512>>>(sp->u, (float*)d_out);
}

// round 8
// speedup vs baseline: 2.0096x; 1.9703x over previous
#include <cuda_runtime.h>
#include <math.h>
#include <stdint.h>

// ------------------------- problem constants -------------------------
constexpr int kNI = 8192, kND = 4096, kNT = 12288, kD = 256, kH = 4, kDH = 64;
constexpr int kB = 8, kKP = 768;
constexpr int kEC = 65536, kEI = 32768, kEO = 32768, kEK = 8192;
constexpr long LXD = (long)kNT * kD;
constexpr long LPD = (long)kB * kKP * kD;

// counter-region offsets (5 CSRs share one cnt/cur buffer)
constexpr int O0 = 0;                 // f0 (inst dst)
constexpr int O1 = kNI;               // f1 (data dst)
constexpr int O2 = kNI + kND;         // r0
constexpr int O3 = 2 * kNI + kND;     // r1
constexpr int O4 = 2 * kNI + 2 * kND; // hg
constexpr int CNT_TOT = O4 + kNT;

// fused edge-slot boundaries
constexpr int BB0 = kEC;                 // f0 control
constexpr int BB1 = BB0 + kEI;           // f0 input
constexpr int BB2 = BB1 + kEK;           // f0 call
constexpr int BB3 = BB2 + kEO;           // f1 output
constexpr int BB4 = BB3 + kEC;           // r0 control
constexpr int BB5 = BB4 + kEO;           // r0 output
constexpr int BB6 = BB5 + kEK;           // r0 call
constexpr int BB7 = BB6 + kEI;           // r1 input
constexpr int BB8 = BB7 + kEC;           // hg control
constexpr int BB9 = BB8 + kEI;           // hg input
constexpr int BB10 = BB9 + kEO;          // hg output
constexpr int BB11 = BB10 + kEK;         // hg call
constexpr int BB12 = BB11 + kNT;         // hg self loops

// ------------------------- scratch -------------------------
struct Scratch {
    float x[LXD], yF[LXD], yR[LXD], Kb[LXD], Qb[LXD], Vb[LXD], agg[LXD];
    float Krel[4L * kNI * kD], Vrel[4L * kNI * kD];
    float S[(long)kB * kH * kKP * kKP];
    float xp[LPD], qb[LPD], kb[LPD], vb[LPD], oh[LPD], yb[LPD], ga[LPD];
    float hv[kNT], sc[kNT];
    float sv[kB * kKP];
    int   si[kB * kKP];
    float u[2 * kB * 512];
    int rpf0[kNI + 1], rpf1[kND + 1], rpr0[kNI + 1], rpr1[kND + 1], rph[kNT + 1];
    int ef0[kEC + kEI + kEK], ef1[kEO], er0[kEC + kEO + kEK], er1[kEI];
    int eh[kEC + kEI + kEO + kEK + kNT];
    int cnt[CNT_TOT], cur[CNT_TOT];
};
__device__ Scratch SC;

// ------------------------- reductions -------------------------
__device__ __forceinline__ float wsum(float v) {
#pragma unroll
    for (int o = 16; o; o >>= 1) v += __shfl_xor_sync(0xffffffffu, v, o);
    return v;
}
__device__ __forceinline__ float bsum(float v) {
    __shared__ float sh[32];
    int lane = threadIdx.x & 31, w = threadIdx.x >> 5;
    v = wsum(v);
    if (!lane) sh[w] = v;
    __syncthreads();
    int nw = blockDim.x >> 5;
    float s = (threadIdx.x < nw) ? sh[threadIdx.x] : 0.f;
    if (w == 0) s = wsum(s);
    if (threadIdx.x == 0) sh[0] = s;
    __syncthreads();
    float r = sh[0];
    __syncthreads();
    return r;
}
__device__ __forceinline__ float bmax(float v) {
    __shared__ float sh[32];
    int lane = threadIdx.x & 31, w = threadIdx.x >> 5;
#pragma unroll
    for (int o = 16; o; o >>= 1) v = fmaxf(v, __shfl_xor_sync(0xffffffffu, v, o));
    if (!lane) sh[w] = v;
    __syncthreads();
    int nw = blockDim.x >> 5;
    float s = (threadIdx.x < nw) ? sh[threadIdx.x] : -INFINITY;
    if (w == 0)
#pragma unroll
        for (int o = 16; o; o >>= 1) s = fmaxf(s, __shfl_xor_sync(0xffffffffu, s, o));
    if (threadIdx.x == 0) sh[0] = s;
    __syncthreads();
    float r = sh[0];
    __syncthreads();
    return r;
}

// ------------------------- tf32 tensor-core GEMM -------------------------
__device__ __forceinline__ uint32_t cvt_tf32(float x) {
    uint32_t u;
    asm("cvt.rna.tf32.f32 %0, %1;" : "=r"(u) : "f"(x));
    return u;
}
__device__ __forceinline__ void mma_tf32(float* c, const uint32_t* a,
                                         uint32_t b0, uint32_t b1) {
    asm volatile(
        "mma.sync.aligned.m16n8k8.row.col.f32.tf32.tf32.f32 "
        "{%0,%1,%2,%3}, {%4,%5,%6,%7}, {%8,%9}, {%0,%1,%2,%3};"
        : "+f"(c[0]), "+f"(c[1]), "+f"(c[2]), "+f"(c[3])
        : "r"(a[0]), "r"(a[1]), "r"(a[2]), "r"(a[3]), "r"(b0), "r"(b1));
}

// C = epilogue(alpha * A @ B(^T)); z -> (zb = z/ZH, zh = z%ZH).
// BM=128, BK=32, BN in {128,64}; 256 threads, warps 4(m) x 2(n).
// mode 0: C = v ; mode 1: C = g*v+(1-g)*Add (g=sigmoid(*gptr)) ; mode 2: C = v+Add
template <int BN, bool TB>
__global__ void __launch_bounds__(256) tgemm_k(
    const float* __restrict__ A, int lda, long Ab, long Ah,
    const float* __restrict__ Bm, int ldb, long Bb, long Bh,
    float* __restrict__ C, int ldc, long Cb, long Ch,
    const float* __restrict__ Add, int ldadd, const float* __restrict__ gptr,
    int Kdim, int ZH, float alpha, int mode)
{
    constexpr int BM = 128, BK = 32;
    constexpr int AST = BM + 8;           // strides chosen so bank = 8*tg + g
    constexpr int BST = BN + 8;
    constexpr int TN = (BN == 128) ? 8 : 4;   // n8 tiles per warp
    __shared__ uint32_t As[BK][AST];      // [k][m] tf32
    __shared__ uint32_t Bs[BK][BST];      // [k][n] tf32

    int z = blockIdx.z, zb = z / ZH, zh = z - zb * ZH;
    A  += zb * Ab + zh * Ah;
    Bm += zb * Bb + zh * Bh;
    C  += zb * Cb + zh * Ch;
    int m0 = blockIdx.x * BM, n0 = blockIdx.y * BN;
    int tid = threadIdx.x, lane = tid & 31, warp = tid >> 5;
    int wm = warp >> 1, wn = warp & 1;
    int g = lane >> 2, tg = lane & 3;

    float acc[2][TN][4];
#pragma unroll
    for (int i = 0; i < 2; i++)
#pragma unroll
        for (int j = 0; j < TN; j++)
#pragma unroll
            for (int q = 0; q < 4; q++) acc[i][j][q] = 0.f;

    for (int k0 = 0; k0 < Kdim; k0 += BK) {
        // ---- A tile: 128 rows x 32 k, stored As[k][m]
#pragma unroll
        for (int kq = 0; kq < 4; kq++) {
            int r = tid >> 1, c = (tid & 1) * 4 + kq * 8;
            float4 v = *(const float4*)(A + (long)(m0 + r) * lda + k0 + c);
            As[c + 0][r] = cvt_tf32(v.x); As[c + 1][r] = cvt_tf32(v.y);
            As[c + 2][r] = cvt_tf32(v.z); As[c + 3][r] = cvt_tf32(v.w);
        }
        // ---- B tile -> Bs[k][n]
        if (TB) {
            if (BN == 128) {
#pragma unroll
                for (int kq = 0; kq < 4; kq++) {
                    int n = tid >> 1, c = (tid & 1) * 4 + kq * 8;
                    float4 v = *(const float4*)(Bm + (long)(n0 + n) * ldb + k0 + c);
                    Bs[c + 0][n] = cvt_tf32(v.x); Bs[c + 1][n] = cvt_tf32(v.y);
                    Bs[c + 2][n] = cvt_tf32(v.z); Bs[c + 3][n] = cvt_tf32(v.w);
                }
            } else {
#pragma unroll
                for (int kq = 0; kq < 2; kq++) {
                    int n = tid >> 2, c = (tid & 3) * 4 + kq * 16;
                    float4 v = *(const float4*)(Bm + (long)(n0 + n) * ldb + k0 + c);
                    Bs[c + 0][n] = cvt_tf32(v.x); Bs[c + 1][n] = cvt_tf32(v.y);
                    Bs[c + 2][n] = cvt_tf32(v.z); Bs[c + 3][n] = cvt_tf32(v.w);
                }
            }
        } else {
            if (BN == 128) {
#pragma unroll
                for (int kq = 0; kq < 4; kq++) {
                    int kr = (tid >> 5) + kq * 8, c = lane * 4;
                    float4 v = *(const float4*)(Bm + (long)(k0 + kr) * ldb + n0 + c);
                    uint4 u;
                    u.x = cvt_tf32(v.x); u.y = cvt_tf32(v.y);
                    u.z = cvt_tf32(v.z); u.w = cvt_tf32(v.w);
                    *(uint4*)&Bs[kr][c] = u;
                }
            } else {
#pragma unroll
                for (int kq = 0; kq < 2; kq++) {
                    int kr = (tid >> 4) + kq * 16, c = (tid & 15) * 4;
                    float4 v = *(const float4*)(Bm + (long)(k0 + kr) * ldb + n0 + c);
                    uint4 u;
                    u.x = cvt_tf32(v.x); u.y = cvt_tf32(v.y);
                    u.z = cvt_tf32(v.z); u.w = cvt_tf32(v.w);
                    *(uint4*)&Bs[kr][c] = u;
                }
            }
        }
        __syncthreads();
#pragma unroll
        for (int k8 = 0; k8 < 4; k8++) {
            int kb = k8 * 8;
            uint32_t a[2][4];
#pragma unroll
            for (int tm = 0; tm < 2; tm++) {
                int mr = wm * 32 + tm * 16;
                a[tm][0] = As[kb + tg][mr + g];
                a[tm][1] = As[kb + tg][mr + 8 + g];
                a[tm][2] = As[kb + tg + 4][mr + g];
                a[tm][3] = As[kb + tg + 4][mr + 8 + g];
            }
#pragma unroll
            for (int tn = 0; tn < TN; tn++) {
                int nc = wn * (TN * 8) + tn * 8 + g;
                uint32_t b0 = Bs[kb + tg][nc];
                uint32_t b1 = Bs[kb + tg + 4][nc];
#pragma unroll
                for (int tm = 0; tm < 2; tm++)
                    mma_tf32(acc[tm][tn], a[tm], b0, b1);
            }
        }
        __syncthreads();
    }

    float gg = 1.f;
    if (mode == 1) gg = 1.f / (1.f + expf(-gptr[0]));
#pragma unroll
    for (int tm = 0; tm < 2; tm++) {
        long row0 = m0 + wm * 32 + tm * 16 + g;
#pragma unroll
        for (int tn = 0; tn < TN; tn++) {
            long col = n0 + wn * (TN * 8) + tn * 8 + tg * 2;
#pragma unroll
            for (int half = 0; half < 2; half++) {
                long r = row0 + half * 8;
                float vx = alpha * acc[tm][tn][half * 2 + 0];
                float vy = alpha * acc[tm][tn][half * 2 + 1];
                if (mode == 1) {
                    float2 ad = *(const float2*)(Add + r * ldadd + col);
                    vx = gg * vx + (1.f - gg) * ad.x;
                    vy = gg * vy + (1.f - gg) * ad.y;
                } else if (mode == 2) {
                    float2 ad = *(const float2*)(Add + r * ldadd + col);
                    vx += ad.x; vy += ad.y;
                }
                float2 o; o.x = vx; o.y = vy;
                *(float2*)(C + r * ldc + col) = o;
            }
        }
    }
}

// ------------------------- elementwise kernels -------------------------
__global__ void assemble_x_k(const float* __restrict__ xi, const float* __restrict__ xd,
                             float* __restrict__ x) {
    long i = ((long)blockIdx.x * blockDim.x + threadIdx.x) * 4;
    if (i < LXD) {
        const long T1 = (long)kNI * kD;
        float4 v = (i < T1) ? *(const float4*)(xi + i) : *(const float4*)(xd + (i - T1));
        *(float4*)(x + i) = v;
    }
}
__global__ void gelu_k(const float* __restrict__ in, float* __restrict__ out, long n) {
    long i = (long)blockIdx.x * blockDim.x + threadIdx.x;
    if (i < n) {
        float v = in[i];
        out[i] = 0.5f * v * (1.f + erff(v * 0.7071067811865475f));
    }
}
__global__ void comb_relu_k(const float* __restrict__ a, const float* __restrict__ b,
                            float* __restrict__ x, long n) {
    long i = (long)blockIdx.x * blockDim.x + threadIdx.x;
    if (i < n) {
        float v = 0.5f * a[i] + 0.5f * b[i];
        x[i] = v > 0.f ? v : 0.f;
    }
}

// ------------------------- fused CSR construction -------------------------
// decode slot -> (cnt offset+dst, packed entry, ent array id)
struct Slot { int idx; int ent; int arr; };
__device__ __forceinline__ Slot decode_slot(
    int i, const int* rc, const int* cc, const int* ri, const int* ci,
    const int* ro, const int* co, const int* rk, const int* ck)
{
    Slot s;
    if (i < BB0)       { s.idx = O0 + cc[i];            s.ent = (0 << 16) | rc[i];            s.arr = 0; }
    else if (i < BB1)  { int j = i - BB0;  s.idx = O0 + ci[j]; s.ent = (1 << 16) | ri[j];     s.arr = 0; }
    else if (i < BB2)  { int j = i - BB1;  s.idx = O0 + ck[j]; s.ent = (3 << 16) | rk[j];     s.arr = 0; }
    else if (i < BB3)  { int j = i - BB2;  s.idx = O1 + co[j]; s.ent = (2 << 16) | ro[j];     s.arr = 1; }
    else if (i < BB4)  { int j = i - BB3;  s.idx = O2 + rc[j]; s.ent = (0 << 16) | cc[j];     s.arr = 2; }
    else if (i < BB5)  { int j = i - BB4;  s.idx = O2 + ro[j]; s.ent = (2 << 16) | co[j];     s.arr = 2; }
    else if (i < BB6)  { int j = i - BB5;  s.idx = O2 + rk[j]; s.ent = (3 << 16) | ck[j];     s.arr = 2; }
    else if (i < BB7)  { int j = i - BB6;  s.idx = O3 + ri[j]; s.ent = (1 << 16) | ci[j];     s.arr = 3; }
    else if (i < BB8)  { int j = i - BB7;  s.idx = O4 + cc[j]; s.ent = rc[j];                 s.arr = 4; }
    else if (i < BB9)  { int j = i - BB8;  s.idx = O4 + ci[j]; s.ent = ri[j] + kNI;           s.arr = 4; }
    else if (i < BB10) { int j = i - BB9;  s.idx = O4 + co[j] + kNI; s.ent = ro[j];           s.arr = 4; }
    else               { int j = i - BB10; s.idx = O4 + ck[j]; s.ent = rk[j];                 s.arr = 4; }
    return s;
}

__global__ void csr_zero_k(Scratch* sp) {
    int i = blockIdx.x * blockDim.x + threadIdx.x;
    if (i < CNT_TOT) sp->cnt[i] = 0;
}
__global__ void csr_count_k(Scratch* sp, const int* rc, const int* cc,
                            const int* ri, const int* ci, const int* ro, const int* co,
                            const int* rk, const int* ck) {
    int i = blockIdx.x * blockDim.x + threadIdx.x;
    if (i < BB11) {
        Slot s = decode_slot(i, rc, cc, ri, ci, ro, co, rk, ck);
        atomicAdd(&sp->cnt[s.idx], 1);
    }
}
__global__ void csr_scan_k(Scratch* sp) {
    __shared__ int sh[1024];
    int region = blockIdx.x, t = threadIdx.x;
    int off, n, extra = 0;
    int* rp;
    switch (region) {
        case 0: off = O0; n = kNI; rp = sp->rpf0; break;
        case 1: off = O1; n = kND; rp = sp->rpf1; break;
        case 2: off = O2; n = kNI; rp = sp->rpr0; break;
        case 3: off = O3; n = kND; rp = sp->rpr1; break;
        default: off = O4; n = kNT; rp = sp->rph; extra = 1; break;  // self loops
    }
    int c = (n + 1023) >> 10;
    int beg = t * c, end = min(beg + c, n);
    int s = 0;
    for (int i = beg; i < end; i++) s += sp->cnt[off + i] + extra;
    sh[t] = s;
    __syncthreads();
    for (int o = 1; o < 1024; o <<= 1) {
        int v = (t >= o) ? sh[t - o] : 0;
        __syncthreads();
        sh[t] += v;
        __syncthreads();
    }
    int run = t ? sh[t - 1] : 0;
    for (int i = beg; i < end; i++) {
        rp[i] = run;
        sp->cur[off + i] = run;
        run += sp->cnt[off + i] + extra;
    }
    if (t == 1023) rp[n] = sh[1023];
}
__global__ void csr_fill_k(Scratch* sp, const int* rc, const int* cc,
                           const int* ri, const int* ci, const int* ro, const int* co,
                           const int* rk, const int* ck) {
    int i = blockIdx.x * blockDim.x + threadIdx.x;
    if (i >= BB12) return;
    if (i < BB11) {
        Slot s = decode_slot(i, rc, cc, ri, ci, ro, co, rk, ck);
        int pos = atomicAdd(&sp->cur[s.idx], 1);
        switch (s.arr) {
            case 0: sp->ef0[pos] = s.ent; break;
            case 1: sp->ef1[pos] = s.ent; break;
            case 2: sp->er0[pos] = s.ent; break;
            case 3: sp->er1[pos] = s.ent; break;
            default: sp->eh[pos] = s.ent; break;
        }
    } else {
        int node = i - BB11;
        int pos = atomicAdd(&sp->cur[O4 + node], 1);
        sp->eh[pos] = node;
    }
}

// ------------------------- HGT softmax aggregation -------------------------
__global__ void hgt_agg_k(const float* __restrict__ Q, const float* __restrict__ Krel,
                          const float* __restrict__ Vrel, const int* __restrict__ rp,
                          const int* __restrict__ ent, const float* __restrict__ prel,
                          float* __restrict__ agg, int dstBase)
{
    int node = blockIdx.x;
    int h = threadIdx.x >> 5, lane = threadIdx.x & 31;
    const float* q = Q + (long)(dstBase + node) * kD + h * kDH;
    float q0 = q[lane], q1 = q[lane + 32];
    float pr0 = prel[0 * kH + h], pr1 = prel[1 * kH + h];
    float pr2 = prel[2 * kH + h], pr3 = prel[3 * kH + h];
    int s = rp[node], e1 = rp[node + 1];
    float m = -INFINITY, den = 0.f, a0 = 0.f, a1 = 0.f;
    for (int e = s; e < e1; e++) {
        int pk = ent[e];
        int r = pk >> 16, src = pk & 0xffff;
        const float* kr = Krel + ((long)r * kNI + src) * kD + h * kDH;
        float d0 = q0 * kr[lane] + q1 * kr[lane + 32];
        d0 = wsum(d0);
        float pr = (r == 0) ? pr0 : (r == 1) ? pr1 : (r == 2) ? pr2 : pr3;
        float sc2 = d0 * pr * 0.125f;
        float mn = fmaxf(m, sc2);
        float cc = expf(m - mn), w = expf(sc2 - mn);
        const float* vr = Vrel + ((long)r * kNI + src) * kD + h * kDH;
        den = den * cc + w;
        a0 = a0 * cc + w * vr[lane];
        a1 = a1 * cc + w * vr[lane + 32];
        m = mn;
    }
    float inv = 1.f / (den + 1e-16f);
    float* o = agg + (long)(dstBase + node) * kD + h * kDH;
    o[lane] = a0 * inv;
    o[lane + 32] = a1 * inv;
}

// ------------------------- pooling -------------------------
__global__ void hv_k(const float* __restrict__ x, const float* __restrict__ pw,
                     float* __restrict__ hv) {
    int node = blockIdx.x * 8 + (threadIdx.x >> 5);
    int lane = threadIdx.x & 31;
    if (node >= kNT) return;
    float s = 0.f;
    for (int d = lane; d < kD; d += 32) s += x[(long)node * kD + d] * pw[d];
    s = wsum(s);
    if (!lane) hv[node] = s;
}
__global__ void gat_score_k(const float* __restrict__ hv, const int* __restrict__ rp,
                            const int* __restrict__ ent, const float* __restrict__ att,
                            const float* __restrict__ bias, float* __restrict__ sc) {
    int i = blockIdx.x * blockDim.x + threadIdx.x;
    if (i >= kNT) return;
    float A0 = att[0], A1 = att[1];
    float hi = hv[i];
    int s = rp[i], e1 = rp[i + 1];
    float m = -INFINITY, den = 0.f, acc = 0.f;
    for (int e = s; e < e1; e++) {
        int src = ent[e] & 0xffff;
        float hs = hv[src];
        float ee = A0 * hs + A1 * hi;
        ee = ee >= 0.f ? ee : 0.2f * ee;
        float mn = fmaxf(m, ee);
        float c = expf(m - mn), w = expf(ee - mn);
        den = den * c + w;
        acc = acc * c + w * hs;
        m = mn;
    }
    sc[i] = acc / (den + 1e-16f) + bias[0];
}

__global__ void topk_sort_k(const float* __restrict__ sc, float* __restrict__ sv,
                            int* __restrict__ si) {
    int b = blockIdx.x, t = threadIdx.x;
    __shared__ float v[2048];
    __shared__ int ix[2048];
    for (int p = t; p < 2048; p += 1024) {
        float val = -INFINITY;
        if (p < 1536) {
            int node = p < 1024 ? b * 1024 + p : kNI + b * 512 + (p - 1024);
            val = sc[node];
        }
        v[p] = val;
        ix[p] = p;
    }
    __syncthreads();
    for (int k = 2; k <= 2048; k <<= 1)
        for (int j = k >> 1; j > 0; j >>= 1) {
#pragma unroll
            for (int pass = 0; pass < 2; pass++) {
                int i = t + pass * 1024;
                int l = i ^ j;
                if (l > i) {
                    bool up = ((i & k) == 0);
                    float vi = v[i], vl = v[l];
                    int ii = ix[i], il = ix[l];
                    bool before = (vi > vl) || (vi == vl && ii < il);
                    if (up != before) {
                        v[i] = vl; v[l] = vi;
                        ix[i] = il; ix[l] = ii;
                    }
                }
            }
            __syncthreads();
        }
    if (t < kKP) {
        sv[b * kKP + t] = v[t];
        si[b * kKP + t] = ix[t];
    }
}
__global__ void gather_k(const float* __restrict__ x, const float* __restrict__ sv,
                         const int* __restrict__ si, float* __restrict__ xp) {
    int q = blockIdx.x, b = blockIdx.y, d = threadIdx.x;
    int j = si[b * kKP + q];
    float tv = tanhf(sv[b * kKP + q]);
    int node = j < 1024 ? b * 1024 + j : kNI + b * 512 + (j - 1024);
    xp[((long)(b * kKP + q)) * kD + d] = x[(long)node * kD + d] * tv;
}

// ------------------------- transformer pieces -------------------------
__global__ void softmax_k(float* __restrict__ S) {
    long row = blockIdx.x;
    float* p = S + row * kKP;
    int t = threadIdx.x;
    float m = -INFINITY;
    for (int i = t; i < kKP; i += 256) m = fmaxf(m, p[i]);
    m = bmax(m);
    float s = 0.f;
    for (int i = t; i < kKP; i += 256) {
        float e = expf(p[i] - m);
        p[i] = e;
        s += e;
    }
    s = bsum(s);
    float inv = 1.f / s;
    for (int i = t; i < kKP; i += 256) p[i] *= inv;
}
__global__ void ln_k(const float* __restrict__ y, const float* __restrict__ g,
                     const float* __restrict__ bta, float* __restrict__ out) {
    long row = blockIdx.x;
    int d = threadIdx.x;
    float v = y[row * kD + d];
    float mu = bsum(v) * (1.f / kD);
    float df = v - mu;
    float var = bsum(df * df) * (1.f / kD);
    out[row * kD + d] = g[d] * df * rsqrtf(var + 1e-5f) + bta[d];
}
__global__ void featsum_k(const float* __restrict__ xp, const float* __restrict__ ga,
                          float* __restrict__ u) {
    int b = blockIdx.x, d = threadIdx.x;
    float s1 = 0.f, s2 = 0.f;
    for (int q = 0; q < kKP; q++) {
        long o = ((long)(b * kKP + q)) * kD + d;
        s1 += xp[o];
        s2 += ga[o];
    }
    u[b * 512 + d] = s1;
    u[b * 512 + 256 + d] = s2;
}
__global__ void cos_k(const float* __restrict__ u, float* __restrict__ out) {
    int b = blockIdx.x, t = threadIdx.x;
    float a = u[b * 512 + t];
    float c = u[(kB + b) * 512 + t];
    float dot = bsum(a * c);
    float na = bsum(a * a);
    float nc = bsum(c * c);
    if (t == 0)
        out[b] = dot / (fmaxf(sqrtf(na), 1e-8f) * fmaxf(sqrtf(nc), 1e-8f));
}

// ------------------------- host orchestration -------------------------
static inline void gemm(bool tb, const float* A, int lda, long Ab, long Ah,
                        const float* Bm, int ldb, long Bb, long Bh,
                        float* C, int ldc, long Cb, long Ch,
                        const float* Add, int ldadd, const float* gptr,
                        int M, int N, int K, int ZB, int ZH, float alpha, int mode) {
    if (N % 128 == 0) {
        dim3 g(M / 128, N / 128, ZB * ZH), blk(256);
        if (tb)
            tgemm_k<128, true><<<g, blk>>>(A, lda, Ab, Ah, Bm, ldb, Bb, Bh, C, ldc, Cb, Ch,
                                           Add, ldadd, gptr, K, ZH, alpha, mode);
        else
            tgemm_k<128, false><<<g, blk>>>(A, lda, Ab, Ah, Bm, ldb, Bb, Bh, C, ldc, Cb, Ch,
                                            Add, ldadd, gptr, K, ZH, alpha, mode);
    } else {
        dim3 g(M / 128, N / 64, ZB * ZH), blk(256);
        if (tb)
            tgemm_k<64, true><<<g, blk>>>(A, lda, Ab, Ah, Bm, ldb, Bb, Bh, C, ldc, Cb, Ch,
                                          Add, ldadd, gptr, K, ZH, alpha, mode);
        else
            tgemm_k<64, false><<<g, blk>>>(A, lda, Ab, Ah, Bm, ldb, Bb, Bh, C, ldc, Cb, Ch,
                                           Add, ldadd, gptr, K, ZH, alpha, mode);
    }
}

static void run_branch(Scratch* sp, const float* xi, const float* xd,
                       const int* ec, const int* ei, const int* eo, const int* ek,
                       const float* Wk, const float* Wq, const float* Wv, const float* Wo,
                       const float* arel, const float* mrel, const float* prel,
                       const float* skip, const float* poolW, const float* poolAtt,
                       const float* poolBias, const float* tWq, const float* tWk,
                       const float* tWv, const float* tWo, const float* lng,
                       const float* lnb, int branch)
{
    const long DD = (long)kD * kD;
    const long T1 = (long)kNI * kD;

    const int *rc = ec, *cc = ec + kEC;
    const int *ri = ei, *ci = ei + kEI;
    const int *ro = eo, *co = eo + kEO;
    const int *rk = ek, *ck = ek + kEK;

    // launches 0..4: assemble x, fused CSR build (so first GEMM is launch #5)
    assemble_x_k<<<(int)(LXD / 4 + 255) / 256, 256>>>(xi, xd, sp->x);
    csr_zero_k<<<(CNT_TOT + 255) / 256, 256>>>(sp);
    csr_count_k<<<(BB11 + 255) / 256, 256>>>(sp, rc, cc, ri, ci, ro, co, rk, ck);
    csr_scan_k<<<5, 1024>>>(sp);
    csr_fill_k<<<(BB12 + 255) / 256, 256>>>(sp, rc, cc, ri, ci, ro, co, rk, ck);

    static const int fwdsrc[4] = {0, 1, 0, 0};
    static const int revsrc[4] = {0, 0, 1, 0};

    for (int l = 0; l < 2; l++) {
        for (int dir = 0; dir < 2; dir++) {
            long wOff = (long)((l * 2 + dir) * 2) * DD;
            for (int t = 0; t < 2; t++) {
                const float* xb = sp->x + (t ? T1 : 0);
                int M = t ? kND : kNI;
                long tOff = t ? T1 : 0;
                gemm(false, xb, kD, 0, 0, Wk + wOff + t * DD, kD, 0, 0,
                     sp->Kb + tOff, kD, 0, 0, nullptr, 0, nullptr,
                     M, kD, kD, 1, 1, 1.f, 0);
                gemm(false, xb, kD, 0, 0, Wq + wOff + t * DD, kD, 0, 0,
                     sp->Qb + tOff, kD, 0, 0, nullptr, 0, nullptr,
                     M, kD, kD, 1, 1, 1.f, 0);
                gemm(false, xb, kD, 0, 0, Wv + wOff + t * DD, kD, 0, 0,
                     sp->Vb + tOff, kD, 0, 0, nullptr, 0, nullptr,
                     M, kD, kD, 1, 1, 1.f, 0);
            }
            for (int r = 0; r < 4; r++) {
                int st = dir ? revsrc[r] : fwdsrc[r];
                int M = st ? kND : kNI;
                long sOff = st ? T1 : 0;
                long relOff = (long)(((l * 2 + dir) * 4 + r) * kH) * kDH * kDH;
                gemm(false, sp->Kb + sOff, kD, 0, 64, arel + relOff, kDH, 0, (long)kDH * kDH,
                     sp->Krel + (long)r * kNI * kD, kD, 0, 64, nullptr, 0, nullptr,
                     M, kDH, kDH, 1, kH, 1.f, 0);
                gemm(false, sp->Vb + sOff, kD, 0, 64, mrel + relOff, kDH, 0, (long)kDH * kDH,
                     sp->Vrel + (long)r * kNI * kD, kD, 0, 64, nullptr, 0, nullptr,
                     M, kDH, kDH, 1, kH, 1.f, 0);
            }
            const float* prelp = prel + (long)((l * 2 + dir) * 4) * kH;
            if (dir == 0) {
                hgt_agg_k<<<kNI, 128>>>(sp->Qb, sp->Krel, sp->Vrel, sp->rpf0, sp->ef0,
                                        prelp, sp->agg, 0);
                hgt_agg_k<<<kND, 128>>>(sp->Qb, sp->Krel, sp->Vrel, sp->rpf1, sp->ef1,
                                        prelp, sp->agg, kNI);
            } else {
                hgt_agg_k<<<kNI, 128>>>(sp->Qb, sp->Krel, sp->Vrel, sp->rpr0, sp->er0,
                                        prelp, sp->agg, 0);
                hgt_agg_k<<<kND, 128>>>(sp->Qb, sp->Krel, sp->Vrel, sp->rpr1, sp->er1,
                                        prelp, sp->agg, kNI);
            }
            gelu_k<<<(int)(LXD / 256), 256>>>(sp->agg, sp->Kb, LXD);
            float* yD = dir ? sp->yR : sp->yF;
            for (int t = 0; t < 2; t++) {
                int M = t ? kND : kNI;
                long tOff = t ? T1 : 0;
                gemm(false, sp->Kb + tOff, kD, 0, 0, Wo + wOff + t * DD, kD, 0, 0,
                     yD + tOff, kD, 0, 0, sp->x + tOff, kD,
                     skip + (l * 2 + dir) * 2 + t, M, kD, kD, 1, 1, 1.f, 1);
            }
        }
        comb_relu_k<<<(int)(LXD / 256), 256>>>(sp->yF, sp->yR, sp->x, LXD);
    }

    // pooling
    hv_k<<<kNT / 8, 256>>>(sp->x, poolW, sp->hv);
    gat_score_k<<<(kNT + 255) / 256, 256>>>(sp->hv, sp->rph, sp->eh, poolAtt, poolBias, sp->sc);
    topk_sort_k<<<kB, 1024>>>(sp->sc, sp->sv, sp->si);
    gather_k<<<dim3(kKP, kB), kD>>>(sp->x, sp->sv, sp->si, sp->xp);

    // transformer attention
    int Mp = kB * kKP;
    gemm(false, sp->xp, kD, 0, 0, tWq, kD, 0, 0, sp->qb, kD, 0, 0,
         nullptr, 0, nullptr, Mp, kD, kD, 1, 1, 1.f, 0);
    gemm(false, sp->xp, kD, 0, 0, tWk, kD, 0, 0, sp->kb, kD, 0, 0,
         nullptr, 0, nullptr, Mp, kD, kD, 1, 1, 1.f, 0);
    gemm(false, sp->xp, kD, 0, 0, tWv, kD, 0, 0, sp->vb, kD, 0, 0,
         nullptr, 0, nullptr, Mp, kD, kD, 1, 1, 1.f, 0);
    long pb = (long)kKP * kD;
    long sb = (long)kH * kKP * kKP;
    gemm(true, sp->qb, kD, pb, kDH, sp->kb, kD, pb, kDH,
         sp->S, kKP, sb, (long)kKP * kKP, nullptr, 0, nullptr,
         kKP, kKP, kDH, kB, kH, 0.125f, 0);
    softmax_k<<<kB * kH * kKP, 256>>>(sp->S);
    gemm(false, sp->S, kKP, sb, (long)kKP * kKP, sp->vb, kD, pb, kDH,
         sp->oh, kD, pb, kDH, nullptr, 0, nullptr,
         kKP, kDH, kKP, kB, kH, 1.f, 0);
    gemm(false, sp->oh, kD, 0, 0, tWo, kD, 0, 0, sp->yb, kD, 0, 0,
         sp->xp, kD, nullptr, Mp, kD, kD, 1, 1, 1.f, 2);
    ln_k<<<Mp, kD>>>(sp->yb, lng, lnb, sp->ga);
    featsum_k<<<kB, kD>>>(sp->xp, sp->ga, sp->u + (long)branch * kB * 512);
}

extern "C" void kernel_launch(void* const* d_in, const int* in_sizes, int n_in,
                              void* d_out, int out_size) {
    Scratch* sp = nullptr;
    cudaGetSymbolAddress((void**)&sp, SC);

    const float* Wk    = (const float*)d_in[12];
    const float* Wq    = (const float*)d_in[13];
    const float* Wv    = (const float*)d_in[14];
    const float* Wo    = (const float*)d_in[15];
    const float* arel  = (const float*)d_in[16];
    const float* mrel  = (const float*)d_in[17];
    const float* prel  = (const float*)d_in[18];
    const float* skip  = (const float*)d_in[19];
    const float* poolW = (const float*)d_in[20];
    const float* poolA = (const float*)d_in[21];
    const float* poolB = (const float*)d_in[22];
    const float* tWq   = (const float*)d_in[23];
    const float* tWk   = (const float*)d_in[24];
    const float* tWv   = (const float*)d_in[25];
    const float* tWo   = (const float*)d_in[26];
    const float* lng   = (const float*)d_in[27];
    const float* lnb   = (const float*)d_in[28];

    for (int g = 0; g < 2; g++) {
        int base = g * 6;
        run_branch(sp,
                   (const float*)d_in[base + 0], (const float*)d_in[base + 1],
                   (const int*)d_in[base + 2], (const int*)d_in[base + 3],
                   (const int*)d_in[base + 4], (const int*)d_in[base + 5],
                   Wk, Wq, Wv, Wo, arel, mrel, prel, skip,
                   poolW, poolA, poolB, tWq, tWk, tWv, tWo, lng, lnb, g);
    }
    cos_k<<<kB, 512>>>(sp->u, (float*)d_out);
}

// round 9
// speedup vs baseline: 2.4694x; 1.2288x over previous
#include <cuda_runtime.h>
#include <math.h>
#include <stdint.h>

// ------------------------- problem constants -------------------------
constexpr int kNI = 8192, kND = 4096, kNT = 12288, kD = 256, kH = 4, kDH = 64;
constexpr int kB = 8, kKP = 768;
constexpr int kEC = 65536, kEI = 32768, kEO = 32768, kEK = 8192;
constexpr long LXD = (long)kNT * kD;
constexpr long LPD = (long)kB * kKP * kD;

// counter-region offsets (5 CSRs share one cnt/cur buffer)
constexpr int O0 = 0;
constexpr int O1 = kNI;
constexpr int O2 = kNI + kND;
constexpr int O3 = 2 * kNI + kND;
constexpr int O4 = 2 * kNI + 2 * kND;
constexpr int CNT_TOT = O4 + kNT;

// fused edge-slot boundaries
constexpr int BB0 = kEC;
constexpr int BB1 = BB0 + kEI;
constexpr int BB2 = BB1 + kEK;
constexpr int BB3 = BB2 + kEO;
constexpr int BB4 = BB3 + kEC;
constexpr int BB5 = BB4 + kEO;
constexpr int BB6 = BB5 + kEK;
constexpr int BB7 = BB6 + kEI;
constexpr int BB8 = BB7 + kEC;
constexpr int BB9 = BB8 + kEI;
constexpr int BB10 = BB9 + kEO;
constexpr int BB11 = BB10 + kEK;
constexpr int BB12 = BB11 + kNT;

// ------------------------- scratch -------------------------
struct Scratch {
    float x[LXD], yF[LXD], agg[LXD];
    float kqv[3 * LXD];                       // [node][768] packed K|Q|V
    float Krel[4L * kNI * kD], Vrel[4L * kNI * kD];
    float S[(long)kB * kH * kKP * kKP];
    float xp[LPD], qkvp[3 * LPD], oh[LPD], yb[LPD], ga[LPD];
    float pW[8L * 256 * 768];                 // packed HGT KQV weights per combo
    float pTw[256 * 768];                     // packed transformer QKV weights
    float hv[kNT], sc[kNT];
    float sv[kB * kKP];
    int   si[kB * kKP];
    float u[2 * kB * 512];
    int rpf0[kNI + 1], rpf1[kND + 1], rpr0[kNI + 1], rpr1[kND + 1], rph[kNT + 1];
    int ef0[kEC + kEI + kEK], ef1[kEO], er0[kEC + kEO + kEK], er1[kEI];
    int eh[kEC + kEI + kEO + kEK + kNT];
    int cnt[CNT_TOT], cur[CNT_TOT];           // zero-initialized at load; scan re-zeroes
};
__device__ Scratch SC;

// ------------------------- reductions -------------------------
__device__ __forceinline__ float wsum(float v) {
#pragma unroll
    for (int o = 16; o; o >>= 1) v += __shfl_xor_sync(0xffffffffu, v, o);
    return v;
}
__device__ __forceinline__ float bsum(float v) {
    __shared__ float sh[32];
    int lane = threadIdx.x & 31, w = threadIdx.x >> 5;
    v = wsum(v);
    if (!lane) sh[w] = v;
    __syncthreads();
    int nw = blockDim.x >> 5;
    float s = (threadIdx.x < nw) ? sh[threadIdx.x] : 0.f;
    if (w == 0) s = wsum(s);
    if (threadIdx.x == 0) sh[0] = s;
    __syncthreads();
    float r = sh[0];
    __syncthreads();
    return r;
}
__device__ __forceinline__ float bmax(float v) {
    __shared__ float sh[32];
    int lane = threadIdx.x & 31, w = threadIdx.x >> 5;
#pragma unroll
    for (int o = 16; o; o >>= 1) v = fmaxf(v, __shfl_xor_sync(0xffffffffu, v, o));
    if (!lane) sh[w] = v;
    __syncthreads();
    int nw = blockDim.x >> 5;
    float s = (threadIdx.x < nw) ? sh[threadIdx.x] : -INFINITY;
    if (w == 0)
#pragma unroll
        for (int o = 16; o; o >>= 1) s = fmaxf(s, __shfl_xor_sync(0xffffffffu, s, o));
    if (threadIdx.x == 0) sh[0] = s;
    __syncthreads();
    float r = sh[0];
    __syncthreads();
    return r;
}

// ------------------------- tf32 tensor-core GEMM -------------------------
__device__ __forceinline__ uint32_t cvt_tf32(float x) {
    uint32_t u;
    asm("cvt.rna.tf32.f32 %0, %1;" : "=r"(u) : "f"(x));
    return u;
}
__device__ __forceinline__ void mma_tf32(float* c, const uint32_t* a,
                                         uint32_t b0, uint32_t b1) {
    asm volatile(
        "mma.sync.aligned.m16n8k8.row.col.f32.tf32.tf32.f32 "
        "{%0,%1,%2,%3}, {%4,%5,%6,%7}, {%8,%9}, {%0,%1,%2,%3};"
        : "+f"(c[0]), "+f"(c[1]), "+f"(c[2]), "+f"(c[3])
        : "r"(a[0]), "r"(a[1]), "r"(a[2]), "r"(a[3]), "r"(b0), "r"(b1));
}

// C = epilogue(alpha * A @ B(^T)); z -> (zb = z/ZH, zh = z%ZH).
// mode 0: C = v
// mode 1: C = g*v + (1-g)*Add                    (g = sigmoid(*gptr))
// mode 2: C = v + Add
// mode 3: C = relu(0.5*(g*v + (1-g)*Add) + 0.5*Add2)
template <int BN, bool TB>
__global__ void __launch_bounds__(256) tgemm_k(
    const float* __restrict__ A, int lda, long Ab, long Ah,
    const float* __restrict__ Bm, int ldb, long Bb, long Bh,
    float* __restrict__ C, int ldc, long Cb, long Ch,
    const float* __restrict__ Add, int ldadd, const float* __restrict__ Add2,
    const float* __restrict__ gptr,
    int Kdim, int ZH, float alpha, int mode)
{
    constexpr int BM = 128, BK = 32;
    constexpr int AST = BM + 8;
    constexpr int BST = BN + 8;
    constexpr int TN = (BN == 128) ? 8 : 4;
    __shared__ uint32_t As[BK][AST];
    __shared__ uint32_t Bs[BK][BST];

    int z = blockIdx.z, zb = z / ZH, zh = z - zb * ZH;
    A  += zb * Ab + zh * Ah;
    Bm += zb * Bb + zh * Bh;
    C  += zb * Cb + zh * Ch;
    int m0 = blockIdx.x * BM, n0 = blockIdx.y * BN;
    int tid = threadIdx.x, lane = tid & 31, warp = tid >> 5;
    int wm = warp >> 1, wn = warp & 1;
    int g = lane >> 2, tg = lane & 3;

    float acc[2][TN][4];
#pragma unroll
    for (int i = 0; i < 2; i++)
#pragma unroll
        for (int j = 0; j < TN; j++)
#pragma unroll
            for (int q = 0; q < 4; q++) acc[i][j][q] = 0.f;

    for (int k0 = 0; k0 < Kdim; k0 += BK) {
#pragma unroll
        for (int kq = 0; kq < 4; kq++) {
            int r = tid >> 1, c = (tid & 1) * 4 + kq * 8;
            float4 v = *(const float4*)(A + (long)(m0 + r) * lda + k0 + c);
            As[c + 0][r] = cvt_tf32(v.x); As[c + 1][r] = cvt_tf32(v.y);
            As[c + 2][r] = cvt_tf32(v.z); As[c + 3][r] = cvt_tf32(v.w);
        }
        if (TB) {
            if (BN == 128) {
#pragma unroll
                for (int kq = 0; kq < 4; kq++) {
                    int n = tid >> 1, c = (tid & 1) * 4 + kq * 8;
                    float4 v = *(const float4*)(Bm + (long)(n0 + n) * ldb + k0 + c);
                    Bs[c + 0][n] = cvt_tf32(v.x); Bs[c + 1][n] = cvt_tf32(v.y);
                    Bs[c + 2][n] = cvt_tf32(v.z); Bs[c + 3][n] = cvt_tf32(v.w);
                }
            } else {
#pragma unroll
                for (int kq = 0; kq < 2; kq++) {
                    int n = tid >> 2, c = (tid & 3) * 4 + kq * 16;
                    float4 v = *(const float4*)(Bm + (long)(n0 + n) * ldb + k0 + c);
                    Bs[c + 0][n] = cvt_tf32(v.x); Bs[c + 1][n] = cvt_tf32(v.y);
                    Bs[c + 2][n] = cvt_tf32(v.z); Bs[c + 3][n] = cvt_tf32(v.w);
                }
            }
        } else {
            if (BN == 128) {
#pragma unroll
                for (int kq = 0; kq < 4; kq++) {
                    int kr = (tid >> 5) + kq * 8, c = lane * 4;
                    float4 v = *(const float4*)(Bm + (long)(k0 + kr) * ldb + n0 + c);
                    uint4 u;
                    u.x = cvt_tf32(v.x); u.y = cvt_tf32(v.y);
                    u.z = cvt_tf32(v.z); u.w = cvt_tf32(v.w);
                    *(uint4*)&Bs[kr][c] = u;
                }
            } else {
#pragma unroll
                for (int kq = 0; kq < 2; kq++) {
                    int kr = (tid >> 4) + kq * 16, c = (tid & 15) * 4;
                    float4 v = *(const float4*)(Bm + (long)(k0 + kr) * ldb + n0 + c);
                    uint4 u;
                    u.x = cvt_tf32(v.x); u.y = cvt_tf32(v.y);
                    u.z = cvt_tf32(v.z); u.w = cvt_tf32(v.w);
                    *(uint4*)&Bs[kr][c] = u;
                }
            }
        }
        __syncthreads();
#pragma unroll
        for (int k8 = 0; k8 < 4; k8++) {
            int kb = k8 * 8;
            uint32_t a[2][4];
#pragma unroll
            for (int tm = 0; tm < 2; tm++) {
                int mr = wm * 32 + tm * 16;
                a[tm][0] = As[kb + tg][mr + g];
                a[tm][1] = As[kb + tg][mr + 8 + g];
                a[tm][2] = As[kb + tg + 4][mr + g];
                a[tm][3] = As[kb + tg + 4][mr + 8 + g];
            }
#pragma unroll
            for (int tn = 0; tn < TN; tn++) {
                int nc = wn * (TN * 8) + tn * 8 + g;
                uint32_t b0 = Bs[kb + tg][nc];
                uint32_t b1 = Bs[kb + tg + 4][nc];
#pragma unroll
                for (int tm = 0; tm < 2; tm++)
                    mma_tf32(acc[tm][tn], a[tm], b0, b1);
            }
        }
        __syncthreads();
    }

    float gg = 1.f;
    if (mode == 1 || mode == 3) gg = 1.f / (1.f + expf(-gptr[0]));
#pragma unroll
    for (int tm = 0; tm < 2; tm++) {
        long row0 = m0 + wm * 32 + tm * 16 + g;
#pragma unroll
        for (int tn = 0; tn < TN; tn++) {
            long col = n0 + wn * (TN * 8) + tn * 8 + tg * 2;
#pragma unroll
            for (int half = 0; half < 2; half++) {
                long r = row0 + half * 8;
                float vx = alpha * acc[tm][tn][half * 2 + 0];
                float vy = alpha * acc[tm][tn][half * 2 + 1];
                if (mode == 1) {
                    float2 ad = *(const float2*)(Add + r * ldadd + col);
                    vx = gg * vx + (1.f - gg) * ad.x;
                    vy = gg * vy + (1.f - gg) * ad.y;
                } else if (mode == 2) {
                    float2 ad = *(const float2*)(Add + r * ldadd + col);
                    vx += ad.x; vy += ad.y;
                } else if (mode == 3) {
                    float2 ad = *(const float2*)(Add + r * ldadd + col);
                    float2 a2 = *(const float2*)(Add2 + r * ldadd + col);
                    vx = 0.5f * (gg * vx + (1.f - gg) * ad.x) + 0.5f * a2.x;
                    vy = 0.5f * (gg * vy + (1.f - gg) * ad.y) + 0.5f * a2.y;
                    vx = vx > 0.f ? vx : 0.f;
                    vy = vy > 0.f ? vy : 0.f;
                }
                float2 o; o.x = vx; o.y = vy;
                *(float2*)(C + r * ldc + col) = o;
            }
        }
    }
}

// ------------------------- weight packing -------------------------
__global__ void pack_hgt_w_k(const float* __restrict__ Wk, const float* __restrict__ Wq,
                             const float* __restrict__ Wv, float* __restrict__ pW) {
    long i = (long)blockIdx.x * blockDim.x + threadIdx.x;
    if (i >= 8L * 256 * 768) return;
    int n = (int)(i % 768);
    long rem = i / 768;
    int k = (int)(rem % 256);
    int c = (int)(rem / 256);
    int sel = n >> 8, nn = n & 255;
    const float* W = (sel == 0) ? Wk : (sel == 1) ? Wq : Wv;
    pW[(long)c * 196608 + (long)k * 768 + n] = W[(long)c * 65536 + (long)k * 256 + nn];
}
__global__ void pack_trans_w_k(const float* __restrict__ Wq, const float* __restrict__ Wk,
                               const float* __restrict__ Wv, float* __restrict__ pTw) {
    int i = blockIdx.x * blockDim.x + threadIdx.x;
    if (i >= 256 * 768) return;
    int n = i % 768, k = i / 768;
    int sel = n >> 8, nn = n & 255;
    const float* W = (sel == 0) ? Wq : (sel == 1) ? Wk : Wv;
    pTw[(long)k * 768 + n] = W[(long)k * 256 + nn];
}

// ------------------------- elementwise -------------------------
__global__ void assemble_x_k(const float* __restrict__ xi, const float* __restrict__ xd,
                             float* __restrict__ x) {
    long i = ((long)blockIdx.x * blockDim.x + threadIdx.x) * 4;
    if (i < LXD) {
        const long T1 = (long)kNI * kD;
        float4 v = (i < T1) ? *(const float4*)(xi + i) : *(const float4*)(xd + (i - T1));
        *(float4*)(x + i) = v;
    }
}

// ------------------------- fused CSR construction -------------------------
struct Slot { int idx; int ent; int arr; };
__device__ __forceinline__ Slot decode_slot(
    int i, const int* rc, const int* cc, const int* ri, const int* ci,
    const int* ro, const int* co, const int* rk, const int* ck)
{
    Slot s;
    if (i < BB0)       { s.idx = O0 + cc[i];            s.ent = (0 << 16) | rc[i];            s.arr = 0; }
    else if (i < BB1)  { int j = i - BB0;  s.idx = O0 + ci[j]; s.ent = (1 << 16) | ri[j];     s.arr = 0; }
    else if (i < BB2)  { int j = i - BB1;  s.idx = O0 + ck[j]; s.ent = (3 << 16) | rk[j];     s.arr = 0; }
    else if (i < BB3)  { int j = i - BB2;  s.idx = O1 + co[j]; s.ent = (2 << 16) | ro[j];     s.arr = 1; }
    else if (i < BB4)  { int j = i - BB3;  s.idx = O2 + rc[j]; s.ent = (0 << 16) | cc[j];     s.arr = 2; }
    else if (i < BB5)  { int j = i - BB4;  s.idx = O2 + ro[j]; s.ent = (2 << 16) | co[j];     s.arr = 2; }
    else if (i < BB6)  { int j = i - BB5;  s.idx = O2 + rk[j]; s.ent = (3 << 16) | ck[j];     s.arr = 2; }
    else if (i < BB7)  { int j = i - BB6;  s.idx = O3 + ri[j]; s.ent = (1 << 16) | ci[j];     s.arr = 3; }
    else if (i < BB8)  { int j = i - BB7;  s.idx = O4 + cc[j]; s.ent = rc[j];                 s.arr = 4; }
    else if (i < BB9)  { int j = i - BB8;  s.idx = O4 + ci[j]; s.ent = ri[j] + kNI;           s.arr = 4; }
    else if (i < BB10) { int j = i - BB9;  s.idx = O4 + co[j] + kNI; s.ent = ro[j];           s.arr = 4; }
    else               { int j = i - BB10; s.idx = O4 + ck[j]; s.ent = rk[j];                 s.arr = 4; }
    return s;
}

__global__ void csr_count_k(Scratch* sp, const int* rc, const int* cc,
                            const int* ri, const int* ci, const int* ro, const int* co,
                            const int* rk, const int* ck) {
    int i = blockIdx.x * blockDim.x + threadIdx.x;
    if (i < BB11) {
        Slot s = decode_slot(i, rc, cc, ri, ci, ro, co, rk, ck);
        atomicAdd(&sp->cnt[s.idx], 1);
    }
}
// scan consumes cnt AND re-zeroes it (so next kernel_launch starts clean; device
// globals are zero-initialized at module load so the first call is also clean).
__global__ void csr_scan_k(Scratch* sp) {
    __shared__ int sh[1024];
    int region = blockIdx.x, t = threadIdx.x;
    int off, n, extra = 0;
    int* rp;
    switch (region) {
        case 0: off = O0; n = kNI; rp = sp->rpf0; break;
        case 1: off = O1; n = kND; rp = sp->rpf1; break;
        case 2: off = O2; n = kNI; rp = sp->rpr0; break;
        case 3: off = O3; n = kND; rp = sp->rpr1; break;
        default: off = O4; n = kNT; rp = sp->rph; extra = 1; break;
    }
    int c = (n + 1023) >> 10;
    int beg = t * c, end = min(beg + c, n);
    int s = 0;
    for (int i = beg; i < end; i++) s += sp->cnt[off + i] + extra;
    sh[t] = s;
    __syncthreads();
    for (int o = 1; o < 1024; o <<= 1) {
        int v = (t >= o) ? sh[t - o] : 0;
        __syncthreads();
        sh[t] += v;
        __syncthreads();
    }
    int run = t ? sh[t - 1] : 0;
    for (int i = beg; i < end; i++) {
        int cv = sp->cnt[off + i];
        sp->cnt[off + i] = 0;
        rp[i] = run;
        sp->cur[off + i] = run;
        run += cv + extra;
    }
    if (t == 1023) rp[n] = sh[1023];
}
__global__ void csr_fill_k(Scratch* sp, const int* rc, const int* cc,
                           const int* ri, const int* ci, const int* ro, const int* co,
                           const int* rk, const int* ck) {
    int i = blockIdx.x * blockDim.x + threadIdx.x;
    if (i >= BB12) return;
    if (i < BB11) {
        Slot s = decode_slot(i, rc, cc, ri, ci, ro, co, rk, ck);
        int pos = atomicAdd(&sp->cur[s.idx], 1);
        switch (s.arr) {
            case 0: sp->ef0[pos] = s.ent; break;
            case 1: sp->ef1[pos] = s.ent; break;
            case 2: sp->er0[pos] = s.ent; break;
            case 3: sp->er1[pos] = s.ent; break;
            default: sp->eh[pos] = s.ent; break;
        }
    } else {
        int node = i - BB11;
        int pos = atomicAdd(&sp->cur[O4 + node], 1);
        sp->eh[pos] = node;
    }
}

// ------------------------- HGT softmax aggregation (gelu fused) -------------------------
__global__ void hgt_agg_k(const float* __restrict__ Q, int qs,
                          const float* __restrict__ Krel, const float* __restrict__ Vrel,
                          const int* __restrict__ rp, const int* __restrict__ ent,
                          const float* __restrict__ prel,
                          float* __restrict__ agg, int dstBase)
{
    int node = blockIdx.x;
    int h = threadIdx.x >> 5, lane = threadIdx.x & 31;
    const float* q = Q + (long)(dstBase + node) * qs + h * kDH;
    float q0 = q[lane], q1 = q[lane + 32];
    float pr0 = prel[0 * kH + h], pr1 = prel[1 * kH + h];
    float pr2 = prel[2 * kH + h], pr3 = prel[3 * kH + h];
    int s = rp[node], e1 = rp[node + 1];
    float m = -INFINITY, den = 0.f, a0 = 0.f, a1 = 0.f;
    for (int e = s; e < e1; e++) {
        int pk = ent[e];
        int r = pk >> 16, src = pk & 0xffff;
        const float* kr = Krel + ((long)r * kNI + src) * kD + h * kDH;
        float d0 = q0 * kr[lane] + q1 * kr[lane + 32];
        d0 = wsum(d0);
        float pr = (r == 0) ? pr0 : (r == 1) ? pr1 : (r == 2) ? pr2 : pr3;
        float sc2 = d0 * pr * 0.125f;
        float mn = fmaxf(m, sc2);
        float cc = expf(m - mn), w = expf(sc2 - mn);
        const float* vr = Vrel + ((long)r * kNI + src) * kD + h * kDH;
        den = den * cc + w;
        a0 = a0 * cc + w * vr[lane];
        a1 = a1 * cc + w * vr[lane + 32];
        m = mn;
    }
    float inv = 1.f / (den + 1e-16f);
    float r0 = a0 * inv, r1 = a1 * inv;
    float* o = agg + (long)(dstBase + node) * kD + h * kDH;
    o[lane]      = 0.5f * r0 * (1.f + erff(r0 * 0.7071067811865475f));
    o[lane + 32] = 0.5f * r1 * (1.f + erff(r1 * 0.7071067811865475f));
}

// ------------------------- pooling -------------------------
__global__ void hv_k(const float* __restrict__ x, const float* __restrict__ pw,
                     float* __restrict__ hv) {
    int node = blockIdx.x * 8 + (threadIdx.x >> 5);
    int lane = threadIdx.x & 31;
    if (node >= kNT) return;
    float s = 0.f;
    for (int d = lane; d < kD; d += 32) s += x[(long)node * kD + d] * pw[d];
    s = wsum(s);
    if (!lane) hv[node] = s;
}
__global__ void gat_score_k(const float* __restrict__ hv, const int* __restrict__ rp,
                            const int* __restrict__ ent, const float* __restrict__ att,
                            const float* __restrict__ bias, float* __restrict__ sc) {
    int i = blockIdx.x * blockDim.x + threadIdx.x;
    if (i >= kNT) return;
    float A0 = att[0], A1 = att[1];
    float hi = hv[i];
    int s = rp[i], e1 = rp[i + 1];
    float m = -INFINITY, den = 0.f, acc = 0.f;
    for (int e = s; e < e1; e++) {
        int src = ent[e] & 0xffff;
        float hs = hv[src];
        float ee = A0 * hs + A1 * hi;
        ee = ee >= 0.f ? ee : 0.2f * ee;
        float mn = fmaxf(m, ee);
        float c = expf(m - mn), w = expf(ee - mn);
        den = den * c + w;
        acc = acc * c + w * hs;
        m = mn;
    }
    sc[i] = acc / (den + 1e-16f) + bias[0];
}

__global__ void topk_sort_k(const float* __restrict__ sc, float* __restrict__ sv,
                            int* __restrict__ si) {
    int b = blockIdx.x, t = threadIdx.x;
    __shared__ float v[2048];
    __shared__ int ix[2048];
    for (int p = t; p < 2048; p += 1024) {
        float val = -INFINITY;
        if (p < 1536) {
            int node = p < 1024 ? b * 1024 + p : kNI + b * 512 + (p - 1024);
            val = sc[node];
        }
        v[p] = val;
        ix[p] = p;
    }
    __syncthreads();
    for (int k = 2; k <= 2048; k <<= 1)
        for (int j = k >> 1; j > 0; j >>= 1) {
#pragma unroll
            for (int pass = 0; pass < 2; pass++) {
                int i = t + pass * 1024;
                int l = i ^ j;
                if (l > i) {
                    bool up = ((i & k) == 0);
                    float vi = v[i], vl = v[l];
                    int ii = ix[i], il = ix[l];
                    bool before = (vi > vl) || (vi == vl && ii < il);
                    if (up != before) {
                        v[i] = vl; v[l] = vi;
                        ix[i] = il; ix[l] = ii;
                    }
                }
            }
            __syncthreads();
        }
    if (t < kKP) {
        sv[b * kKP + t] = v[t];
        si[b * kKP + t] = ix[t];
    }
}
__global__ void gather_k(const float* __restrict__ x, const float* __restrict__ sv,
                         const int* __restrict__ si, float* __restrict__ xp) {
    int q = blockIdx.x, b = blockIdx.y, d = threadIdx.x;
    int j = si[b * kKP + q];
    float tv = tanhf(sv[b * kKP + q]);
    int node = j < 1024 ? b * 1024 + j : kNI + b * 512 + (j - 1024);
    xp[((long)(b * kKP + q)) * kD + d] = x[(long)node * kD + d] * tv;
}

// ------------------------- transformer pieces -------------------------
// single pass: 3 elems per thread held in registers
__global__ void softmax_k(float* __restrict__ S) {
    long row = blockIdx.x;
    float* p = S + row * kKP;
    int t = threadIdx.x;
    float v0 = p[t], v1 = p[t + 256], v2 = p[t + 512];
    float m = bmax(fmaxf(v0, fmaxf(v1, v2)));
    v0 = expf(v0 - m); v1 = expf(v1 - m); v2 = expf(v2 - m);
    float s = bsum(v0 + v1 + v2);
    float inv = 1.f / s;
    p[t] = v0 * inv; p[t + 256] = v1 * inv; p[t + 512] = v2 * inv;
}
__global__ void ln_k(const float* __restrict__ y, const float* __restrict__ g,
                     const float* __restrict__ bta, float* __restrict__ out) {
    long row = blockIdx.x;
    int d = threadIdx.x;
    float v = y[row * kD + d];
    float mu = bsum(v) * (1.f / kD);
    float df = v - mu;
    float var = bsum(df * df) * (1.f / kD);
    out[row * kD + d] = g[d] * df * rsqrtf(var + 1e-5f) + bta[d];
}
__global__ void featsum_k(const float* __restrict__ xp, const float* __restrict__ ga,
                          float* __restrict__ u) {
    int b = blockIdx.x, d = threadIdx.x;
    float s1 = 0.f, s2 = 0.f;
    for (int q = 0; q < kKP; q++) {
        long o = ((long)(b * kKP + q)) * kD + d;
        s1 += xp[o];
        s2 += ga[o];
    }
    u[b * 512 + d] = s1;
    u[b * 512 + 256 + d] = s2;
}
__global__ void cos_k(const float* __restrict__ u, float* __restrict__ out) {
    int b = blockIdx.x, t = threadIdx.x;
    float a = u[b * 512 + t];
    float c = u[(kB + b) * 512 + t];
    float dot = bsum(a * c);
    float na = bsum(a * a);
    float nc = bsum(c * c);
    if (t == 0)
        out[b] = dot / (fmaxf(sqrtf(na), 1e-8f) * fmaxf(sqrtf(nc), 1e-8f));
}

// ------------------------- host orchestration -------------------------
static inline void gemm(bool tb, const float* A, int lda, long Ab, long Ah,
                        const float* Bm, int ldb, long Bb, long Bh,
                        float* C, int ldc, long Cb, long Ch,
                        const float* Add, int ldadd, const float* Add2,
                        const float* gptr,
                        int M, int N, int K, int ZB, int ZH, float alpha, int mode) {
    if (N % 128 == 0) {
        dim3 g(M / 128, N / 128, ZB * ZH), blk(256);
        if (tb)
            tgemm_k<128, true><<<g, blk>>>(A, lda, Ab, Ah, Bm, ldb, Bb, Bh, C, ldc, Cb, Ch,
                                           Add, ldadd, Add2, gptr, K, ZH, alpha, mode);
        else
            tgemm_k<128, false><<<g, blk>>>(A, lda, Ab, Ah, Bm, ldb, Bb, Bh, C, ldc, Cb, Ch,
                                            Add, ldadd, Add2, gptr, K, ZH, alpha, mode);
    } else {
        dim3 g(M / 128, N / 64, ZB * ZH), blk(256);
        if (tb)
            tgemm_k<64, true><<<g, blk>>>(A, lda, Ab, Ah, Bm, ldb, Bb, Bh, C, ldc, Cb, Ch,
                                          Add, ldadd, Add2, gptr, K, ZH, alpha, mode);
        else
            tgemm_k<64, false><<<g, blk>>>(A, lda, Ab, Ah, Bm, ldb, Bb, Bh, C, ldc, Cb, Ch,
                                           Add, ldadd, Add2, gptr, K, ZH, alpha, mode);
    }
}

static void run_branch(Scratch* sp, const float* xi, const float* xd,
                       const int* ec, const int* ei, const int* eo, const int* ek,
                       const float* Wo, const float* arel, const float* mrel,
                       const float* prel, const float* skip, const float* poolW,
                       const float* poolAtt, const float* poolBias,
                       const float* tWo, const float* lng, const float* lnb, int branch)
{
    const long DD = (long)kD * kD;
    const long T1 = (long)kNI * kD;

    const int *rc = ec, *cc = ec + kEC;
    const int *ri = ei, *ci = ei + kEI;
    const int *ro = eo, *co = eo + kEO;
    const int *rk = ek, *ck = ek + kEK;

    assemble_x_k<<<(int)(LXD / 4 + 255) / 256, 256>>>(xi, xd, sp->x);

    static const int fwdsrc[4] = {0, 1, 0, 0};
    static const int revsrc[4] = {0, 0, 1, 0};
    bool csr_done = false;

    for (int l = 0; l < 2; l++) {
        for (int dir = 0; dir < 2; dir++) {
            int combo0 = (l * 2 + dir) * 2;
            // fused K|Q|V GEMM per node type: C = kqv (ldc 768)
            for (int t = 0; t < 2; t++) {
                const float* xb = sp->x + (t ? T1 : 0);
                int M = t ? kND : kNI;
                long rowOff = (t ? T1 : 0) * 3;
                gemm(false, xb, kD, 0, 0, sp->pW + (long)(combo0 + t) * 196608, 768, 0, 0,
                     sp->kqv + rowOff, 768, 0, 0, nullptr, 0, nullptr, nullptr,
                     M, 768, kD, 1, 1, 1.f, 0);
            }
            if (!csr_done) {   // CSR build overlapped after the first big GEMMs
                csr_count_k<<<(BB11 + 255) / 256, 256>>>(sp, rc, cc, ri, ci, ro, co, rk, ck);
                csr_scan_k<<<5, 1024>>>(sp);
                csr_fill_k<<<(BB12 + 255) / 256, 256>>>(sp, rc, cc, ri, ci, ro, co, rk, ck);
                csr_done = true;
            }
            // Krel / Vrel per relation (z over heads)
            for (int r = 0; r < 4; r++) {
                int st = dir ? revsrc[r] : fwdsrc[r];
                int M = st ? kND : kNI;
                long rowOff = (st ? T1 : 0) * 3;
                long relOff = (long)(((l * 2 + dir) * 4 + r) * kH) * kDH * kDH;
                gemm(false, sp->kqv + rowOff, 768, 0, 64, arel + relOff, kDH, 0, (long)kDH * kDH,
                     sp->Krel + (long)r * kNI * kD, kD, 0, 64, nullptr, 0, nullptr, nullptr,
                     M, kDH, kDH, 1, kH, 1.f, 0);
                gemm(false, sp->kqv + rowOff + 512, 768, 0, 64, mrel + relOff, kDH, 0, (long)kDH * kDH,
                     sp->Vrel + (long)r * kNI * kD, kD, 0, 64, nullptr, 0, nullptr, nullptr,
                     M, kDH, kDH, 1, kH, 1.f, 0);
            }
            const float* prelp = prel + (long)((l * 2 + dir) * 4) * kH;
            const float* Qbase = sp->kqv + 256;
            if (dir == 0) {
                hgt_agg_k<<<kNI, 128>>>(Qbase, 768, sp->Krel, sp->Vrel, sp->rpf0, sp->ef0,
                                        prelp, sp->agg, 0);
                hgt_agg_k<<<kND, 128>>>(Qbase, 768, sp->Krel, sp->Vrel, sp->rpf1, sp->ef1,
                                        prelp, sp->agg, kNI);
            } else {
                hgt_agg_k<<<kNI, 128>>>(Qbase, 768, sp->Krel, sp->Vrel, sp->rpr0, sp->er0,
                                        prelp, sp->agg, 0);
                hgt_agg_k<<<kND, 128>>>(Qbase, 768, sp->Krel, sp->Vrel, sp->rpr1, sp->er1,
                                        prelp, sp->agg, kNI);
            }
            // Wo: dir0 -> yF (mode 1); dir1 -> x in place (mode 3, fused 0.5 comb + relu)
            long wOff = (long)combo0 * DD;
            for (int t = 0; t < 2; t++) {
                int M = t ? kND : kNI;
                long tOff = t ? T1 : 0;
                const float* gp = skip + (l * 2 + dir) * 2 + t;
                if (dir == 0)
                    gemm(false, sp->agg + tOff, kD, 0, 0, Wo + wOff + t * DD, kD, 0, 0,
                         sp->yF + tOff, kD, 0, 0, sp->x + tOff, kD, nullptr, gp,
                         M, kD, kD, 1, 1, 1.f, 1);
                else
                    gemm(false, sp->agg + tOff, kD, 0, 0, Wo + wOff + t * DD, kD, 0, 0,
                         sp->x + tOff, kD, 0, 0, sp->x + tOff, kD, sp->yF + tOff, gp,
                         M, kD, kD, 1, 1, 1.f, 3);
            }
        }
    }

    // pooling
    hv_k<<<kNT / 8, 256>>>(sp->x, poolW, sp->hv);
    gat_score_k<<<(kNT + 255) / 256, 256>>>(sp->hv, sp->rph, sp->eh, poolAtt, poolBias, sp->sc);
    topk_sort_k<<<kB, 1024>>>(sp->sc, sp->sv, sp->si);
    gather_k<<<dim3(kKP, kB), kD>>>(sp->x, sp->sv, sp->si, sp->xp);

    // transformer attention (fused QKV projection)
    int Mp = kB * kKP;
    gemm(false, sp->xp, kD, 0, 0, sp->pTw, 768, 0, 0, sp->qkvp, 768, 0, 0,
         nullptr, 0, nullptr, nullptr, Mp, 768, kD, 1, 1, 1.f, 0);
    long pb = (long)kKP * kD;
    long pq = (long)kKP * 768;
    long sb = (long)kH * kKP * kKP;
    gemm(true, sp->qkvp, 768, pq, kDH, sp->qkvp + 256, 768, pq, kDH,
         sp->S, kKP, sb, (long)kKP * kKP, nullptr, 0, nullptr, nullptr,
         kKP, kKP, kDH, kB, kH, 0.125f, 0);
    softmax_k<<<kB * kH * kKP, 256>>>(sp->S);
    gemm(false, sp->S, kKP, sb, (long)kKP * kKP, sp->qkvp + 512, 768, pq, kDH,
         sp->oh, kD, pb, kDH, nullptr, 0, nullptr, nullptr,
         kKP, kDH, kKP, kB, kH, 1.f, 0);
    gemm(false, sp->oh, kD, 0, 0, tWo, kD, 0, 0, sp->yb, kD, 0, 0,
         sp->xp, kD, nullptr, nullptr, Mp, kD, kD, 1, 1, 1.f, 2);
    ln_k<<<Mp, kD>>>(sp->yb, lng, lnb, sp->ga);
    featsum_k<<<kB, kD>>>(sp->xp, sp->ga, sp->u + (long)branch * kB * 512);
}

extern "C" void kernel_launch(void* const* d_in, const int* in_sizes, int n_in,
                              void* d_out, int out_size) {
    Scratch* sp = nullptr;
    cudaGetSymbolAddress((void**)&sp, SC);

    const float* Wk    = (const float*)d_in[12];
    const float* Wq    = (const float*)d_in[13];
    const float* Wv    = (const float*)d_in[14];
    const float* Wo    = (const float*)d_in[15];
    const float* arel  = (const float*)d_in[16];
    const float* mrel  = (const float*)d_in[17];
    const float* prel  = (const float*)d_in[18];
    const float* skip  = (const float*)d_in[19];
    const float* poolW = (const float*)d_in[20];
    const float* poolA = (const float*)d_in[21];
    const float* poolB = (const float*)d_in[22];
    const float* tWq   = (const float*)d_in[23];
    const float* tWk   = (const float*)d_in[24];
    const float* tWv   = (const float*)d_in[25];
    const float* tWo   = (const float*)d_in[26];
    const float* lng   = (const float*)d_in[27];
    const float* lnb   = (const float*)d_in[28];

    pack_hgt_w_k<<<(int)((8L * 256 * 768 + 255) / 256), 256>>>(Wk, Wq, Wv, sp->pW);
    pack_trans_w_k<<<(256 * 768 + 255) / 256, 256>>>(tWq, tWk, tWv, sp->pTw);

    for (int g = 0; g < 2; g++) {
        int base = g * 6;
        run_branch(sp,
                   (const float*)d_in[base + 0], (const float*)d_in[base + 1],
                   (const int*)d_in[base + 2], (const int*)d_in[base + 3],
                   (const int*)d_in[base + 4], (const int*)d_in[base + 5],
                   Wo, arel, mrel, prel, skip, poolW, poolA, poolB,
                   tWo, lng, lnb, g);
    }
    cos_k<<<kB, 512>>>(sp->u, (float*)d_out);
}

// round 10
// speedup vs baseline: 3.4223x; 1.3859x over previous
#include <cuda_runtime.h>
#include <math.h>
#include <stdint.h>

// ------------------------- problem constants -------------------------
constexpr int kNI = 8192, kND = 4096, kNT = 12288, kD = 256, kH = 4, kDH = 64;
constexpr int kB = 8, kKP = 768;
constexpr int kEC = 65536, kEI = 32768, kEO = 32768, kEK = 8192;
constexpr long LXD = (long)kNT * kD;
constexpr long LPD = (long)kB * kKP * kD;

// counter-region offsets (5 CSRs share one cnt/cur buffer)
constexpr int O0 = 0;
constexpr int O1 = kNI;
constexpr int O2 = kNI + kND;
constexpr int O3 = 2 * kNI + kND;
constexpr int O4 = 2 * kNI + 2 * kND;
constexpr int CNT_TOT = O4 + kNT;

// fused edge-slot boundaries
constexpr int BB0 = kEC;
constexpr int BB1 = BB0 + kEI;
constexpr int BB2 = BB1 + kEK;
constexpr int BB3 = BB2 + kEO;
constexpr int BB4 = BB3 + kEC;
constexpr int BB5 = BB4 + kEO;
constexpr int BB6 = BB5 + kEK;
constexpr int BB7 = BB6 + kEI;
constexpr int BB8 = BB7 + kEC;
constexpr int BB9 = BB8 + kEI;
constexpr int BB10 = BB9 + kEO;
constexpr int BB11 = BB10 + kEK;
constexpr int BB12 = BB11 + kNT;

// ------------------------- scratch -------------------------
struct Scratch {
    float x[LXD], yF[LXD], agg[LXD];
    float kqv[3 * LXD];                       // [node][768] packed K|Q|V
    float Krel[4L * kNI * kD], Vrel[4L * kNI * kD];
    float S[(long)kB * kH * kKP * kKP];
    float xp[LPD], qkvp[3 * LPD], oh[LPD], yb[LPD], ga[LPD];
    float pW[8L * 256 * 768];
    float pTw[256 * 768];
    float hv[kNT], sc[kNT];
    float sv[kB * kKP];
    int   si[kB * kKP];
    float u[2 * kB * 512];
    int rpf0[kNI + 1], rpf1[kND + 1], rpr0[kNI + 1], rpr1[kND + 1], rph[kNT + 1];
    int ef0[kEC + kEI + kEK], ef1[kEO], er0[kEC + kEO + kEK], er1[kEI];
    int eh[kEC + kEI + kEO + kEK + kNT];
    int cnt[CNT_TOT], cur[CNT_TOT];
};
__device__ Scratch SC;

// ------------------------- reductions -------------------------
__device__ __forceinline__ float wsum(float v) {
#pragma unroll
    for (int o = 16; o; o >>= 1) v += __shfl_xor_sync(0xffffffffu, v, o);
    return v;
}
__device__ __forceinline__ float bsum(float v) {
    __shared__ float sh[32];
    int lane = threadIdx.x & 31, w = threadIdx.x >> 5;
    v = wsum(v);
    if (!lane) sh[w] = v;
    __syncthreads();
    int nw = blockDim.x >> 5;
    float s = (threadIdx.x < nw) ? sh[threadIdx.x] : 0.f;
    if (w == 0) s = wsum(s);
    if (threadIdx.x == 0) sh[0] = s;
    __syncthreads();
    float r = sh[0];
    __syncthreads();
    return r;
}
__device__ __forceinline__ float bmax(float v) {
    __shared__ float sh[32];
    int lane = threadIdx.x & 31, w = threadIdx.x >> 5;
#pragma unroll
    for (int o = 16; o; o >>= 1) v = fmaxf(v, __shfl_xor_sync(0xffffffffu, v, o));
    if (!lane) sh[w] = v;
    __syncthreads();
    int nw = blockDim.x >> 5;
    float s = (threadIdx.x < nw) ? sh[threadIdx.x] : -INFINITY;
    if (w == 0)
#pragma unroll
        for (int o = 16; o; o >>= 1) s = fmaxf(s, __shfl_xor_sync(0xffffffffu, s, o));
    if (threadIdx.x == 0) sh[0] = s;
    __syncthreads();
    float r = sh[0];
    __syncthreads();
    return r;
}

// ------------------------- tf32 tensor-core GEMM (cp.async pipelined) --------
__device__ __forceinline__ void mma_tf32(float* c, const uint32_t* a,
                                         uint32_t b0, uint32_t b1) {
    asm volatile(
        "mma.sync.aligned.m16n8k8.row.col.f32.tf32.tf32.f32 "
        "{%0,%1,%2,%3}, {%4,%5,%6,%7}, {%8,%9}, {%0,%1,%2,%3};"
        : "+f"(c[0]), "+f"(c[1]), "+f"(c[2]), "+f"(c[3])
        : "r"(a[0]), "r"(a[1]), "r"(a[2]), "r"(a[3]), "r"(b0), "r"(b1));
}
__device__ __forceinline__ void cpa16(float* dst, const float* src) {
    unsigned d = (unsigned)__cvta_generic_to_shared(dst);
    asm volatile("cp.async.cg.shared.global [%0], [%1], 16;\n" :: "r"(d), "l"(src));
}
#define CP_COMMIT() asm volatile("cp.async.commit_group;\n" ::: "memory")
#define CP_WAIT1()  asm volatile("cp.async.wait_group 1;\n" ::: "memory")
#define CP_WAIT0()  asm volatile("cp.async.wait_group 0;\n" ::: "memory")

// C = epilogue(alpha * A @ B(^T)); z -> (zb = z/ZH, zh = z%ZH).
// Per-z masking: if bit zb of zmask set, A += Aalt and M = Malt (blocks beyond exit).
// mode 0: C = v
// mode 1: C = g*v + (1-g)*Add              (g = sigmoid(*gptr))
// mode 2: C = v + Add
// mode 3: C = relu(0.5*(g*v + (1-g)*Add) + 0.5*Add2)
template <int BN, bool TB>
__global__ void __launch_bounds__(256, 2) tgemm_k(
    const float* __restrict__ A, int lda, long Ab, long Ah,
    const float* __restrict__ Bm, int ldb, long Bb, long Bh,
    float* __restrict__ C, int ldc, long Cb, long Ch,
    const float* __restrict__ Add, int ldadd, const float* __restrict__ Add2,
    const float* __restrict__ gptr,
    int Kdim, int ZH, float alpha, int mode,
    unsigned zmask, long Aalt, int Malt, int Mdef)
{
    constexpr int BM = 128, BK = 32;
    constexpr int ASTR = 44;                      // conflict-free + 16B aligned
    constexpr int BROWS = TB ? BN : BK;
    constexpr int BSTR = TB ? 44 : (BN + 8);      // NN: 136 / 72
    constexpr int TN = (BN == 128) ? 8 : 4;
    extern __shared__ float sm_[];
    float* As = sm_;                              // [2][BM][ASTR]
    float* Bs = sm_ + 2 * BM * ASTR;              // [2][BROWS][BSTR]

    int z = blockIdx.z, zb = z / ZH, zh = z - zb * ZH;
    int msk = (zmask >> zb) & 1;
    int Mz = msk ? Malt : Mdef;
    int m0 = blockIdx.x * BM;
    if (m0 >= Mz) return;
    const float* Ax = A + zb * Ab + zh * Ah + (msk ? Aalt : 0);
    const float* Bx = Bm + zb * Bb + zh * Bh;
    C += zb * Cb + zh * Ch;
    int n0 = blockIdx.y * BN;
    int tid = threadIdx.x, lane = tid & 31, warp = tid >> 5;
    int wm = warp >> 1, wn = warp & 1;
    int g = lane >> 2, tg = lane & 3;

    float acc[2][TN][4];
#pragma unroll
    for (int i = 0; i < 2; i++)
#pragma unroll
        for (int j = 0; j < TN; j++)
#pragma unroll
            for (int q = 0; q < 4; q++) acc[i][j][q] = 0.f;

    int nt = Kdim / BK;

    // ---- stage-issue helper (inlined twice) ----
#define ISSUE(K0, S) do {                                                      \
        float* Ad = As + (S) * BM * ASTR;                                      \
        _Pragma("unroll")                                                      \
        for (int q = 0; q < 4; q++) {                                          \
            int f = tid + q * 256, row = f >> 3, kc = (f & 7) * 4;             \
            cpa16(Ad + row * ASTR + kc,                                        \
                  Ax + (long)(m0 + row) * lda + (K0) + kc);                    \
        }                                                                      \
        float* Bd = Bs + (S) * BROWS * BSTR;                                   \
        _Pragma("unroll")                                                      \
        for (int q = 0; q < BN / 32; q++) {                                    \
            int f = tid + q * 256;                                             \
            if (TB) {                                                          \
                int rr = f >> 3, rc = (f & 7) * 4;                             \
                cpa16(Bd + rr * BSTR + rc,                                     \
                      Bx + (long)(n0 + rr) * ldb + (K0) + rc);                 \
            } else {                                                           \
                int rr = f / (BN / 4), rc = (f % (BN / 4)) * 4;                \
                cpa16(Bd + rr * BSTR + rc,                                     \
                      Bx + (long)((K0) + rr) * ldb + n0 + rc);                 \
            }                                                                  \
        }                                                                      \
    } while (0)

    ISSUE(0, 0);
    CP_COMMIT();

    for (int t = 0; t < nt; t++) {
        if (t + 1 < nt) {
            ISSUE((t + 1) * BK, (t + 1) & 1);
            CP_COMMIT();
            CP_WAIT1();
        } else {
            CP_WAIT0();
        }
        __syncthreads();
        const float* Ap = As + (size_t)(t & 1) * BM * ASTR;
        const float* Bp = Bs + (size_t)(t & 1) * BROWS * BSTR;
#pragma unroll
        for (int k8 = 0; k8 < 4; k8++) {
            int kb = k8 * 8;
            uint32_t a[2][4];
#pragma unroll
            for (int tm = 0; tm < 2; tm++) {
                int mr = wm * 32 + tm * 16;
                a[tm][0] = __float_as_uint(Ap[(mr + g) * ASTR + kb + tg]);
                a[tm][1] = __float_as_uint(Ap[(mr + 8 + g) * ASTR + kb + tg]);
                a[tm][2] = __float_as_uint(Ap[(mr + g) * ASTR + kb + tg + 4]);
                a[tm][3] = __float_as_uint(Ap[(mr + 8 + g) * ASTR + kb + tg + 4]);
            }
#pragma unroll
            for (int tn = 0; tn < TN; tn++) {
                int nc = wn * (TN * 8) + tn * 8 + g;
                uint32_t b0, b1;
                if (TB) {
                    b0 = __float_as_uint(Bp[nc * BSTR + kb + tg]);
                    b1 = __float_as_uint(Bp[nc * BSTR + kb + tg + 4]);
                } else {
                    b0 = __float_as_uint(Bp[(kb + tg) * BSTR + nc]);
                    b1 = __float_as_uint(Bp[(kb + tg + 4) * BSTR + nc]);
                }
#pragma unroll
                for (int tm = 0; tm < 2; tm++)
                    mma_tf32(acc[tm][tn], a[tm], b0, b1);
            }
        }
        __syncthreads();
    }
#undef ISSUE

    float gg = 1.f;
    if (mode == 1 || mode == 3) gg = 1.f / (1.f + expf(-gptr[0]));
#pragma unroll
    for (int tm = 0; tm < 2; tm++) {
        long row0 = m0 + wm * 32 + tm * 16 + g;
#pragma unroll
        for (int tn = 0; tn < TN; tn++) {
            long col = n0 + wn * (TN * 8) + tn * 8 + tg * 2;
#pragma unroll
            for (int half = 0; half < 2; half++) {
                long r = row0 + half * 8;
                float vx = alpha * acc[tm][tn][half * 2 + 0];
                float vy = alpha * acc[tm][tn][half * 2 + 1];
                if (mode == 1) {
                    float2 ad = *(const float2*)(Add + r * ldadd + col);
                    vx = gg * vx + (1.f - gg) * ad.x;
                    vy = gg * vy + (1.f - gg) * ad.y;
                } else if (mode == 2) {
                    float2 ad = *(const float2*)(Add + r * ldadd + col);
                    vx += ad.x; vy += ad.y;
                } else if (mode == 3) {
                    float2 ad = *(const float2*)(Add + r * ldadd + col);
                    float2 a2 = *(const float2*)(Add2 + r * ldadd + col);
                    vx = 0.5f * (gg * vx + (1.f - gg) * ad.x) + 0.5f * a2.x;
                    vy = 0.5f * (gg * vy + (1.f - gg) * ad.y) + 0.5f * a2.y;
                    vx = vx > 0.f ? vx : 0.f;
                    vy = vy > 0.f ? vy : 0.f;
                }
                float2 o; o.x = vx; o.y = vy;
                *(float2*)(C + r * ldc + col) = o;
            }
        }
    }
}

// ------------------------- weight packing -------------------------
__global__ void pack_hgt_w_k(const float* __restrict__ Wk, const float* __restrict__ Wq,
                             const float* __restrict__ Wv, float* __restrict__ pW) {
    long i = (long)blockIdx.x * blockDim.x + threadIdx.x;
    if (i >= 8L * 256 * 768) return;
    int n = (int)(i % 768);
    long rem = i / 768;
    int k = (int)(rem % 256);
    int c = (int)(rem / 256);
    int sel = n >> 8, nn = n & 255;
    const float* W = (sel == 0) ? Wk : (sel == 1) ? Wq : Wv;
    pW[(long)c * 196608 + (long)k * 768 + n] = W[(long)c * 65536 + (long)k * 256 + nn];
}
__global__ void pack_trans_w_k(const float* __restrict__ Wq, const float* __restrict__ Wk,
                               const float* __restrict__ Wv, float* __restrict__ pTw) {
    int i = blockIdx.x * blockDim.x + threadIdx.x;
    if (i >= 256 * 768) return;
    int n = i % 768, k = i / 768;
    int sel = n >> 8, nn = n & 255;
    const float* W = (sel == 0) ? Wq : (sel == 1) ? Wk : Wv;
    pTw[(long)k * 768 + n] = W[(long)k * 256 + nn];
}

// ------------------------- elementwise -------------------------
__global__ void assemble_x_k(const float* __restrict__ xi, const float* __restrict__ xd,
                             float* __restrict__ x) {
    long i = ((long)blockIdx.x * blockDim.x + threadIdx.x) * 4;
    if (i < LXD) {
        const long T1 = (long)kNI * kD;
        float4 v = (i < T1) ? *(const float4*)(xi + i) : *(const float4*)(xd + (i - T1));
        *(float4*)(x + i) = v;
    }
}

// ------------------------- fused CSR construction -------------------------
struct Slot { int idx; int ent; int arr; };
__device__ __forceinline__ Slot decode_slot(
    int i, const int* rc, const int* cc, const int* ri, const int* ci,
    const int* ro, const int* co, const int* rk, const int* ck)
{
    Slot s;
    if (i < BB0)       { s.idx = O0 + cc[i];            s.ent = (0 << 16) | rc[i];            s.arr = 0; }
    else if (i < BB1)  { int j = i - BB0;  s.idx = O0 + ci[j]; s.ent = (1 << 16) | ri[j];     s.arr = 0; }
    else if (i < BB2)  { int j = i - BB1;  s.idx = O0 + ck[j]; s.ent = (3 << 16) | rk[j];     s.arr = 0; }
    else if (i < BB3)  { int j = i - BB2;  s.idx = O1 + co[j]; s.ent = (2 << 16) | ro[j];     s.arr = 1; }
    else if (i < BB4)  { int j = i - BB3;  s.idx = O2 + rc[j]; s.ent = (0 << 16) | cc[j];     s.arr = 2; }
    else if (i < BB5)  { int j = i - BB4;  s.idx = O2 + ro[j]; s.ent = (2 << 16) | co[j];     s.arr = 2; }
    else if (i < BB6)  { int j = i - BB5;  s.idx = O2 + rk[j]; s.ent = (3 << 16) | ck[j];     s.arr = 2; }
    else if (i < BB7)  { int j = i - BB6;  s.idx = O3 + ri[j]; s.ent = (1 << 16) | ci[j];     s.arr = 3; }
    else if (i < BB8)  { int j = i - BB7;  s.idx = O4 + cc[j]; s.ent = rc[j];                 s.arr = 4; }
    else if (i < BB9)  { int j = i - BB8;  s.idx = O4 + ci[j]; s.ent = ri[j] + kNI;           s.arr = 4; }
    else if (i < BB10) { int j = i - BB9;  s.idx = O4 + co[j] + kNI; s.ent = ro[j];           s.arr = 4; }
    else               { int j = i - BB10; s.idx = O4 + ck[j]; s.ent = rk[j];                 s.arr = 4; }
    return s;
}

__global__ void csr_count_k(Scratch* sp, const int* rc, const int* cc,
                            const int* ri, const int* ci, const int* ro, const int* co,
                            const int* rk, const int* ck) {
    int i = blockIdx.x * blockDim.x + threadIdx.x;
    if (i < BB11) {
        Slot s = decode_slot(i, rc, cc, ri, ci, ro, co, rk, ck);
        atomicAdd(&sp->cnt[s.idx], 1);
    }
}
__global__ void csr_scan_k(Scratch* sp) {
    __shared__ int sh[1024];
    int region = blockIdx.x, t = threadIdx.x;
    int off, n, extra = 0;
    int* rp;
    switch (region) {
        case 0: off = O0; n = kNI; rp = sp->rpf0; break;
        case 1: off = O1; n = kND; rp = sp->rpf1; break;
        case 2: off = O2; n = kNI; rp = sp->rpr0; break;
        case 3: off = O3; n = kND; rp = sp->rpr1; break;
        default: off = O4; n = kNT; rp = sp->rph; extra = 1; break;
    }
    int c = (n + 1023) >> 10;
    int beg = t * c, end = min(beg + c, n);
    int s = 0;
    for (int i = beg; i < end; i++) s += sp->cnt[off + i] + extra;
    sh[t] = s;
    __syncthreads();
    for (int o = 1; o < 1024; o <<= 1) {
        int v = (t >= o) ? sh[t - o] : 0;
        __syncthreads();
        sh[t] += v;
        __syncthreads();
    }
    int run = t ? sh[t - 1] : 0;
    for (int i = beg; i < end; i++) {
        int cv = sp->cnt[off + i];
        sp->cnt[off + i] = 0;
        rp[i] = run;
        sp->cur[off + i] = run;
        run += cv + extra;
    }
    if (t == 1023) rp[n] = sh[1023];
}
__global__ void csr_fill_k(Scratch* sp, const int* rc, const int* cc,
                           const int* ri, const int* ci, const int* ro, const int* co,
                           const int* rk, const int* ck) {
    int i = blockIdx.x * blockDim.x + threadIdx.x;
    if (i >= BB12) return;
    if (i < BB11) {
        Slot s = decode_slot(i, rc, cc, ri, ci, ro, co, rk, ck);
        int pos = atomicAdd(&sp->cur[s.idx], 1);
        switch (s.arr) {
            case 0: sp->ef0[pos] = s.ent; break;
            case 1: sp->ef1[pos] = s.ent; break;
            case 2: sp->er0[pos] = s.ent; break;
            case 3: sp->er1[pos] = s.ent; break;
            default: sp->eh[pos] = s.ent; break;
        }
    } else {
        int node = i - BB11;
        int pos = atomicAdd(&sp->cur[O4 + node], 1);
        sp->eh[pos] = node;
    }
}

// ------------------------- HGT softmax aggregation (merged types, gelu fused) ----
__global__ void hgt_agg_k(const float* __restrict__ Q, int qs,
                          const float* __restrict__ Krel, const float* __restrict__ Vrel,
                          const int* __restrict__ rp0, const int* __restrict__ e0,
                          const int* __restrict__ rp1, const int* __restrict__ e1,
                          const float* __restrict__ prel, float* __restrict__ agg)
{
    int node = blockIdx.x;
    const int* rp; const int* ent; int idx;
    if (node < kNI) { rp = rp0; ent = e0; idx = node; }
    else            { rp = rp1; ent = e1; idx = node - kNI; }
    int h = threadIdx.x >> 5, lane = threadIdx.x & 31;
    const float* q = Q + (long)node * qs + h * kDH;
    float q0 = q[lane], q1 = q[lane + 32];
    float pr0 = prel[0 * kH + h], pr1 = prel[1 * kH + h];
    float pr2 = prel[2 * kH + h], pr3 = prel[3 * kH + h];
    int s = rp[idx], e1i = rp[idx + 1];
    float m = -INFINITY, den = 0.f, a0 = 0.f, a1 = 0.f;
    for (int e = s; e < e1i; e++) {
        int pk = ent[e];
        int r = pk >> 16, src = pk & 0xffff;
        const float* kr = Krel + ((long)r * kNI + src) * kD + h * kDH;
        float d0 = q0 * kr[lane] + q1 * kr[lane + 32];
        d0 = wsum(d0);
        float pr = (r == 0) ? pr0 : (r == 1) ? pr1 : (r == 2) ? pr2 : pr3;
        float sc2 = d0 * pr * 0.125f;
        float mn = fmaxf(m, sc2);
        float cc = expf(m - mn), w = expf(sc2 - mn);
        const float* vr = Vrel + ((long)r * kNI + src) * kD + h * kDH;
        den = den * cc + w;
        a0 = a0 * cc + w * vr[lane];
        a1 = a1 * cc + w * vr[lane + 32];
        m = mn;
    }
    float inv = 1.f / (den + 1e-16f);
    float r0 = a0 * inv, r1 = a1 * inv;
    float* o = agg + (long)node * kD + h * kDH;
    o[lane]      = 0.5f * r0 * (1.f + erff(r0 * 0.7071067811865475f));
    o[lane + 32] = 0.5f * r1 * (1.f + erff(r1 * 0.7071067811865475f));
}

// ------------------------- pooling -------------------------
__global__ void hv_k(const float* __restrict__ x, const float* __restrict__ pw,
                     float* __restrict__ hv) {
    int node = blockIdx.x * 8 + (threadIdx.x >> 5);
    int lane = threadIdx.x & 31;
    if (node >= kNT) return;
    float s = 0.f;
    for (int d = lane; d < kD; d += 32) s += x[(long)node * kD + d] * pw[d];
    s = wsum(s);
    if (!lane) hv[node] = s;
}
__global__ void gat_score_k(const float* __restrict__ hv, const int* __restrict__ rp,
                            const int* __restrict__ ent, const float* __restrict__ att,
                            const float* __restrict__ bias, float* __restrict__ sc) {
    int i = blockIdx.x * blockDim.x + threadIdx.x;
    if (i >= kNT) return;
    float A0 = att[0], A1 = att[1];
    float hi = hv[i];
    int s = rp[i], e1 = rp[i + 1];
    float m = -INFINITY, den = 0.f, acc = 0.f;
    for (int e = s; e < e1; e++) {
        int src = ent[e] & 0xffff;
        float hs = hv[src];
        float ee = A0 * hs + A1 * hi;
        ee = ee >= 0.f ? ee : 0.2f * ee;
        float mn = fmaxf(m, ee);
        float c = expf(m - mn), w = expf(ee - mn);
        den = den * c + w;
        acc = acc * c + w * hs;
        m = mn;
    }
    sc[i] = acc / (den + 1e-16f) + bias[0];
}

__global__ void topk_sort_k(const float* __restrict__ sc, float* __restrict__ sv,
                            int* __restrict__ si) {
    int b = blockIdx.x, t = threadIdx.x;
    __shared__ float v[2048];
    __shared__ int ix[2048];
    for (int p = t; p < 2048; p += 1024) {
        float val = -INFINITY;
        if (p < 1536) {
            int node = p < 1024 ? b * 1024 + p : kNI + b * 512 + (p - 1024);
            val = sc[node];
        }
        v[p] = val;
        ix[p] = p;
    }
    __syncthreads();
    for (int k = 2; k <= 2048; k <<= 1)
        for (int j = k >> 1; j > 0; j >>= 1) {
#pragma unroll
            for (int pass = 0; pass < 2; pass++) {
                int i = t + pass * 1024;
                int l = i ^ j;
                if (l > i) {
                    bool up = ((i & k) == 0);
                    float vi = v[i], vl = v[l];
                    int ii = ix[i], il = ix[l];
                    bool before = (vi > vl) || (vi == vl && ii < il);
                    if (up != before) {
                        v[i] = vl; v[l] = vi;
                        ix[i] = il; ix[l] = ii;
                    }
                }
            }
            __syncthreads();
        }
    if (t < kKP) {
        sv[b * kKP + t] = v[t];
        si[b * kKP + t] = ix[t];
    }
}
__global__ void gather_k(const float* __restrict__ x, const float* __restrict__ sv,
                         const int* __restrict__ si, float* __restrict__ xp) {
    int q = blockIdx.x, b = blockIdx.y, d = threadIdx.x;
    int j = si[b * kKP + q];
    float tv = tanhf(sv[b * kKP + q]);
    int node = j < 1024 ? b * 1024 + j : kNI + b * 512 + (j - 1024);
    xp[((long)(b * kKP + q)) * kD + d] = x[(long)node * kD + d] * tv;
}

// ------------------------- transformer pieces -------------------------
__global__ void softmax_k(float* __restrict__ S) {
    long row = blockIdx.x;
    float* p = S + row * kKP;
    int t = threadIdx.x;
    float v0 = p[t], v1 = p[t + 256], v2 = p[t + 512];
    float m = bmax(fmaxf(v0, fmaxf(v1, v2)));
    v0 = expf(v0 - m); v1 = expf(v1 - m); v2 = expf(v2 - m);
    float s = bsum(v0 + v1 + v2);
    float inv = 1.f / s;
    p[t] = v0 * inv; p[t + 256] = v1 * inv; p[t + 512] = v2 * inv;
}
__global__ void ln_k(const float* __restrict__ y, const float* __restrict__ g,
                     const float* __restrict__ bta, float* __restrict__ out) {
    long row = blockIdx.x;
    int d = threadIdx.x;
    float v = y[row * kD + d];
    float mu = bsum(v) * (1.f / kD);
    float df = v - mu;
    float var = bsum(df * df) * (1.f / kD);
    out[row * kD + d] = g[d] * df * rsqrtf(var + 1e-5f) + bta[d];
}
__global__ void featsum_k(const float* __restrict__ xp, const float* __restrict__ ga,
                          float* __restrict__ u) {
    int b = blockIdx.x, d = threadIdx.x;
    float s1 = 0.f, s2 = 0.f;
    for (int q = 0; q < kKP; q++) {
        long o = ((long)(b * kKP + q)) * kD + d;
        s1 += xp[o];
        s2 += ga[o];
    }
    u[b * 512 + d] = s1;
    u[b * 512 + 256 + d] = s2;
}
__global__ void cos_k(const float* __restrict__ u, float* __restrict__ out) {
    int b = blockIdx.x, t = threadIdx.x;
    float a = u[b * 512 + t];
    float c = u[(kB + b) * 512 + t];
    float dot = bsum(a * c);
    float na = bsum(a * a);
    float nc = bsum(c * c);
    if (t == 0)
        out[b] = dot / (fmaxf(sqrtf(na), 1e-8f) * fmaxf(sqrtf(nc), 1e-8f));
}

// ------------------------- host orchestration -------------------------
static inline int gemm_smem(bool tb, int BN) {
    int a = 2 * 128 * 44;
    int b = tb ? 2 * BN * 44 : 2 * 32 * (BN + 8);
    return (a + b) * 4;
}
static inline void gemm(bool tb, const float* A, int lda, long Ab, long Ah,
                        const float* Bm, int ldb, long Bb, long Bh,
                        float* C, int ldc, long Cb, long Ch,
                        const float* Add, int ldadd, const float* Add2,
                        const float* gptr,
                        int M, int N, int K, int ZB, int ZH, float alpha, int mode,
                        unsigned zmask = 0, long Aalt = 0, int Malt = 0) {
    if (N % 128 == 0) {
        int sm = gemm_smem(tb, 128);
        dim3 g(M / 128, N / 128, ZB * ZH), blk(256);
        if (tb) {
            cudaFuncSetAttribute(tgemm_k<128, true>,
                                 cudaFuncAttributeMaxDynamicSharedMemorySize, sm);
            tgemm_k<128, true><<<g, blk, sm>>>(A, lda, Ab, Ah, Bm, ldb, Bb, Bh, C, ldc, Cb, Ch,
                                               Add, ldadd, Add2, gptr, K, ZH, alpha, mode,
                                               zmask, Aalt, Malt, M);
        } else {
            cudaFuncSetAttribute(tgemm_k<128, false>,
                                 cudaFuncAttributeMaxDynamicSharedMemorySize, sm);
            tgemm_k<128, false><<<g, blk, sm>>>(A, lda, Ab, Ah, Bm, ldb, Bb, Bh, C, ldc, Cb, Ch,
                                                Add, ldadd, Add2, gptr, K, ZH, alpha, mode,
                                                zmask, Aalt, Malt, M);
        }
    } else {
        int sm = gemm_smem(tb, 64);
        dim3 g(M / 128, N / 64, ZB * ZH), blk(256);
        if (tb) {
            cudaFuncSetAttribute(tgemm_k<64, true>,
                                 cudaFuncAttributeMaxDynamicSharedMemorySize, sm);
            tgemm_k<64, true><<<g, blk, sm>>>(A, lda, Ab, Ah, Bm, ldb, Bb, Bh, C, ldc, Cb, Ch,
                                              Add, ldadd, Add2, gptr, K, ZH, alpha, mode,
                                              zmask, Aalt, Malt, M);
        } else {
            cudaFuncSetAttribute(tgemm_k<64, false>,
                                 cudaFuncAttributeMaxDynamicSharedMemorySize, sm);
            tgemm_k<64, false><<<g, blk, sm>>>(A, lda, Ab, Ah, Bm, ldb, Bb, Bh, C, ldc, Cb, Ch,
                                               Add, ldadd, Add2, gptr, K, ZH, alpha, mode,
                                               zmask, Aalt, Malt, M);
        }
    }
}

static void run_branch(Scratch* sp, const float* xi, const float* xd,
                       const int* ec, const int* ei, const int* eo, const int* ek,
                       const float* Wo, const float* arel, const float* mrel,
                       const float* prel, const float* skip, const float* poolW,
                       const float* poolAtt, const float* poolBias,
                       const float* tWo, const float* lng, const float* lnb, int branch)
{
    const long DD = (long)kD * kD;
    const long T1 = (long)kNI * kD;

    const int *rc = ec, *cc = ec + kEC;
    const int *ri = ei, *ci = ei + kEI;
    const int *ro = eo, *co = eo + kEO;
    const int *rk = ek, *ck = ek + kEK;

    assemble_x_k<<<(int)(LXD / 4 + 255) / 256, 256>>>(xi, xd, sp->x);

    bool csr_done = false;

    for (int l = 0; l < 2; l++) {
        for (int dir = 0; dir < 2; dir++) {
            int combo0 = (l * 2 + dir) * 2;
            // fused K|Q|V GEMM per node type
            for (int t = 0; t < 2; t++) {
                const float* xb = sp->x + (t ? T1 : 0);
                int M = t ? kND : kNI;
                long rowOff = (t ? T1 : 0) * 3;
                gemm(false, xb, kD, 0, 0, sp->pW + (long)(combo0 + t) * 196608, 768, 0, 0,
                     sp->kqv + rowOff, 768, 0, 0, nullptr, 0, nullptr, nullptr,
                     M, 768, kD, 1, 1, 1.f, 0);
            }
            if (!csr_done) {
                csr_count_k<<<(BB11 + 255) / 256, 256>>>(sp, rc, cc, ri, ci, ro, co, rk, ck);
                csr_scan_k<<<5, 1024>>>(sp);
                csr_fill_k<<<(BB12 + 255) / 256, 256>>>(sp, rc, cc, ri, ci, ro, co, rk, ck);
                csr_done = true;
            }
            // Krel / Vrel: batched across relations (zb) and heads (zh)
            // fwd: relation 1 reads data rows; rev: relation 2 reads data rows
            unsigned mask = dir ? 0x4u : 0x2u;
            long relOff = (long)((l * 2 + dir) * 4) * kH * kDH * kDH;
            long Aalt = (long)kNI * 768;   // data rows start here in kqv
            gemm(false, sp->kqv, 768, 0, 64, arel + relOff, kDH,
                 (long)kH * kDH * kDH, (long)kDH * kDH,
                 sp->Krel, kD, (long)kNI * kD, 64, nullptr, 0, nullptr, nullptr,
                 kNI, kDH, kDH, 4, kH, 1.f, 0, mask, Aalt, kND);
            gemm(false, sp->kqv + 512, 768, 0, 64, mrel + relOff, kDH,
                 (long)kH * kDH * kDH, (long)kDH * kDH,
                 sp->Vrel, kD, (long)kNI * kD, 64, nullptr, 0, nullptr, nullptr,
                 kNI, kDH, kDH, 4, kH, 1.f, 0, mask, Aalt, kND);

            const float* prelp = prel + (long)((l * 2 + dir) * 4) * kH;
            const float* Qbase = sp->kqv + 256;
            if (dir == 0)
                hgt_agg_k<<<kNT, 128>>>(Qbase, 768, sp->Krel, sp->Vrel,
                                        sp->rpf0, sp->ef0, sp->rpf1, sp->ef1,
                                        prelp, sp->agg);
            else
                hgt_agg_k<<<kNT, 128>>>(Qbase, 768, sp->Krel, sp->Vrel,
                                        sp->rpr0, sp->er0, sp->rpr1, sp->er1,
                                        prelp, sp->agg);
            // Wo: dir0 -> yF (mode 1); dir1 -> x in place (mode 3 fused comb+relu)
            long wOff = (long)combo0 * DD;
            for (int t = 0; t < 2; t++) {
                int M = t ? kND : kNI;
                long tOff = t ? T1 : 0;
                const float* gp = skip + (l * 2 + dir) * 2 + t;
                if (dir == 0)
                    gemm(false, sp->agg + tOff, kD, 0, 0, Wo + wOff + t * DD, kD, 0, 0,
                         sp->yF + tOff, kD, 0, 0, sp->x + tOff, kD, nullptr, gp,
                         M, kD, kD, 1, 1, 1.f, 1);
                else
                    gemm(false, sp->agg + tOff, kD, 0, 0, Wo + wOff + t * DD, kD, 0, 0,
                         sp->x + tOff, kD, 0, 0, sp->x + tOff, kD, sp->yF + tOff, gp,
                         M, kD, kD, 1, 1, 1.f, 3);
            }
        }
    }

    // pooling
    hv_k<<<kNT / 8, 256>>>(sp->x, poolW, sp->hv);
    gat_score_k<<<(kNT + 255) / 256, 256>>>(sp->hv, sp->rph, sp->eh, poolAtt, poolBias, sp->sc);
    topk_sort_k<<<kB, 1024>>>(sp->sc, sp->sv, sp->si);
    gather_k<<<dim3(kKP, kB), kD>>>(sp->x, sp->sv, sp->si, sp->xp);

    // transformer attention (fused QKV projection)
    int Mp = kB * kKP;
    gemm(false, sp->xp, kD, 0, 0, sp->pTw, 768, 0, 0, sp->qkvp, 768, 0, 0,
         nullptr, 0, nullptr, nullptr, Mp, 768, kD, 1, 1, 1.f, 0);
    long pb = (long)kKP * kD;
    long pq = (long)kKP * 768;
    long sb = (long)kH * kKP * kKP;
    gemm(true, sp->qkvp, 768, pq, kDH, sp->qkvp + 256, 768, pq, kDH,
         sp->S, kKP, sb, (long)kKP * kKP, nullptr, 0, nullptr, nullptr,
         kKP, kKP, kDH, kB, kH, 0.125f, 0);
    softmax_k<<<kB * kH * kKP, 256>>>(sp->S);
    gemm(false, sp->S, kKP, sb, (long)kKP * kKP, sp->qkvp + 512, 768, pq, kDH,
         sp->oh, kD, pb, kDH, nullptr, 0, nullptr, nullptr,
         kKP, kDH, kKP, kB, kH, 1.f, 0);
    gemm(false, sp->oh, kD, 0, 0, tWo, kD, 0, 0, sp->yb, kD, 0, 0,
         sp->xp, kD, nullptr, nullptr, Mp, kD, kD, 1, 1, 1.f, 2);
    ln_k<<<Mp, kD>>>(sp->yb, lng, lnb, sp->ga);
    featsum_k<<<kB, kD>>>(sp->xp, sp->ga, sp->u + (long)branch * kB * 512);
}

extern "C" void kernel_launch(void* const* d_in, const int* in_sizes, int n_in,
                              void* d_out, int out_size) {
    Scratch* sp = nullptr;
    cudaGetSymbolAddress((void**)&sp, SC);

    const float* Wk    = (const float*)d_in[12];
    const float* Wq    = (const float*)d_in[13];
    const float* Wv    = (const float*)d_in[14];
    const float* Wo    = (const float*)d_in[15];
    const float* arel  = (const float*)d_in[16];
    const float* mrel  = (const float*)d_in[17];
    const float* prel  = (const float*)d_in[18];
    const float* skip  = (const float*)d_in[19];
    const float* poolW = (const float*)d_in[20];
    const float* poolA = (const float*)d_in[21];
    const float* poolB = (const float*)d_in[22];
    const float* tWq   = (const float*)d_in[23];
    const float* tWk   = (const float*)d_in[24];
    const float* tWv   = (const float*)d_in[25];
    const float* tWo   = (const float*)d_in[26];
    const float* lng   = (const float*)d_in[27];
    const float* lnb   = (const float*)d_in[28];

    pack_hgt_w_k<<<(int)((8L * 256 * 768 + 255) / 256), 256>>>(Wk, Wq, Wv, sp->pW);
    pack_trans_w_k<<<(256 * 768 + 255) / 256, 256>>>(tWq, tWk, tWv, sp->pTw);

    for (int g = 0; g < 2; g++) {
        int base = g * 6;
        run_branch(sp,
                   (const float*)d_in[base + 0], (const float*)d_in[base + 1],
                   (const int*)d_in[base + 2], (const int*)d_in[base + 3],
                   (const int*)d_in[base + 4], (const int*)d_in[base + 5],
                   Wo, arel, mrel, prel, skip, poolW, poolA, poolB,
                   tWo, lng, lnb, g);
    }
    cos_k<<<kB, 512>>>(sp->u, (float*)d_out);
}

// round 11
// speedup vs baseline: 4.0336x; 1.1786x over previous
#include <cuda_runtime.h>
#include <math.h>
#include <stdint.h>

// ------------------------- problem constants -------------------------
constexpr int kNI = 8192, kND = 4096, kNT = 12288, kD = 256, kH = 4, kDH = 64;
constexpr int kB = 8, kKP = 768;
constexpr int kEC = 65536, kEI = 32768, kEO = 32768, kEK = 8192;
constexpr long LXD = (long)kNT * kD;
constexpr long LPD = (long)kB * kKP * kD;

// counter-region offsets (5 CSRs share one cnt/cur buffer)
constexpr int O0 = 0;
constexpr int O1 = kNI;
constexpr int O2 = kNI + kND;
constexpr int O3 = 2 * kNI + kND;
constexpr int O4 = 2 * kNI + 2 * kND;
constexpr int CNT_TOT = O4 + kNT;

// fused edge-slot boundaries
constexpr int BB0 = kEC;
constexpr int BB1 = BB0 + kEI;
constexpr int BB2 = BB1 + kEK;
constexpr int BB3 = BB2 + kEO;
constexpr int BB4 = BB3 + kEC;
constexpr int BB5 = BB4 + kEO;
constexpr int BB6 = BB5 + kEK;
constexpr int BB7 = BB6 + kEI;
constexpr int BB8 = BB7 + kEC;
constexpr int BB9 = BB8 + kEI;
constexpr int BB10 = BB9 + kEO;
constexpr int BB11 = BB10 + kEK;
constexpr int BB12 = BB11 + kNT;

// ------------------------- scratch -------------------------
struct Scratch {
    float x[LXD], yF[LXD], agg[LXD];
    float kqv[3 * LXD];                       // [node][768] packed K|Q|V
    float Krel[4L * kNI * kD];                // MUST stay adjacent to Vrel (z-batched C)
    float Vrel[4L * kNI * kD];
    float S[(long)kB * kH * kKP * kKP];
    float xp[LPD], qkvp[3 * LPD], oh[LPD], yb[LPD], ga[LPD];
    float pW[8L * 256 * 768];
    float pTw[256 * 768];
    float pRel[4L * 8 * 4 * 64 * 64];         // [combo][rel(K0-3,V0-3)][h][64][64]
    float hv[kNT], sc[kNT];
    float sv[kB * kKP];
    int   si[kB * kKP];
    float u[2 * kB * 512];
    float up[kB * 6 * 512];
    int rpf0[kNI + 1], rpf1[kND + 1], rpr0[kNI + 1], rpr1[kND + 1], rph[kNT + 1];
    int ef0[kEC + kEI + kEK], ef1[kEO], er0[kEC + kEO + kEK], er1[kEI];
    int eh[kEC + kEI + kEO + kEK + kNT];
    int cnt[CNT_TOT], cur[CNT_TOT];
};
__device__ Scratch SC;

// ------------------------- reductions -------------------------
__device__ __forceinline__ float wsum(float v) {
#pragma unroll
    for (int o = 16; o; o >>= 1) v += __shfl_xor_sync(0xffffffffu, v, o);
    return v;
}
__device__ __forceinline__ float bsum(float v) {
    __shared__ float sh[32];
    int lane = threadIdx.x & 31, w = threadIdx.x >> 5;
    v = wsum(v);
    if (!lane) sh[w] = v;
    __syncthreads();
    int nw = blockDim.x >> 5;
    float s = (threadIdx.x < nw) ? sh[threadIdx.x] : 0.f;
    if (w == 0) s = wsum(s);
    if (threadIdx.x == 0) sh[0] = s;
    __syncthreads();
    float r = sh[0];
    __syncthreads();
    return r;
}
__device__ __forceinline__ float bmax(float v) {
    __shared__ float sh[32];
    int lane = threadIdx.x & 31, w = threadIdx.x >> 5;
#pragma unroll
    for (int o = 16; o; o >>= 1) v = fmaxf(v, __shfl_xor_sync(0xffffffffu, v, o));
    if (!lane) sh[w] = v;
    __syncthreads();
    int nw = blockDim.x >> 5;
    float s = (threadIdx.x < nw) ? sh[threadIdx.x] : -INFINITY;
    if (w == 0)
#pragma unroll
        for (int o = 16; o; o >>= 1) s = fmaxf(s, __shfl_xor_sync(0xffffffffu, s, o));
    if (threadIdx.x == 0) sh[0] = s;
    __syncthreads();
    float r = sh[0];
    __syncthreads();
    return r;
}

// ------------------------- tf32 tensor-core GEMM (cp.async pipelined) --------
__device__ __forceinline__ void mma_tf32(float* c, const uint32_t* a,
                                         uint32_t b0, uint32_t b1) {
    asm volatile(
        "mma.sync.aligned.m16n8k8.row.col.f32.tf32.tf32.f32 "
        "{%0,%1,%2,%3}, {%4,%5,%6,%7}, {%8,%9}, {%0,%1,%2,%3};"
        : "+f"(c[0]), "+f"(c[1]), "+f"(c[2]), "+f"(c[3])
        : "r"(a[0]), "r"(a[1]), "r"(a[2]), "r"(a[3]), "r"(b0), "r"(b1));
}
__device__ __forceinline__ void cpa16(float* dst, const float* src) {
    unsigned d = (unsigned)__cvta_generic_to_shared(dst);
    asm volatile("cp.async.cg.shared.global [%0], [%1], 16;\n" :: "r"(d), "l"(src));
}
#define CP_COMMIT() asm volatile("cp.async.commit_group;\n" ::: "memory")
#define CP_WAIT1()  asm volatile("cp.async.wait_group 1;\n" ::: "memory")
#define CP_WAIT0()  asm volatile("cp.async.wait_group 0;\n" ::: "memory")

// C = epilogue(alpha * A @ B(^T)); z -> (zb = z/ZH, zh = z%ZH).
// Per-z: if bit zb of zmask set -> A += Aalt, M = Malt. If zb >= zsplit -> A += Valt.
// Add/Add2 are offset by zb*Cb + zh*Ch (same strides as C). Gate is gptr[zb].
// mode 0: C = v
// mode 1: C = g*v + (1-g)*Add
// mode 2: C = v + Add
// mode 3: C = relu(0.5*(g*v + (1-g)*Add) + 0.5*Add2)
template <int BN, bool TB>
__global__ void __launch_bounds__(256, 2) tgemm_k(
    const float* __restrict__ A, int lda, long Ab, long Ah,
    const float* __restrict__ Bm, int ldb, long Bb, long Bh,
    float* __restrict__ C, int ldc, long Cb, long Ch,
    const float* __restrict__ Add, int ldadd, const float* __restrict__ Add2,
    const float* __restrict__ gptr,
    int Kdim, int ZH, float alpha, int mode,
    unsigned zmask, long Aalt, int Malt, int Mdef, long Valt, int zsplit)
{
    constexpr int BM = 128, BK = 32;
    constexpr int ASTR = 44;
    constexpr int BROWS = TB ? BN : BK;
    constexpr int BSTR = TB ? 44 : (BN + 8);
    constexpr int TN = (BN == 128) ? 8 : 4;
    extern __shared__ float sm_[];
    float* As = sm_;
    float* Bs = sm_ + 2 * BM * ASTR;

    int z = blockIdx.z, zb = z / ZH, zh = z - zb * ZH;
    int msk = (zmask >> zb) & 1;
    int Mz = msk ? Malt : Mdef;
    int m0 = blockIdx.x * BM;
    if (m0 >= Mz) return;
    const float* Ax = A + zb * Ab + zh * Ah + (msk ? Aalt : 0) + (zb >= zsplit ? Valt : 0);
    const float* Bx = Bm + zb * Bb + zh * Bh;
    C += zb * Cb + zh * Ch;
    if (Add)  Add  += zb * Cb + zh * Ch;
    if (Add2) Add2 += zb * Cb + zh * Ch;
    int n0 = blockIdx.y * BN;
    int tid = threadIdx.x, lane = tid & 31, warp = tid >> 5;
    int wm = warp >> 1, wn = warp & 1;
    int g = lane >> 2, tg = lane & 3;

    float acc[2][TN][4];
#pragma unroll
    for (int i = 0; i < 2; i++)
#pragma unroll
        for (int j = 0; j < TN; j++)
#pragma unroll
            for (int q = 0; q < 4; q++) acc[i][j][q] = 0.f;

    int nt = Kdim / BK;

#define ISSUE(K0, S) do {                                                      \
        float* Ad = As + (S) * BM * ASTR;                                      \
        _Pragma("unroll")                                                      \
        for (int q = 0; q < 4; q++) {                                          \
            int f = tid + q * 256, row = f >> 3, kc = (f & 7) * 4;             \
            cpa16(Ad + row * ASTR + kc,                                        \
                  Ax + (long)(m0 + row) * lda + (K0) + kc);                    \
        }                                                                      \
        float* Bd = Bs + (S) * BROWS * BSTR;                                   \
        _Pragma("unroll")                                                      \
        for (int q = 0; q < BN / 32; q++) {                                    \
            int f = tid + q * 256;                                             \
            if (TB) {                                                          \
                int rr = f >> 3, rc = (f & 7) * 4;                             \
                cpa16(Bd + rr * BSTR + rc,                                     \
                      Bx + (long)(n0 + rr) * ldb + (K0) + rc);                 \
            } else {                                                           \
                int rr = f / (BN / 4), rc = (f % (BN / 4)) * 4;                \
                cpa16(Bd + rr * BSTR + rc,                                     \
                      Bx + (long)((K0) + rr) * ldb + n0 + rc);                 \
            }                                                                  \
        }                                                                      \
    } while (0)

    ISSUE(0, 0);
    CP_COMMIT();

    for (int t = 0; t < nt; t++) {
        if (t + 1 < nt) {
            ISSUE((t + 1) * BK, (t + 1) & 1);
            CP_COMMIT();
            CP_WAIT1();
        } else {
            CP_WAIT0();
        }
        __syncthreads();
        const float* Ap = As + (size_t)(t & 1) * BM * ASTR;
        const float* Bp = Bs + (size_t)(t & 1) * BROWS * BSTR;
#pragma unroll
        for (int k8 = 0; k8 < 4; k8++) {
            int kb = k8 * 8;
            uint32_t a[2][4];
#pragma unroll
            for (int tm = 0; tm < 2; tm++) {
                int mr = wm * 32 + tm * 16;
                a[tm][0] = __float_as_uint(Ap[(mr + g) * ASTR + kb + tg]);
                a[tm][1] = __float_as_uint(Ap[(mr + 8 + g) * ASTR + kb + tg]);
                a[tm][2] = __float_as_uint(Ap[(mr + g) * ASTR + kb + tg + 4]);
                a[tm][3] = __float_as_uint(Ap[(mr + 8 + g) * ASTR + kb + tg + 4]);
            }
#pragma unroll
            for (int tn = 0; tn < TN; tn++) {
                int nc = wn * (TN * 8) + tn * 8 + g;
                uint32_t b0, b1;
                if (TB) {
                    b0 = __float_as_uint(Bp[nc * BSTR + kb + tg]);
                    b1 = __float_as_uint(Bp[nc * BSTR + kb + tg + 4]);
                } else {
                    b0 = __float_as_uint(Bp[(kb + tg) * BSTR + nc]);
                    b1 = __float_as_uint(Bp[(kb + tg + 4) * BSTR + nc]);
                }
#pragma unroll
                for (int tm = 0; tm < 2; tm++)
                    mma_tf32(acc[tm][tn], a[tm], b0, b1);
            }
        }
        __syncthreads();
    }
#undef ISSUE

    float gg = 1.f;
    if (mode == 1 || mode == 3) gg = 1.f / (1.f + expf(-gptr[zb]));
#pragma unroll
    for (int tm = 0; tm < 2; tm++) {
        long row0 = m0 + wm * 32 + tm * 16 + g;
#pragma unroll
        for (int tn = 0; tn < TN; tn++) {
            long col = n0 + wn * (TN * 8) + tn * 8 + tg * 2;
#pragma unroll
            for (int half = 0; half < 2; half++) {
                long r = row0 + half * 8;
                float vx = alpha * acc[tm][tn][half * 2 + 0];
                float vy = alpha * acc[tm][tn][half * 2 + 1];
                if (mode == 1) {
                    float2 ad = *(const float2*)(Add + r * ldadd + col);
                    vx = gg * vx + (1.f - gg) * ad.x;
                    vy = gg * vy + (1.f - gg) * ad.y;
                } else if (mode == 2) {
                    float2 ad = *(const float2*)(Add + r * ldadd + col);
                    vx += ad.x; vy += ad.y;
                } else if (mode == 3) {
                    float2 ad = *(const float2*)(Add + r * ldadd + col);
                    float2 a2 = *(const float2*)(Add2 + r * ldadd + col);
                    vx = 0.5f * (gg * vx + (1.f - gg) * ad.x) + 0.5f * a2.x;
                    vy = 0.5f * (gg * vy + (1.f - gg) * ad.y) + 0.5f * a2.y;
                    vx = vx > 0.f ? vx : 0.f;
                    vy = vy > 0.f ? vy : 0.f;
                }
                float2 o; o.x = vx; o.y = vy;
                *(float2*)(C + r * ldc + col) = o;
            }
        }
    }
}

// ------------------------- weight packing -------------------------
__global__ void pack_hgt_w_k(const float* __restrict__ Wk, const float* __restrict__ Wq,
                             const float* __restrict__ Wv, float* __restrict__ pW) {
    long i = (long)blockIdx.x * blockDim.x + threadIdx.x;
    if (i >= 8L * 256 * 768) return;
    int n = (int)(i % 768);
    long rem = i / 768;
    int k = (int)(rem % 256);
    int c = (int)(rem / 256);
    int sel = n >> 8, nn = n & 255;
    const float* W = (sel == 0) ? Wk : (sel == 1) ? Wq : Wv;
    pW[(long)c * 196608 + (long)k * 768 + n] = W[(long)c * 65536 + (long)k * 256 + nn];
}
__global__ void pack_trans_w_k(const float* __restrict__ Wq, const float* __restrict__ Wk,
                               const float* __restrict__ Wv, float* __restrict__ pTw) {
    int i = blockIdx.x * blockDim.x + threadIdx.x;
    if (i >= 256 * 768) return;
    int n = i % 768, k = i / 768;
    int sel = n >> 8, nn = n & 255;
    const float* W = (sel == 0) ? Wq : (sel == 1) ? Wk : Wv;
    pTw[(long)k * 768 + n] = W[(long)k * 256 + nn];
}
// pRel[c][zr][h][64*64]; zr 0-3 = arel rels, 4-7 = mrel rels
__global__ void pack_rel_k(const float* __restrict__ arel, const float* __restrict__ mrel,
                           float* __restrict__ pRel) {
    long i = (long)blockIdx.x * blockDim.x + threadIdx.x;
    if (i >= 4L * 8 * 4 * 4096) return;
    int n  = (int)(i & 4095);
    int hh = (int)((i >> 12) & 3);
    int zr = (int)((i >> 14) & 7);
    int c  = (int)(i >> 17);
    const float* src = (zr < 4) ? arel : mrel;
    int r = zr & 3;
    pRel[i] = src[(((long)(c * 4 + r) * 4 + hh) << 12) + n];
}

// ------------------------- elementwise -------------------------
__global__ void assemble_x_k(const float* __restrict__ xi, const float* __restrict__ xd,
                             float* __restrict__ x) {
    long i = ((long)blockIdx.x * blockDim.x + threadIdx.x) * 4;
    if (i < LXD) {
        const long T1 = (long)kNI * kD;
        float4 v = (i < T1) ? *(const float4*)(xi + i) : *(const float4*)(xd + (i - T1));
        *(float4*)(x + i) = v;
    }
}

// ------------------------- fused CSR construction -------------------------
struct Slot { int idx; int ent; int arr; };
__device__ __forceinline__ Slot decode_slot(
    int i, const int* rc, const int* cc, const int* ri, const int* ci,
    const int* ro, const int* co, const int* rk, const int* ck)
{
    Slot s;
    if (i < BB0)       { s.idx = O0 + cc[i];            s.ent = (0 << 16) | rc[i];            s.arr = 0; }
    else if (i < BB1)  { int j = i - BB0;  s.idx = O0 + ci[j]; s.ent = (1 << 16) | ri[j];     s.arr = 0; }
    else if (i < BB2)  { int j = i - BB1;  s.idx = O0 + ck[j]; s.ent = (3 << 16) | rk[j];     s.arr = 0; }
    else if (i < BB3)  { int j = i - BB2;  s.idx = O1 + co[j]; s.ent = (2 << 16) | ro[j];     s.arr = 1; }
    else if (i < BB4)  { int j = i - BB3;  s.idx = O2 + rc[j]; s.ent = (0 << 16) | cc[j];     s.arr = 2; }
    else if (i < BB5)  { int j = i - BB4;  s.idx = O2 + ro[j]; s.ent = (2 << 16) | co[j];     s.arr = 2; }
    else if (i < BB6)  { int j = i - BB5;  s.idx = O2 + rk[j]; s.ent = (3 << 16) | ck[j];     s.arr = 2; }
    else if (i < BB7)  { int j = i - BB6;  s.idx = O3 + ri[j]; s.ent = (1 << 16) | ci[j];     s.arr = 3; }
    else if (i < BB8)  { int j = i - BB7;  s.idx = O4 + cc[j]; s.ent = rc[j];                 s.arr = 4; }
    else if (i < BB9)  { int j = i - BB8;  s.idx = O4 + ci[j]; s.ent = ri[j] + kNI;           s.arr = 4; }
    else if (i < BB10) { int j = i - BB9;  s.idx = O4 + co[j] + kNI; s.ent = ro[j];           s.arr = 4; }
    else               { int j = i - BB10; s.idx = O4 + ck[j]; s.ent = rk[j];                 s.arr = 4; }
    return s;
}

__global__ void csr_count_k(Scratch* sp, const int* rc, const int* cc,
                            const int* ri, const int* ci, const int* ro, const int* co,
                            const int* rk, const int* ck) {
    int i = blockIdx.x * blockDim.x + threadIdx.x;
    if (i < BB11) {
        Slot s = decode_slot(i, rc, cc, ri, ci, ro, co, rk, ck);
        atomicAdd(&sp->cnt[s.idx], 1);
    }
}
__global__ void csr_scan_k(Scratch* sp) {
    __shared__ int sh[1024];
    int region = blockIdx.x, t = threadIdx.x;
    int off, n, extra = 0;
    int* rp;
    switch (region) {
        case 0: off = O0; n = kNI; rp = sp->rpf0; break;
        case 1: off = O1; n = kND; rp = sp->rpf1; break;
        case 2: off = O2; n = kNI; rp = sp->rpr0; break;
        case 3: off = O3; n = kND; rp = sp->rpr1; break;
        default: off = O4; n = kNT; rp = sp->rph; extra = 1; break;
    }
    int c = (n + 1023) >> 10;
    int beg = t * c, end = min(beg + c, n);
    int s = 0;
    for (int i = beg; i < end; i++) s += sp->cnt[off + i] + extra;
    sh[t] = s;
    __syncthreads();
    for (int o = 1; o < 1024; o <<= 1) {
        int v = (t >= o) ? sh[t - o] : 0;
        __syncthreads();
        sh[t] += v;
        __syncthreads();
    }
    int run = t ? sh[t - 1] : 0;
    for (int i = beg; i < end; i++) {
        int cv = sp->cnt[off + i];
        sp->cnt[off + i] = 0;
        rp[i] = run;
        sp->cur[off + i] = run;
        run += cv + extra;
    }
    if (t == 1023) rp[n] = sh[1023];
}
__global__ void csr_fill_k(Scratch* sp, const int* rc, const int* cc,
                           const int* ri, const int* ci, const int* ro, const int* co,
                           const int* rk, const int* ck) {
    int i = blockIdx.x * blockDim.x + threadIdx.x;
    if (i >= BB12) return;
    if (i < BB11) {
        Slot s = decode_slot(i, rc, cc, ri, ci, ro, co, rk, ck);
        int pos = atomicAdd(&sp->cur[s.idx], 1);
        switch (s.arr) {
            case 0: sp->ef0[pos] = s.ent; break;
            case 1: sp->ef1[pos] = s.ent; break;
            case 2: sp->er0[pos] = s.ent; break;
            case 3: sp->er1[pos] = s.ent; break;
            default: sp->eh[pos] = s.ent; break;
        }
    } else {
        int node = i - BB11;
        int pos = atomicAdd(&sp->cur[O4 + node], 1);
        sp->eh[pos] = node;
    }
}

// ------------------------- HGT softmax aggregation (2-edge ILP, gelu fused) ----
__global__ void hgt_agg_k(const float* __restrict__ Q, int qs,
                          const float* __restrict__ Krel, const float* __restrict__ Vrel,
                          const int* __restrict__ rp0, const int* __restrict__ e0,
                          const int* __restrict__ rp1, const int* __restrict__ e1,
                          const float* __restrict__ prel, float* __restrict__ agg)
{
    int node = blockIdx.x;
    const int* rp; const int* ent; int idx;
    if (node < kNI) { rp = rp0; ent = e0; idx = node; }
    else            { rp = rp1; ent = e1; idx = node - kNI; }
    int h = threadIdx.x >> 5, lane = threadIdx.x & 31;
    const float* q = Q + (long)node * qs + h * kDH;
    float q0 = q[lane], q1 = q[lane + 32];
    float pr0 = prel[0 * kH + h], pr1 = prel[1 * kH + h];
    float pr2 = prel[2 * kH + h], pr3 = prel[3 * kH + h];
    int s = rp[idx], eend = rp[idx + 1];
    float m = -INFINITY, den = 0.f, a0 = 0.f, a1 = 0.f;
    int e = s;
    for (; e + 1 < eend; e += 2) {
        int pkA = ent[e], pkB = ent[e + 1];
        int rA = pkA >> 16, sA = pkA & 0xffff;
        int rB = pkB >> 16, sB = pkB & 0xffff;
        const float* krA = Krel + ((long)rA * kNI + sA) * kD + h * kDH;
        const float* krB = Krel + ((long)rB * kNI + sB) * kD + h * kDH;
        const float* vrA = Vrel + ((long)rA * kNI + sA) * kD + h * kDH;
        const float* vrB = Vrel + ((long)rB * kNI + sB) * kD + h * kDH;
        float dA = q0 * krA[lane] + q1 * krA[lane + 32];
        float dB = q0 * krB[lane] + q1 * krB[lane + 32];
        float vA0 = vrA[lane], vA1 = vrA[lane + 32];
        float vB0 = vrB[lane], vB1 = vrB[lane + 32];
#pragma unroll
        for (int o = 16; o; o >>= 1) {
            dA += __shfl_xor_sync(0xffffffffu, dA, o);
            dB += __shfl_xor_sync(0xffffffffu, dB, o);
        }
        float prA = (rA == 0) ? pr0 : (rA == 1) ? pr1 : (rA == 2) ? pr2 : pr3;
        float prB = (rB == 0) ? pr0 : (rB == 1) ? pr1 : (rB == 2) ? pr2 : pr3;
        float scA = dA * prA * 0.125f, scB = dB * prB * 0.125f;
        float mn = fmaxf(m, fmaxf(scA, scB));
        float cc = expf(m - mn), wA = expf(scA - mn), wB = expf(scB - mn);
        den = den * cc + wA + wB;
        a0 = a0 * cc + wA * vA0 + wB * vB0;
        a1 = a1 * cc + wA * vA1 + wB * vB1;
        m = mn;
    }
    if (e < eend) {
        int pk = ent[e];
        int r = pk >> 16, src = pk & 0xffff;
        const float* kr = Krel + ((long)r * kNI + src) * kD + h * kDH;
        const float* vr = Vrel + ((long)r * kNI + src) * kD + h * kDH;
        float d0 = q0 * kr[lane] + q1 * kr[lane + 32];
        d0 = wsum(d0);
        float pr = (r == 0) ? pr0 : (r == 1) ? pr1 : (r == 2) ? pr2 : pr3;
        float sc2 = d0 * pr * 0.125f;
        float mn = fmaxf(m, sc2);
        float cc = expf(m - mn), w = expf(sc2 - mn);
        den = den * cc + w;
        a0 = a0 * cc + w * vr[lane];
        a1 = a1 * cc + w * vr[lane + 32];
        m = mn;
    }
    float inv = 1.f / (den + 1e-16f);
    float r0 = a0 * inv, r1 = a1 * inv;
    float* o = agg + (long)node * kD + h * kDH;
    o[lane]      = 0.5f * r0 * (1.f + erff(r0 * 0.7071067811865475f));
    o[lane + 32] = 0.5f * r1 * (1.f + erff(r1 * 0.7071067811865475f));
}

// ------------------------- pooling -------------------------
__global__ void hv_k(const float* __restrict__ x, const float* __restrict__ pw,
                     float* __restrict__ hv) {
    int node = blockIdx.x * 8 + (threadIdx.x >> 5);
    int lane = threadIdx.x & 31;
    if (node >= kNT) return;
    float s = 0.f;
    for (int d = lane; d < kD; d += 32) s += x[(long)node * kD + d] * pw[d];
    s = wsum(s);
    if (!lane) hv[node] = s;
}
__global__ void gat_score_k(const float* __restrict__ hv, const int* __restrict__ rp,
                            const int* __restrict__ ent, const float* __restrict__ att,
                            const float* __restrict__ bias, float* __restrict__ sc) {
    int i = blockIdx.x * blockDim.x + threadIdx.x;
    if (i >= kNT) return;
    float A0 = att[0], A1 = att[1];
    float hi = hv[i];
    int s = rp[i], e1 = rp[i + 1];
    float m = -INFINITY, den = 0.f, acc = 0.f;
    for (int e = s; e < e1; e++) {
        int src = ent[e] & 0xffff;
        float hs = hv[src];
        float ee = A0 * hs + A1 * hi;
        ee = ee >= 0.f ? ee : 0.2f * ee;
        float mn = fmaxf(m, ee);
        float c = expf(m - mn), w = expf(ee - mn);
        den = den * c + w;
        acc = acc * c + w * hs;
        m = mn;
    }
    sc[i] = acc / (den + 1e-16f) + bias[0];
}

__global__ void topk_sort_k(const float* __restrict__ sc, float* __restrict__ sv,
                            int* __restrict__ si) {
    int b = blockIdx.x, t = threadIdx.x;
    __shared__ float v[2048];
    __shared__ int ix[2048];
    for (int p = t; p < 2048; p += 1024) {
        float val = -INFINITY;
        if (p < 1536) {
            int node = p < 1024 ? b * 1024 + p : kNI + b * 512 + (p - 1024);
            val = sc[node];
        }
        v[p] = val;
        ix[p] = p;
    }
    __syncthreads();
    for (int k = 2; k <= 2048; k <<= 1)
        for (int j = k >> 1; j > 0; j >>= 1) {
#pragma unroll
            for (int pass = 0; pass < 2; pass++) {
                int i = t + pass * 1024;
                int l = i ^ j;
                if (l > i) {
                    bool up = ((i & k) == 0);
                    float vi = v[i], vl = v[l];
                    int ii = ix[i], il = ix[l];
                    bool before = (vi > vl) || (vi == vl && ii < il);
                    if (up != before) {
                        v[i] = vl; v[l] = vi;
                        ix[i] = il; ix[l] = ii;
                    }
                }
            }
            __syncthreads();
        }
    if (t < kKP) {
        sv[b * kKP + t] = v[t];
        si[b * kKP + t] = ix[t];
    }
}
__global__ void gather_k(const float* __restrict__ x, const float* __restrict__ sv,
                         const int* __restrict__ si, float* __restrict__ xp) {
    int q = blockIdx.x, b = blockIdx.y, d = threadIdx.x;
    int j = si[b * kKP + q];
    float tv = tanhf(sv[b * kKP + q]);
    int node = j < 1024 ? b * 1024 + j : kNI + b * 512 + (j - 1024);
    xp[((long)(b * kKP + q)) * kD + d] = x[(long)node * kD + d] * tv;
}

// ------------------------- transformer pieces -------------------------
__global__ void softmax_k(float* __restrict__ S) {
    long row = blockIdx.x;
    float* p = S + row * kKP;
    int t = threadIdx.x;
    float v0 = p[t], v1 = p[t + 256], v2 = p[t + 512];
    float m = bmax(fmaxf(v0, fmaxf(v1, v2)));
    v0 = expf(v0 - m); v1 = expf(v1 - m); v2 = expf(v2 - m);
    float s = bsum(v0 + v1 + v2);
    float inv = 1.f / s;
    p[t] = v0 * inv; p[t + 256] = v1 * inv; p[t + 512] = v2 * inv;
}
__global__ void ln_k(const float* __restrict__ y, const float* __restrict__ g,
                     const float* __restrict__ bta, float* __restrict__ out) {
    long row = blockIdx.x;
    int d = threadIdx.x;
    float v = y[row * kD + d];
    float mu = bsum(v) * (1.f / kD);
    float df = v - mu;
    float var = bsum(df * df) * (1.f / kD);
    out[row * kD + d] = g[d] * df * rsqrtf(var + 1e-5f) + bta[d];
}
// two-stage deterministic featsum: partials then reduce
__global__ void featsum_part_k(const float* __restrict__ xp, const float* __restrict__ ga,
                               float* __restrict__ up) {
    int b = blockIdx.x, ch = blockIdx.y, d = threadIdx.x;   // 256 threads
    float s1 = 0.f, s2 = 0.f;
    int q0 = ch * 128;
    for (int q = q0; q < q0 + 128; q++) {
        long o = ((long)(b * kKP + q)) * kD + d;
        s1 += xp[o];
        s2 += ga[o];
    }
    up[(b * 6 + ch) * 512 + d] = s1;
    up[(b * 6 + ch) * 512 + 256 + d] = s2;
}
__global__ void featsum_red_k(const float* __restrict__ up, float* __restrict__ u) {
    int b = blockIdx.x, d = threadIdx.x;   // 512 threads
    float s = 0.f;
    for (int ch = 0; ch < 6; ch++) s += up[(b * 6 + ch) * 512 + d];
    u[b * 512 + d] = s;
}
__global__ void cos_k(const float* __restrict__ u, float* __restrict__ out) {
    int b = blockIdx.x, t = threadIdx.x;
    float a = u[b * 512 + t];
    float c = u[(kB + b) * 512 + t];
    float dot = bsum(a * c);
    float na = bsum(a * a);
    float nc = bsum(c * c);
    if (t == 0)
        out[b] = dot / (fmaxf(sqrtf(na), 1e-8f) * fmaxf(sqrtf(nc), 1e-8f));
}

// ------------------------- host orchestration -------------------------
static inline int gemm_smem(bool tb, int BN) {
    int a = 2 * 128 * 44;
    int b = tb ? 2 * BN * 44 : 2 * 32 * (BN + 8);
    return (a + b) * 4;
}
static inline void gemm(bool tb, const float* A, int lda, long Ab, long Ah,
                        const float* Bm, int ldb, long Bb, long Bh,
                        float* C, int ldc, long Cb, long Ch,
                        const float* Add, int ldadd, const float* Add2,
                        const float* gptr,
                        int M, int N, int K, int ZB, int ZH, float alpha, int mode,
                        unsigned zmask = 0, long Aalt = 0, int Malt = 0,
                        long Valt = 0, int zsplit = 1 << 30) {
    if (N % 128 == 0) {
        int sm = gemm_smem(tb, 128);
        dim3 g(M / 128, N / 128, ZB * ZH), blk(256);
        if (tb) {
            cudaFuncSetAttribute(tgemm_k<128, true>,
                                 cudaFuncAttributeMaxDynamicSharedMemorySize, sm);
            tgemm_k<128, true><<<g, blk, sm>>>(A, lda, Ab, Ah, Bm, ldb, Bb, Bh, C, ldc, Cb, Ch,
                                               Add, ldadd, Add2, gptr, K, ZH, alpha, mode,
                                               zmask, Aalt, Malt, M, Valt, zsplit);
        } else {
            cudaFuncSetAttribute(tgemm_k<128, false>,
                                 cudaFuncAttributeMaxDynamicSharedMemorySize, sm);
            tgemm_k<128, false><<<g, blk, sm>>>(A, lda, Ab, Ah, Bm, ldb, Bb, Bh, C, ldc, Cb, Ch,
                                                Add, ldadd, Add2, gptr, K, ZH, alpha, mode,
                                                zmask, Aalt, Malt, M, Valt, zsplit);
        }
    } else {
        int sm = gemm_smem(tb, 64);
        dim3 g(M / 128, N / 64, ZB * ZH), blk(256);
        if (tb) {
            cudaFuncSetAttribute(tgemm_k<64, true>,
                                 cudaFuncAttributeMaxDynamicSharedMemorySize, sm);
            tgemm_k<64, true><<<g, blk, sm>>>(A, lda, Ab, Ah, Bm, ldb, Bb, Bh, C, ldc, Cb, Ch,
                                              Add, ldadd, Add2, gptr, K, ZH, alpha, mode,
                                              zmask, Aalt, Malt, M, Valt, zsplit);
        } else {
            cudaFuncSetAttribute(tgemm_k<64, false>,
                                 cudaFuncAttributeMaxDynamicSharedMemorySize, sm);
            tgemm_k<64, false><<<g, blk, sm>>>(A, lda, Ab, Ah, Bm, ldb, Bb, Bh, C, ldc, Cb, Ch,
                                               Add, ldadd, Add2, gptr, K, ZH, alpha, mode,
                                               zmask, Aalt, Malt, M, Valt, zsplit);
        }
    }
}

static void run_branch(Scratch* sp, const float* xi, const float* xd,
                       const int* ec, const int* ei, const int* eo, const int* ek,
                       const float* Wo, const float* prel, const float* skip,
                       const float* poolW, const float* poolAtt, const float* poolBias,
                       const float* tWo, const float* lng, const float* lnb, int branch)
{
    const long DD = (long)kD * kD;
    const long T1 = (long)kNI * kD;

    const int *rc = ec, *cc = ec + kEC;
    const int *ri = ei, *ci = ei + kEI;
    const int *ro = eo, *co = eo + kEO;
    const int *rk = ek, *ck = ek + kEK;

    assemble_x_k<<<(int)(LXD / 4 + 255) / 256, 256>>>(xi, xd, sp->x);

    bool csr_done = false;

    for (int l = 0; l < 2; l++) {
        for (int dir = 0; dir < 2; dir++) {
            int combo = l * 2 + dir;
            // fused K|Q|V GEMM, both node types in one z=2 launch
            gemm(false, sp->x, kD, 0, 0,
                 sp->pW + (long)(combo * 2) * 196608, 768, 196608, 0,
                 sp->kqv, 768, (long)kNI * 768, 0,
                 nullptr, 0, nullptr, nullptr,
                 kNI, 768, kD, 2, 1, 1.f, 0,
                 0x2u, T1, kND);
            if (!csr_done) {
                csr_count_k<<<(BB11 + 255) / 256, 256>>>(sp, rc, cc, ri, ci, ro, co, rk, ck);
                csr_scan_k<<<5, 1024>>>(sp);
                csr_fill_k<<<(BB12 + 255) / 256, 256>>>(sp, rc, cc, ri, ci, ro, co, rk, ck);
                csr_done = true;
            }
            // Krel + Vrel: one z=32 launch (zb 0-3 = K rels, 4-7 = V rels; zh = head)
            unsigned mask = dir ? 0x44u : 0x22u;
            gemm(false, sp->kqv, 768, 0, 64,
                 sp->pRel + (long)combo * 8 * 4 * 4096, kDH, (long)4 * 4096, 4096,
                 sp->Krel, kD, (long)kNI * kD, 64,
                 nullptr, 0, nullptr, nullptr,
                 kNI, kDH, kDH, 8, kH, 1.f, 0,
                 mask, (long)kNI * 768, kND, 512, 4);

            const float* prelp = prel + (long)(combo * 4) * kH;
            const float* Qbase = sp->kqv + 256;
            if (dir == 0)
                hgt_agg_k<<<kNT, 128>>>(Qbase, 768, sp->Krel, sp->Vrel,
                                        sp->rpf0, sp->ef0, sp->rpf1, sp->ef1,
                                        prelp, sp->agg);
            else
                hgt_agg_k<<<kNT, 128>>>(Qbase, 768, sp->Krel, sp->Vrel,
                                        sp->rpr0, sp->er0, sp->rpr1, sp->er1,
                                        prelp, sp->agg);
            // Wo: both node types in one z=2 launch
            long wOff = (long)(combo * 2) * DD;
            const float* gp = skip + combo * 2;
            if (dir == 0)
                gemm(false, sp->agg, kD, 0, 0, Wo + wOff, kD, DD, 0,
                     sp->yF, kD, T1, 0, sp->x, kD, nullptr, gp,
                     kNI, kD, kD, 2, 1, 1.f, 1,
                     0x2u, T1, kND);
            else
                gemm(false, sp->agg, kD, 0, 0, Wo + wOff, kD, DD, 0,
                     sp->x, kD, T1, 0, sp->x, kD, sp->yF, gp,
                     kNI, kD, kD, 2, 1, 1.f, 3,
                     0x2u, T1, kND);
        }
    }

    // pooling
    hv_k<<<kNT / 8, 256>>>(sp->x, poolW, sp->hv);
    gat_score_k<<<(kNT + 255) / 256, 256>>>(sp->hv, sp->rph, sp->eh, poolAtt, poolBias, sp->sc);
    topk_sort_k<<<kB, 1024>>>(sp->sc, sp->sv, sp->si);
    gather_k<<<dim3(kKP, kB), kD>>>(sp->x, sp->sv, sp->si, sp->xp);

    // transformer attention (fused QKV projection)
    int Mp = kB * kKP;
    gemm(false, sp->xp, kD, 0, 0, sp->pTw, 768, 0, 0, sp->qkvp, 768, 0, 0,
         nullptr, 0, nullptr, nullptr, Mp, 768, kD, 1, 1, 1.f, 0);
    long pb = (long)kKP * kD;
    long pq = (long)kKP * 768;
    long sb = (long)kH * kKP * kKP;
    gemm(true, sp->qkvp, 768, pq, kDH, sp->qkvp + 256, 768, pq, kDH,
         sp->S, kKP, sb, (long)kKP * kKP, nullptr, 0, nullptr, nullptr,
         kKP, kKP, kDH, kB, kH, 0.125f, 0);
    softmax_k<<<kB * kH * kKP, 256>>>(sp->S);
    gemm(false, sp->S, kKP, sb, (long)kKP * kKP, sp->qkvp + 512, 768, pq, kDH,
         sp->oh, kD, pb, kDH, nullptr, 0, nullptr, nullptr,
         kKP, kDH, kKP, kB, kH, 1.f, 0);
    gemm(false, sp->oh, kD, 0, 0, tWo, kD, 0, 0, sp->yb, kD, 0, 0,
         sp->xp, kD, nullptr, nullptr, Mp, kD, kD, 1, 1, 1.f, 2);
    ln_k<<<Mp, kD>>>(sp->yb, lng, lnb, sp->ga);
    featsum_part_k<<<dim3(kB, 6), 256>>>(sp->xp, sp->ga, sp->up);
    featsum_red_k<<<kB, 512>>>(sp->up, sp->u + (long)branch * kB * 512);
}

extern "C" void kernel_launch(void* const* d_in, const int* in_sizes, int n_in,
                              void* d_out, int out_size) {
    Scratch* sp = nullptr;
    cudaGetSymbolAddress((void**)&sp, SC);

    const float* Wk    = (const float*)d_in[12];
    const float* Wq    = (const float*)d_in[13];
    const float* Wv    = (const float*)d_in[14];
    const float* Wo    = (const float*)d_in[15];
    const float* arel  = (const float*)d_in[16];
    const float* mrel  = (const float*)d_in[17];
    const float* prel  = (const float*)d_in[18];
    const float* skip  = (const float*)d_in[19];
    const float* poolW = (const float*)d_in[20];
    const float* poolA = (const float*)d_in[21];
    const float* poolB = (const float*)d_in[22];
    const float* tWq   = (const float*)d_in[23];
    const float* tWk   = (const float*)d_in[24];
    const float* tWv   = (const float*)d_in[25];
    const float* tWo   = (const float*)d_in[26];
    const float* lng   = (const float*)d_in[27];
    const float* lnb   = (const float*)d_in[28];

    pack_hgt_w_k<<<(int)((8L * 256 * 768 + 255) / 256), 256>>>(Wk, Wq, Wv, sp->pW);
    pack_trans_w_k<<<(256 * 768 + 255) / 256, 256>>>(tWq, tWk, tWv, sp->pTw);
    pack_rel_k<<<(int)((4L * 8 * 4 * 4096 + 255) / 256), 256>>>(arel, mrel, sp->pRel);

    for (int g = 0; g < 2; g++) {
        int base = g * 6;
        run_branch(sp,
                   (const float*)d_in[base + 0], (const float*)d_in[base + 1],
                   (const int*)d_in[base + 2], (const int*)d_in[base + 3],
                   (const int*)d_in[base + 4], (const int*)d_in[base + 5],
                   Wo, prel, skip, poolW, poolA, poolB,
                   tWo, lng, lnb, g);
    }
    cos_k<<<kB, 512>>>(sp->u, (float*)d_out);
}

// round 12
// speedup vs baseline: 4.3441x; 1.0770x over previous
#include <cuda_runtime.h>
#include <cuda_bf16.h>
#include <math.h>
#include <stdint.h>

// ------------------------- problem constants -------------------------
constexpr int kNI = 8192, kND = 4096, kNT = 12288, kD = 256, kH = 4, kDH = 64;
constexpr int kB = 8, kKP = 768;
constexpr int kEC = 65536, kEI = 32768, kEO = 32768, kEK = 8192;
constexpr long LXD = (long)kNT * kD;
constexpr long LPD = (long)kB * kKP * kD;
constexpr long KRVB = 8L * kNI * 256;          // bf16 elems per branch (K rels 0-3, V rels 4-7)

// counter-region offsets (5 CSRs share one cnt/cur buffer)
constexpr int O0 = 0;
constexpr int O1 = kNI;
constexpr int O2 = kNI + kND;
constexpr int O3 = 2 * kNI + kND;
constexpr int O4 = 2 * kNI + 2 * kND;
constexpr int CNT_TOT = O4 + kNT;

// fused edge-slot boundaries
constexpr int BB0 = kEC;
constexpr int BB1 = BB0 + kEI;
constexpr int BB2 = BB1 + kEK;
constexpr int BB3 = BB2 + kEO;
constexpr int BB4 = BB3 + kEC;
constexpr int BB5 = BB4 + kEO;
constexpr int BB6 = BB5 + kEK;
constexpr int BB7 = BB6 + kEI;
constexpr int BB8 = BB7 + kEC;
constexpr int BB9 = BB8 + kEI;
constexpr int BB10 = BB9 + kEO;
constexpr int BB11 = BB10 + kEK;
constexpr int BB12 = BB11 + kNT;

// ------------------------- scratch -------------------------
struct Scratch {
    float x[2][LXD], yF[2][LXD], agg[2][LXD];
    float kqv[2][3 * LXD];                    // [branch][node][768] K|Q|V
    float S[2][(long)kB * kH * kKP * kKP];
    float xp[2][LPD], qkvp[2][3 * LPD], oh[2][LPD], yb[2][LPD], ga[2][LPD];
    float pW[8L * 256 * 768];
    float pTw[256 * 768];
    float pRel[4L * 8 * 4 * 64 * 64];         // [combo][relslot(K0-3,V0-3)][h][64][64]
    float hv[2 * kNT], sc[2 * kNT];
    float sv[2 * kB * kKP];
    int   si[2 * kB * kKP];
    float u[2 * kB * 512];
    float up[2 * kB * 6 * 512];
    int rpf0[2][kNI + 1], rpf1[2][kND + 1], rpr0[2][kNI + 1], rpr1[2][kND + 1], rph[2][kNT + 1];
    int ef0[2][kEC + kEI + kEK], ef1[2][kEO], er0[2][kEC + kEO + kEK], er1[2][kEI];
    int eh[2][kEC + kEI + kEO + kEK + kNT];
    int cnt[CNT_TOT], cur[CNT_TOT];
    __nv_bfloat16 krv[2][KRVB];               // Krel/Vrel in bf16 (4B-aligned by layout)
};
__device__ Scratch SC;

// ------------------------- reductions -------------------------
__device__ __forceinline__ float wsum(float v) {
#pragma unroll
    for (int o = 16; o; o >>= 1) v += __shfl_xor_sync(0xffffffffu, v, o);
    return v;
}
__device__ __forceinline__ float bsum(float v) {
    __shared__ float sh[32];
    int lane = threadIdx.x & 31, w = threadIdx.x >> 5;
    v = wsum(v);
    if (!lane) sh[w] = v;
    __syncthreads();
    int nw = blockDim.x >> 5;
    float s = (threadIdx.x < nw) ? sh[threadIdx.x] : 0.f;
    if (w == 0) s = wsum(s);
    if (threadIdx.x == 0) sh[0] = s;
    __syncthreads();
    float r = sh[0];
    __syncthreads();
    return r;
}
__device__ __forceinline__ float bmax(float v) {
    __shared__ float sh[32];
    int lane = threadIdx.x & 31, w = threadIdx.x >> 5;
#pragma unroll
    for (int o = 16; o; o >>= 1) v = fmaxf(v, __shfl_xor_sync(0xffffffffu, v, o));
    if (!lane) sh[w] = v;
    __syncthreads();
    int nw = blockDim.x >> 5;
    float s = (threadIdx.x < nw) ? sh[threadIdx.x] : -INFINITY;
    if (w == 0)
#pragma unroll
        for (int o = 16; o; o >>= 1) s = fmaxf(s, __shfl_xor_sync(0xffffffffu, s, o));
    if (threadIdx.x == 0) sh[0] = s;
    __syncthreads();
    float r = sh[0];
    __syncthreads();
    return r;
}

// ------------------------- tf32 tensor-core GEMM (cp.async pipelined) --------
__device__ __forceinline__ void mma_tf32(float* c, const uint32_t* a,
                                         uint32_t b0, uint32_t b1) {
    asm volatile(
        "mma.sync.aligned.m16n8k8.row.col.f32.tf32.tf32.f32 "
        "{%0,%1,%2,%3}, {%4,%5,%6,%7}, {%8,%9}, {%0,%1,%2,%3};"
        : "+f"(c[0]), "+f"(c[1]), "+f"(c[2]), "+f"(c[3])
        : "r"(a[0]), "r"(a[1]), "r"(a[2]), "r"(a[3]), "r"(b0), "r"(b1));
}
__device__ __forceinline__ void cpa16(float* dst, const float* src) {
    unsigned d = (unsigned)__cvta_generic_to_shared(dst);
    asm volatile("cp.async.cg.shared.global [%0], [%1], 16;\n" :: "r"(d), "l"(src));
}
#define CP_COMMIT() asm volatile("cp.async.commit_group;\n" ::: "memory")
#define CP_WAIT1()  asm volatile("cp.async.wait_group 1;\n" ::: "memory")
#define CP_WAIT0()  asm volatile("cp.async.wait_group 0;\n" ::: "memory")

// C = epilogue(alpha * A @ B(^T)); blockIdx.z -> (z2 = z/ZT, zb = (z%ZT)/ZH, zh = z%ZH).
// A offset: z2*A2 + zb*Ab + zh*Ah (+Aalt if zmask bit zb; +Valt if zb>=zsplit).
// B offset: z2*B2 + zb*Bb + zh*Bh.  C/Add/Add2 offset: z2*C2 + zb*Cb + zh*Ch.
// If zmask bit zb set, M = Malt. Gate g = sigmoid(gptr[zb]).
// mode 0: C=v | 1: C=g*v+(1-g)*Add | 2: C=v+Add | 3: C=relu(.5*(g*v+(1-g)*Add)+.5*Add2)
// mode 5: C=v stored as bf16 (C strides in bf16 elements)
template <int BN, bool TB>
__global__ void __launch_bounds__(256, 2) tgemm_k(
    const float* __restrict__ A, int lda, long A2, long Ab, long Ah,
    const float* __restrict__ Bm, int ldb, long B2, long Bb, long Bh,
    void* __restrict__ Cv, int ldc, long C2, long Cb, long Ch,
    const float* __restrict__ Add, int ldadd, const float* __restrict__ Add2,
    const float* __restrict__ gptr,
    int Kdim, int ZH, int ZT, float alpha, int mode,
    unsigned zmask, long Aalt, int Malt, int Mdef, long Valt, int zsplit)
{
    constexpr int BM = 128, BK = 32;
    constexpr int ASTR = 44;
    constexpr int BROWS = TB ? BN : BK;
    constexpr int BSTR = TB ? 44 : (BN + 8);
    constexpr int TN = (BN == 128) ? 8 : 4;
    extern __shared__ float sm_[];
    float* As = sm_;
    float* Bs = sm_ + 2 * BM * ASTR;

    int z = blockIdx.z;
    int z2 = z / ZT, rz = z - z2 * ZT;
    int zb = rz / ZH, zh = rz - zb * ZH;
    int msk = (zmask >> zb) & 1;
    int Mz = msk ? Malt : Mdef;
    int m0 = blockIdx.x * BM;
    if (m0 >= Mz) return;
    const float* Ax = A + z2 * A2 + zb * Ab + zh * Ah + (msk ? Aalt : 0)
                        + (zb >= zsplit ? Valt : 0);
    const float* Bx = Bm + z2 * B2 + zb * Bb + zh * Bh;
    long coff = z2 * C2 + zb * Cb + zh * Ch;
    if (Add)  Add  += coff;
    if (Add2) Add2 += coff;
    int n0 = blockIdx.y * BN;
    int tid = threadIdx.x, lane = tid & 31, warp = tid >> 5;
    int wm = warp >> 1, wn = warp & 1;
    int g = lane >> 2, tg = lane & 3;

    float acc[2][TN][4];
#pragma unroll
    for (int i = 0; i < 2; i++)
#pragma unroll
        for (int j = 0; j < TN; j++)
#pragma unroll
            for (int q = 0; q < 4; q++) acc[i][j][q] = 0.f;

    int nt = Kdim / BK;

#define ISSUE(K0, S) do {                                                      \
        float* Ad = As + (S) * BM * ASTR;                                      \
        _Pragma("unroll")                                                      \
        for (int q = 0; q < 4; q++) {                                          \
            int f = tid + q * 256, row = f >> 3, kc = (f & 7) * 4;             \
            cpa16(Ad + row * ASTR + kc,                                        \
                  Ax + (long)(m0 + row) * lda + (K0) + kc);                    \
        }                                                                      \
        float* Bd = Bs + (S) * BROWS * BSTR;                                   \
        _Pragma("unroll")                                                      \
        for (int q = 0; q < BN / 32; q++) {                                    \
            int f = tid + q * 256;                                             \
            if (TB) {                                                          \
                int rr = f >> 3, rc = (f & 7) * 4;                             \
                cpa16(Bd + rr * BSTR + rc,                                     \
                      Bx + (long)(n0 + rr) * ldb + (K0) + rc);                 \
            } else {                                                           \
                int rr = f / (BN / 4), rc = (f % (BN / 4)) * 4;                \
                cpa16(Bd + rr * BSTR + rc,                                     \
                      Bx + (long)((K0) + rr) * ldb + n0 + rc);                 \
            }                                                                  \
        }                                                                      \
    } while (0)

    ISSUE(0, 0);
    CP_COMMIT();

    for (int t = 0; t < nt; t++) {
        if (t + 1 < nt) {
            ISSUE((t + 1) * BK, (t + 1) & 1);
            CP_COMMIT();
            CP_WAIT1();
        } else {
            CP_WAIT0();
        }
        __syncthreads();
        const float* Ap = As + (size_t)(t & 1) * BM * ASTR;
        const float* Bp = Bs + (size_t)(t & 1) * BROWS * BSTR;
#pragma unroll
        for (int k8 = 0; k8 < 4; k8++) {
            int kb = k8 * 8;
            uint32_t a[2][4];
#pragma unroll
            for (int tm = 0; tm < 2; tm++) {
                int mr = wm * 32 + tm * 16;
                a[tm][0] = __float_as_uint(Ap[(mr + g) * ASTR + kb + tg]);
                a[tm][1] = __float_as_uint(Ap[(mr + 8 + g) * ASTR + kb + tg]);
                a[tm][2] = __float_as_uint(Ap[(mr + g) * ASTR + kb + tg + 4]);
                a[tm][3] = __float_as_uint(Ap[(mr + 8 + g) * ASTR + kb + tg + 4]);
            }
#pragma unroll
            for (int tn = 0; tn < TN; tn++) {
                int nc = wn * (TN * 8) + tn * 8 + g;
                uint32_t b0, b1;
                if (TB) {
                    b0 = __float_as_uint(Bp[nc * BSTR + kb + tg]);
                    b1 = __float_as_uint(Bp[nc * BSTR + kb + tg + 4]);
                } else {
                    b0 = __float_as_uint(Bp[(kb + tg) * BSTR + nc]);
                    b1 = __float_as_uint(Bp[(kb + tg + 4) * BSTR + nc]);
                }
#pragma unroll
                for (int tm = 0; tm < 2; tm++)
                    mma_tf32(acc[tm][tn], a[tm], b0, b1);
            }
        }
        __syncthreads();
    }
#undef ISSUE

    float gg = 1.f;
    if (mode == 1 || mode == 3) gg = 1.f / (1.f + expf(-gptr[zb]));
    float* Cf = (float*)Cv + coff;
    __nv_bfloat16* Ch16 = (__nv_bfloat16*)Cv + coff;
#pragma unroll
    for (int tm = 0; tm < 2; tm++) {
        long row0 = m0 + wm * 32 + tm * 16 + g;
#pragma unroll
        for (int tn = 0; tn < TN; tn++) {
            long col = n0 + wn * (TN * 8) + tn * 8 + tg * 2;
#pragma unroll
            for (int half = 0; half < 2; half++) {
                long r = row0 + half * 8;
                float vx = alpha * acc[tm][tn][half * 2 + 0];
                float vy = alpha * acc[tm][tn][half * 2 + 1];
                if (mode == 1) {
                    float2 ad = *(const float2*)(Add + r * ldadd + col);
                    vx = gg * vx + (1.f - gg) * ad.x;
                    vy = gg * vy + (1.f - gg) * ad.y;
                } else if (mode == 2) {
                    float2 ad = *(const float2*)(Add + r * ldadd + col);
                    vx += ad.x; vy += ad.y;
                } else if (mode == 3) {
                    float2 ad = *(const float2*)(Add + r * ldadd + col);
                    float2 a2 = *(const float2*)(Add2 + r * ldadd + col);
                    vx = 0.5f * (gg * vx + (1.f - gg) * ad.x) + 0.5f * a2.x;
                    vy = 0.5f * (gg * vy + (1.f - gg) * ad.y) + 0.5f * a2.y;
                    vx = vx > 0.f ? vx : 0.f;
                    vy = vy > 0.f ? vy : 0.f;
                }
                if (mode == 5) {
                    __nv_bfloat162 h2 = __floats2bfloat162_rn(vx, vy);
                    *(__nv_bfloat162*)(Ch16 + r * ldc + col) = h2;
                } else {
                    float2 o; o.x = vx; o.y = vy;
                    *(float2*)(Cf + r * ldc + col) = o;
                }
            }
        }
    }
}

// ------------------------- fused weight packing -------------------------
constexpr long PN1 = 8L * 256 * 768;
constexpr long PN2 = 256L * 768;
constexpr long PN3 = 4L * 8 * 4 * 4096;
__global__ void pack_all_k(const float* __restrict__ Wk, const float* __restrict__ Wq,
                           const float* __restrict__ Wv, const float* __restrict__ tWq,
                           const float* __restrict__ tWk, const float* __restrict__ tWv,
                           const float* __restrict__ arel, const float* __restrict__ mrel,
                           Scratch* sp) {
    long i = (long)blockIdx.x * 256 + threadIdx.x;
    if (i < PN1) {
        int n = (int)(i % 768);
        long rem = i / 768;
        int k = (int)(rem % 256);
        int c = (int)(rem / 256);
        int sel = n >> 8, nn = n & 255;
        const float* W = (sel == 0) ? Wk : (sel == 1) ? Wq : Wv;
        sp->pW[(long)c * 196608 + (long)k * 768 + n] =
            W[(long)c * 65536 + (long)k * 256 + nn];
    } else if (i < PN1 + PN2) {
        long j = i - PN1;
        int n = (int)(j % 768), k = (int)(j / 768);
        int sel = n >> 8, nn = n & 255;
        const float* W = (sel == 0) ? tWq : (sel == 1) ? tWk : tWv;
        sp->pTw[(long)k * 768 + n] = W[(long)k * 256 + nn];
    } else if (i < PN1 + PN2 + PN3) {
        long j = i - PN1 - PN2;
        int n  = (int)(j & 4095);
        int hh = (int)((j >> 12) & 3);
        int zr = (int)((j >> 14) & 7);
        int c  = (int)(j >> 17);
        const float* src = (zr < 4) ? arel : mrel;
        int r = zr & 3;
        sp->pRel[j] = src[(((long)(c * 4 + r) * 4 + hh) << 12) + n];
    }
}

// ------------------------- elementwise -------------------------
__global__ void assemble_x_k(const float* __restrict__ xi0, const float* __restrict__ xd0,
                             const float* __restrict__ xi1, const float* __restrict__ xd1,
                             Scratch* sp) {
    long i = ((long)blockIdx.x * blockDim.x + threadIdx.x) * 4;
    if (i < 2 * LXD) {
        const long T1 = (long)kNI * kD;
        int br = i >= LXD;
        long loc = i - (long)br * LXD;
        const float* xi = br ? xi1 : xi0;
        const float* xd = br ? xd1 : xd0;
        float4 v = (loc < T1) ? *(const float4*)(xi + loc) : *(const float4*)(xd + (loc - T1));
        *(float4*)(&sp->x[0][0] + i) = v;
    }
}

// ------------------------- fused CSR construction -------------------------
struct Slot { int idx; int ent; int arr; };
__device__ __forceinline__ Slot decode_slot(
    int i, const int* rc, const int* cc, const int* ri, const int* ci,
    const int* ro, const int* co, const int* rk, const int* ck)
{
    Slot s;
    if (i < BB0)       { s.idx = O0 + cc[i];            s.ent = (0 << 16) | rc[i];            s.arr = 0; }
    else if (i < BB1)  { int j = i - BB0;  s.idx = O0 + ci[j]; s.ent = (1 << 16) | ri[j];     s.arr = 0; }
    else if (i < BB2)  { int j = i - BB1;  s.idx = O0 + ck[j]; s.ent = (3 << 16) | rk[j];     s.arr = 0; }
    else if (i < BB3)  { int j = i - BB2;  s.idx = O1 + co[j]; s.ent = (2 << 16) | ro[j];     s.arr = 1; }
    else if (i < BB4)  { int j = i - BB3;  s.idx = O2 + rc[j]; s.ent = (0 << 16) | cc[j];     s.arr = 2; }
    else if (i < BB5)  { int j = i - BB4;  s.idx = O2 + ro[j]; s.ent = (2 << 16) | co[j];     s.arr = 2; }
    else if (i < BB6)  { int j = i - BB5;  s.idx = O2 + rk[j]; s.ent = (3 << 16) | ck[j];     s.arr = 2; }
    else if (i < BB7)  { int j = i - BB6;  s.idx = O3 + ri[j]; s.ent = (1 << 16) | ci[j];     s.arr = 3; }
    else if (i < BB8)  { int j = i - BB7;  s.idx = O4 + cc[j]; s.ent = rc[j];                 s.arr = 4; }
    else if (i < BB9)  { int j = i - BB8;  s.idx = O4 + ci[j]; s.ent = ri[j] + kNI;           s.arr = 4; }
    else if (i < BB10) { int j = i - BB9;  s.idx = O4 + co[j] + kNI; s.ent = ro[j];           s.arr = 4; }
    else               { int j = i - BB10; s.idx = O4 + ck[j]; s.ent = rk[j];                 s.arr = 4; }
    return s;
}

__global__ void csr_count_k(Scratch* sp, const int* rc, const int* cc,
                            const int* ri, const int* ci, const int* ro, const int* co,
                            const int* rk, const int* ck) {
    int i = blockIdx.x * blockDim.x + threadIdx.x;
    if (i < BB11) {
        Slot s = decode_slot(i, rc, cc, ri, ci, ro, co, rk, ck);
        atomicAdd(&sp->cnt[s.idx], 1);
    }
}
__global__ void csr_scan_k(Scratch* sp, int br) {
    __shared__ int sh[1024];
    int region = blockIdx.x, t = threadIdx.x;
    int off, n, extra = 0;
    int* rp;
    switch (region) {
        case 0: off = O0; n = kNI; rp = sp->rpf0[br]; break;
        case 1: off = O1; n = kND; rp = sp->rpf1[br]; break;
        case 2: off = O2; n = kNI; rp = sp->rpr0[br]; break;
        case 3: off = O3; n = kND; rp = sp->rpr1[br]; break;
        default: off = O4; n = kNT; rp = sp->rph[br]; extra = 1; break;
    }
    int c = (n + 1023) >> 10;
    int beg = t * c, end = min(beg + c, n);
    int s = 0;
    for (int i = beg; i < end; i++) s += sp->cnt[off + i] + extra;
    sh[t] = s;
    __syncthreads();
    for (int o = 1; o < 1024; o <<= 1) {
        int v = (t >= o) ? sh[t - o] : 0;
        __syncthreads();
        sh[t] += v;
        __syncthreads();
    }
    int run = t ? sh[t - 1] : 0;
    for (int i = beg; i < end; i++) {
        int cv = sp->cnt[off + i];
        sp->cnt[off + i] = 0;
        rp[i] = run;
        sp->cur[off + i] = run;
        run += cv + extra;
    }
    if (t == 1023) rp[n] = sh[1023];
}
__global__ void csr_fill_k(Scratch* sp, int br, const int* rc, const int* cc,
                           const int* ri, const int* ci, const int* ro, const int* co,
                           const int* rk, const int* ck) {
    int i = blockIdx.x * blockDim.x + threadIdx.x;
    if (i >= BB12) return;
    if (i < BB11) {
        Slot s = decode_slot(i, rc, cc, ri, ci, ro, co, rk, ck);
        int pos = atomicAdd(&sp->cur[s.idx], 1);
        switch (s.arr) {
            case 0: sp->ef0[br][pos] = s.ent; break;
            case 1: sp->ef1[br][pos] = s.ent; break;
            case 2: sp->er0[br][pos] = s.ent; break;
            case 3: sp->er1[br][pos] = s.ent; break;
            default: sp->eh[br][pos] = s.ent; break;
        }
    } else {
        int node = i - BB11;
        int pos = atomicAdd(&sp->cur[O4 + node], 1);
        sp->eh[br][pos] = node;
    }
}

// ------------------- HGT softmax aggregation (merged branches, bf16 KV) -------------
__global__ void hgt_agg_k(Scratch* sp, int dir, const float* __restrict__ prel) {
    int nb = blockIdx.x;                     // 0..2*kNT-1
    int branch = nb >= kNT;
    int node = nb - branch * kNT;
    const int *rp, *ent; int idx;
    if (dir == 0) {
        if (node < kNI) { rp = sp->rpf0[branch]; ent = sp->ef0[branch]; idx = node; }
        else            { rp = sp->rpf1[branch]; ent = sp->ef1[branch]; idx = node - kNI; }
    } else {
        if (node < kNI) { rp = sp->rpr0[branch]; ent = sp->er0[branch]; idx = node; }
        else            { rp = sp->rpr1[branch]; ent = sp->er1[branch]; idx = node - kNI; }
    }
    int h = threadIdx.x >> 5, lane = threadIdx.x & 31;
    const float* q = sp->kqv[branch] + (long)node * 768 + 256 + h * 64 + 2 * lane;
    float q0 = q[0], q1 = q[1];
    const __nv_bfloat16* krv = sp->krv[branch];
    float pr0 = prel[0 * kH + h], pr1 = prel[1 * kH + h];
    float pr2 = prel[2 * kH + h], pr3 = prel[3 * kH + h];
    int s = rp[idx], eend = rp[idx + 1];
    float m = -INFINITY, den = 0.f, a0 = 0.f, a1 = 0.f;
    long hoff = h * 64 + 2 * lane;
    int e = s;
    for (; e + 1 < eend; e += 2) {
        int pkA = ent[e], pkB = ent[e + 1];
        int rA = pkA >> 16, sA = pkA & 0xffff;
        int rB = pkB >> 16, sB = pkB & 0xffff;
        float2 kA = __bfloat1622float2(
            *(const __nv_bfloat162*)(krv + ((long)rA * kNI + sA) * 256 + hoff));
        float2 kB2 = __bfloat1622float2(
            *(const __nv_bfloat162*)(krv + ((long)rB * kNI + sB) * 256 + hoff));
        float2 vA = __bfloat1622float2(
            *(const __nv_bfloat162*)(krv + ((long)(rA + 4) * kNI + sA) * 256 + hoff));
        float2 vB = __bfloat1622float2(
            *(const __nv_bfloat162*)(krv + ((long)(rB + 4) * kNI + sB) * 256 + hoff));
        float dA = q0 * kA.x + q1 * kA.y;
        float dB = q0 * kB2.x + q1 * kB2.y;
#pragma unroll
        for (int o = 16; o; o >>= 1) {
            dA += __shfl_xor_sync(0xffffffffu, dA, o);
            dB += __shfl_xor_sync(0xffffffffu, dB, o);
        }
        float prA = (rA == 0) ? pr0 : (rA == 1) ? pr1 : (rA == 2) ? pr2 : pr3;
        float prB = (rB == 0) ? pr0 : (rB == 1) ? pr1 : (rB == 2) ? pr2 : pr3;
        float scA = dA * prA * 0.125f, scB = dB * prB * 0.125f;
        float mn = fmaxf(m, fmaxf(scA, scB));
        float cc = expf(m - mn), wA = expf(scA - mn), wB = expf(scB - mn);
        den = den * cc + wA + wB;
        a0 = a0 * cc + wA * vA.x + wB * vB.x;
        a1 = a1 * cc + wA * vA.y + wB * vB.y;
        m = mn;
    }
    if (e < eend) {
        int pk = ent[e];
        int r = pk >> 16, src = pk & 0xffff;
        float2 kk = __bfloat1622float2(
            *(const __nv_bfloat162*)(krv + ((long)r * kNI + src) * 256 + hoff));
        float2 vv = __bfloat1622float2(
            *(const __nv_bfloat162*)(krv + ((long)(r + 4) * kNI + src) * 256 + hoff));
        float d0 = q0 * kk.x + q1 * kk.y;
        d0 = wsum(d0);
        float pr = (r == 0) ? pr0 : (r == 1) ? pr1 : (r == 2) ? pr2 : pr3;
        float sc2 = d0 * pr * 0.125f;
        float mn = fmaxf(m, sc2);
        float cc = expf(m - mn), w = expf(sc2 - mn);
        den = den * cc + w;
        a0 = a0 * cc + w * vv.x;
        a1 = a1 * cc + w * vv.y;
        m = mn;
    }
    float inv = 1.f / (den + 1e-16f);
    float r0 = a0 * inv, r1 = a1 * inv;
    float2 o;
    o.x = 0.5f * r0 * (1.f + erff(r0 * 0.7071067811865475f));
    o.y = 0.5f * r1 * (1.f + erff(r1 * 0.7071067811865475f));
    *(float2*)(sp->agg[branch] + (long)node * kD + hoff) = o;
}

// ------------------------- pooling -------------------------
__global__ void hv_k(Scratch* sp, const float* __restrict__ pw) {
    int nb = blockIdx.x * 8 + (threadIdx.x >> 5);
    int lane = threadIdx.x & 31;
    if (nb >= 2 * kNT) return;
    const float* x = &sp->x[0][0];
    float s = 0.f;
    for (int d = lane; d < kD; d += 32) s += x[(long)nb * kD + d] * pw[d];
    s = wsum(s);
    if (!lane) sp->hv[nb] = s;
}
__global__ void gat_score_k(Scratch* sp, const float* __restrict__ att,
                            const float* __restrict__ bias) {
    int i = blockIdx.x * blockDim.x + threadIdx.x;
    if (i >= 2 * kNT) return;
    int branch = i / kNT, ii = i - branch * kNT;
    const int* rp = sp->rph[branch];
    const int* ent = sp->eh[branch];
    float A0 = att[0], A1 = att[1];
    float hi = sp->hv[i];
    int s = rp[ii], e1 = rp[ii + 1];
    float m = -INFINITY, den = 0.f, acc = 0.f;
    int hb = branch * kNT;
    for (int e = s; e < e1; e++) {
        int src = ent[e] & 0xffff;
        float hs = sp->hv[hb + src];
        float ee = A0 * hs + A1 * hi;
        ee = ee >= 0.f ? ee : 0.2f * ee;
        float mn = fmaxf(m, ee);
        float c = expf(m - mn), w = expf(ee - mn);
        den = den * c + w;
        acc = acc * c + w * hs;
        m = mn;
    }
    sp->sc[i] = acc / (den + 1e-16f) + bias[0];
}

__global__ void topk_sort_k(Scratch* sp) {
    int bi = blockIdx.x;                     // 0..15
    int branch = bi >> 3, b = bi & 7;
    int t = threadIdx.x;
    const float* sc = sp->sc + branch * kNT;
    __shared__ float v[2048];
    __shared__ int ix[2048];
    for (int p = t; p < 2048; p += 1024) {
        float val = -INFINITY;
        if (p < 1536) {
            int node = p < 1024 ? b * 1024 + p : kNI + b * 512 + (p - 1024);
            val = sc[node];
        }
        v[p] = val;
        ix[p] = p;
    }
    __syncthreads();
    for (int k = 2; k <= 2048; k <<= 1)
        for (int j = k >> 1; j > 0; j >>= 1) {
#pragma unroll
            for (int pass = 0; pass < 2; pass++) {
                int i = t + pass * 1024;
                int l = i ^ j;
                if (l > i) {
                    bool up = ((i & k) == 0);
                    float vi = v[i], vl = v[l];
                    int ii = ix[i], il = ix[l];
                    bool before = (vi > vl) || (vi == vl && ii < il);
                    if (up != before) {
                        v[i] = vl; v[l] = vi;
                        ix[i] = il; ix[l] = ii;
                    }
                }
            }
            __syncthreads();
        }
    if (t < kKP) {
        sp->sv[bi * kKP + t] = v[t];
        sp->si[bi * kKP + t] = ix[t];
    }
}
__global__ void gather_k(Scratch* sp) {
    int q = blockIdx.x, bi = blockIdx.y, d = threadIdx.x;
    int branch = bi >> 3, b = bi & 7;
    int j = sp->si[bi * kKP + q];
    float tv = tanhf(sp->sv[bi * kKP + q]);
    int node = j < 1024 ? b * 1024 + j : kNI + b * 512 + (j - 1024);
    sp->xp[branch][((long)(b * kKP + q)) * kD + d] =
        sp->x[branch][(long)node * kD + d] * tv;
}

// ------------------------- transformer pieces -------------------------
__global__ void softmax_k(float* __restrict__ S) {
    long row = blockIdx.x;
    float* p = S + row * kKP;
    int t = threadIdx.x;
    float v0 = p[t], v1 = p[t + 256], v2 = p[t + 512];
    float m = bmax(fmaxf(v0, fmaxf(v1, v2)));
    v0 = expf(v0 - m); v1 = expf(v1 - m); v2 = expf(v2 - m);
    float s = bsum(v0 + v1 + v2);
    float inv = 1.f / s;
    p[t] = v0 * inv; p[t + 256] = v1 * inv; p[t + 512] = v2 * inv;
}
__global__ void ln_k(const float* __restrict__ y, const float* __restrict__ g,
                     const float* __restrict__ bta, float* __restrict__ out) {
    long row = blockIdx.x;
    int d = threadIdx.x;
    float v = y[row * kD + d];
    float mu = bsum(v) * (1.f / kD);
    float df = v - mu;
    float var = bsum(df * df) * (1.f / kD);
    out[row * kD + d] = g[d] * df * rsqrtf(var + 1e-5f) + bta[d];
}
__global__ void featsum_part_k(Scratch* sp) {
    int bi = blockIdx.x, ch = blockIdx.y, d = threadIdx.x;   // bi 0..15
    int branch = bi >> 3, b = bi & 7;
    const float* xp = sp->xp[branch];
    const float* ga = sp->ga[branch];
    float s1 = 0.f, s2 = 0.f;
    int q0 = ch * 128;
    for (int q = q0; q < q0 + 128; q++) {
        long o = ((long)(b * kKP + q)) * kD + d;
        s1 += xp[o];
        s2 += ga[o];
    }
    sp->up[(bi * 6 + ch) * 512 + d] = s1;
    sp->up[(bi * 6 + ch) * 512 + 256 + d] = s2;
}
__global__ void featsum_red_k(Scratch* sp) {
    int bi = blockIdx.x, d = threadIdx.x;    // bi 0..15, 512 threads
    float s = 0.f;
    for (int ch = 0; ch < 6; ch++) s += sp->up[(bi * 6 + ch) * 512 + d];
    sp->u[bi * 512 + d] = s;
}
__global__ void cos_k(const float* __restrict__ u, float* __restrict__ out) {
    int b = blockIdx.x, t = threadIdx.x;
    float a = u[b * 512 + t];
    float c = u[(kB + b) * 512 + t];
    float dot = bsum(a * c);
    float na = bsum(a * a);
    float nc = bsum(c * c);
    if (t == 0)
        out[b] = dot / (fmaxf(sqrtf(na), 1e-8f) * fmaxf(sqrtf(nc), 1e-8f));
}

// ------------------------- host orchestration -------------------------
static inline int gemm_smem(bool tb, int BN) {
    int a = 2 * 128 * 44;
    int b = tb ? 2 * BN * 44 : 2 * 32 * (BN + 8);
    return (a + b) * 4;
}
static void gemm(bool tb, const float* A, int lda, long A2, long Ab, long Ah,
                 const float* Bm, int ldb, long B2, long Bb, long Bh,
                 void* C, int ldc, long C2, long Cb, long Ch,
                 const float* Add, int ldadd, const float* Add2, const float* gptr,
                 int M, int N, int K, int ZC, int ZB, int ZH, float alpha, int mode,
                 unsigned zmask = 0, long Aalt = 0, int Malt = 0,
                 long Valt = 0, int zsplit = 1 << 30) {
    int ZT = ZB * ZH;
    if (N % 128 == 0) {
        int sm = gemm_smem(tb, 128);
        dim3 g(M / 128, N / 128, ZC * ZT), blk(256);
        if (tb) {
            cudaFuncSetAttribute(tgemm_k<128, true>,
                                 cudaFuncAttributeMaxDynamicSharedMemorySize, sm);
            tgemm_k<128, true><<<g, blk, sm>>>(A, lda, A2, Ab, Ah, Bm, ldb, B2, Bb, Bh,
                                               C, ldc, C2, Cb, Ch, Add, ldadd, Add2, gptr,
                                               K, ZH, ZT, alpha, mode,
                                               zmask, Aalt, Malt, M, Valt, zsplit);
        } else {
            cudaFuncSetAttribute(tgemm_k<128, false>,
                                 cudaFuncAttributeMaxDynamicSharedMemorySize, sm);
            tgemm_k<128, false><<<g, blk, sm>>>(A, lda, A2, Ab, Ah, Bm, ldb, B2, Bb, Bh,
                                                C, ldc, C2, Cb, Ch, Add, ldadd, Add2, gptr,
                                                K, ZH, ZT, alpha, mode,
                                                zmask, Aalt, Malt, M, Valt, zsplit);
        }
    } else {
        int sm = gemm_smem(tb, 64);
        dim3 g(M / 128, N / 64, ZC * ZT), blk(256);
        if (tb) {
            cudaFuncSetAttribute(tgemm_k<64, true>,
                                 cudaFuncAttributeMaxDynamicSharedMemorySize, sm);
            tgemm_k<64, true><<<g, blk, sm>>>(A, lda, A2, Ab, Ah, Bm, ldb, B2, Bb, Bh,
                                              C, ldc, C2, Cb, Ch, Add, ldadd, Add2, gptr,
                                              K, ZH, ZT, alpha, mode,
                                              zmask, Aalt, Malt, M, Valt, zsplit);
        } else {
            cudaFuncSetAttribute(tgemm_k<64, false>,
                                 cudaFuncAttributeMaxDynamicSharedMemorySize, sm);
            tgemm_k<64, false><<<g, blk, sm>>>(A, lda, A2, Ab, Ah, Bm, ldb, B2, Bb, Bh,
                                               C, ldc, C2, Cb, Ch, Add, ldadd, Add2, gptr,
                                               K, ZH, ZT, alpha, mode,
                                               zmask, Aalt, Malt, M, Valt, zsplit);
        }
    }
}

extern "C" void kernel_launch(void* const* d_in, const int* in_sizes, int n_in,
                              void* d_out, int out_size) {
    Scratch* sp = nullptr;
    cudaGetSymbolAddress((void**)&sp, SC);

    const float* Wk    = (const float*)d_in[12];
    const float* Wq    = (const float*)d_in[13];
    const float* Wv    = (const float*)d_in[14];
    const float* Wo    = (const float*)d_in[15];
    const float* arel  = (const float*)d_in[16];
    const float* mrel  = (const float*)d_in[17];
    const float* prel  = (const float*)d_in[18];
    const float* skip  = (const float*)d_in[19];
    const float* poolW = (const float*)d_in[20];
    const float* poolA = (const float*)d_in[21];
    const float* poolB = (const float*)d_in[22];
    const float* tWq   = (const float*)d_in[23];
    const float* tWk   = (const float*)d_in[24];
    const float* tWv   = (const float*)d_in[25];
    const float* tWo   = (const float*)d_in[26];
    const float* lng   = (const float*)d_in[27];
    const float* lnb   = (const float*)d_in[28];

    const long DD = (long)kD * kD;
    const long T1 = (long)kNI * kD;
    const long KQVB = 3 * LXD;

    // 1: packing, 2: assemble (both branches)
    pack_all_k<<<(int)((PN1 + PN2 + PN3 + 255) / 256), 256>>>(
        Wk, Wq, Wv, tWq, tWk, tWv, arel, mrel, sp);
    assemble_x_k<<<(int)(2 * LXD / 4 + 255) / 256, 256>>>(
        (const float*)d_in[0], (const float*)d_in[1],
        (const float*)d_in[6], (const float*)d_in[7], sp);

    bool csr_done = false;

    for (int l = 0; l < 2; l++) {
        for (int dir = 0; dir < 2; dir++) {
            int combo = l * 2 + dir;
            // QKV: z = (branch:2) x (type:2 via zb mask)
            gemm(false, &sp->x[0][0], kD, LXD, 0, 0,
                 sp->pW + (long)(combo * 2) * 196608, 768, 0, 196608, 0,
                 &sp->kqv[0][0], 768, KQVB, (long)kNI * 768, 0,
                 nullptr, 0, nullptr, nullptr,
                 kNI, 768, kD, 2, 2, 1, 1.f, 0,
                 0x2u, T1, kND);
            // Krel+Vrel bf16: z = (branch:2) x (relslot:8) x (head:4)
            unsigned mask = dir ? 0x44u : 0x22u;
            gemm(false, &sp->kqv[0][0], 768, KQVB, 0, 64,
                 sp->pRel + (long)combo * 8 * 4 * 4096, kDH, 0, (long)4 * 4096, 4096,
                 &sp->krv[0][0], 256, KRVB, (long)kNI * 256, 64,
                 nullptr, 0, nullptr, nullptr,
                 kNI, kDH, kDH, 2, 8, kH, 1.f, 5,
                 mask, (long)kNI * 768, kND, 512, 4);
            if (!csr_done) {
                for (int br = 0; br < 2; br++) {
                    const int* e = (const int*)d_in[br * 6 + 2];
                    const int *rc = e, *cc = e + kEC;
                    const int* e2 = (const int*)d_in[br * 6 + 3];
                    const int *ri = e2, *ci = e2 + kEI;
                    const int* e3 = (const int*)d_in[br * 6 + 4];
                    const int *ro = e3, *co = e3 + kEO;
                    const int* e4 = (const int*)d_in[br * 6 + 5];
                    const int *rk = e4, *ck = e4 + kEK;
                    csr_count_k<<<(BB11 + 255) / 256, 256>>>(sp, rc, cc, ri, ci, ro, co, rk, ck);
                    csr_scan_k<<<5, 1024>>>(sp, br);
                    csr_fill_k<<<(BB12 + 255) / 256, 256>>>(sp, br, rc, cc, ri, ci, ro, co, rk, ck);
                }
                csr_done = true;
            }
            hgt_agg_k<<<2 * kNT, 128>>>(sp, dir, prel + (long)(combo * 4) * kH);
            // Wo: z = (branch:2) x (type:2 via zb mask)
            long wOff = (long)(combo * 2) * DD;
            const float* gp = skip + combo * 2;
            if (dir == 0)
                gemm(false, &sp->agg[0][0], kD, LXD, 0, 0, Wo + wOff, kD, 0, DD, 0,
                     &sp->yF[0][0], kD, LXD, T1, 0, &sp->x[0][0], kD, nullptr, gp,
                     kNI, kD, kD, 2, 2, 1, 1.f, 1,
                     0x2u, T1, kND);
            else
                gemm(false, &sp->agg[0][0], kD, LXD, 0, 0, Wo + wOff, kD, 0, DD, 0,
                     &sp->x[0][0], kD, LXD, T1, 0, &sp->x[0][0], kD, &sp->yF[0][0], gp,
                     kNI, kD, kD, 2, 2, 1, 1.f, 3,
                     0x2u, T1, kND);
        }
    }

    // pooling (both branches)
    hv_k<<<2 * kNT / 8, 256>>>(sp, poolW);
    gat_score_k<<<(2 * kNT + 255) / 256, 256>>>(sp, poolA, poolB);
    topk_sort_k<<<16, 1024>>>(sp);
    gather_k<<<dim3(kKP, 16), kD>>>(sp);

    // transformer attention (both branches)
    int Mp = kB * kKP;
    long pb = (long)kKP * kD;
    long pq = (long)kKP * 768;
    long sb = (long)kH * kKP * kKP;
    long SB = (long)kB * kH * kKP * kKP;
    gemm(false, &sp->xp[0][0], kD, LPD, 0, 0, sp->pTw, 768, 0, 0, 0,
         &sp->qkvp[0][0], 768, 3 * LPD, 0, 0,
         nullptr, 0, nullptr, nullptr, Mp, 768, kD, 2, 1, 1, 1.f, 0);
    gemm(true, &sp->qkvp[0][0], 768, 3 * LPD, pq, kDH,
         &sp->qkvp[0][0] + 256, 768, 3 * LPD, pq, kDH,
         &sp->S[0][0], kKP, SB, sb, (long)kKP * kKP,
         nullptr, 0, nullptr, nullptr,
         kKP, kKP, kDH, 2, kB, kH, 0.125f, 0);
    softmax_k<<<2 * kB * kH * kKP, 256>>>(&sp->S[0][0]);
    gemm(false, &sp->S[0][0], kKP, SB, (long)kH * kKP * kKP, (long)kKP * kKP,
         &sp->qkvp[0][0] + 512, 768, 3 * LPD, pq, kDH,
         &sp->oh[0][0], kD, LPD, pb, kDH,
         nullptr, 0, nullptr, nullptr,
         kKP, kDH, kKP, 2, kB, kH, 1.f, 0);
    gemm(false, &sp->oh[0][0], kD, LPD, 0, 0, tWo, kD, 0, 0, 0,
         &sp->yb[0][0], kD, LPD, 0, 0,
         &sp->xp[0][0], kD, nullptr, nullptr, Mp, kD, kD, 2, 1, 1, 1.f, 2);
    ln_k<<<2 * Mp, kD>>>(&sp->yb[0][0], lng, lnb, &sp->ga[0][0]);
    featsum_part_k<<<dim3(16, 6), 256>>>(sp);
    featsum_red_k<<<16, 512>>>(sp);
    cos_k<<<kB, 512>>>(sp->u, (float*)d_out);
}

// round 13
// speedup vs baseline: 5.2155x; 1.2006x over previous
#include <cuda_runtime.h>
#include <cuda_bf16.h>
#include <math.h>
#include <stdint.h>

// ------------------------- problem constants -------------------------
constexpr int kNI = 8192, kND = 4096, kNT = 12288, kD = 256, kH = 4, kDH = 64;
constexpr int kB = 8, kKP = 768;
constexpr int kEC = 65536, kEI = 32768, kEO = 32768, kEK = 8192;
constexpr long LXD = (long)kNT * kD;
constexpr long LPD = (long)kB * kKP * kD;
constexpr long KRVB = 8L * kNI * 256;          // bf16 elems per branch (K rels 0-3, V 4-7)
constexpr long SLEN = (long)kB * kH * kKP * kKP;

constexpr int O0 = 0;
constexpr int O1 = kNI;
constexpr int O2 = kNI + kND;
constexpr int O3 = 2 * kNI + kND;
constexpr int O4 = 2 * kNI + 2 * kND;
constexpr int CNT_TOT = O4 + kNT;

constexpr int BB0 = kEC;
constexpr int BB1 = BB0 + kEI;
constexpr int BB2 = BB1 + kEK;
constexpr int BB3 = BB2 + kEO;
constexpr int BB4 = BB3 + kEC;
constexpr int BB5 = BB4 + kEO;
constexpr int BB6 = BB5 + kEK;
constexpr int BB7 = BB6 + kEI;
constexpr int BB8 = BB7 + kEC;
constexpr int BB9 = BB8 + kEI;
constexpr int BB10 = BB9 + kEO;
constexpr int BB11 = BB10 + kEK;
constexpr int BB12 = BB11 + kNT;

typedef __nv_bfloat16 bf16;
typedef __nv_bfloat162 bf162;

// ------------------------- scratch -------------------------
struct Scratch {
    bf16 x[2][LXD], yF[2][LXD], agg[2][LXD];
    bf16 kqv[2][3 * LXD];                     // [branch][node][768] K|Q|V
    bf16 krv[2][KRVB];                        // [relslot 0-7][node][256]
    bf16 S[2][SLEN];
    bf16 xp[2][LPD], qkvp[2][3 * LPD], oh[2][LPD], yb[2][LPD], ga[2][LPD];
    bf16 vT[2][(long)kB * kH * 64 * kKP];     // V transposed [b][h][dh][key]
    bf16 pW[8L * 768 * 256];                  // [combo*2+t][n][k]
    bf16 pTw[768L * 256];
    bf16 pRel[4L * 8 * 4 * 64 * 64];          // [combo][relslot][h][n][k]
    bf16 pWo[8L * 256 * 256];
    bf16 pTwo[256L * 256];
    float hv[2 * kNT], sc[2 * kNT];
    float sv[2 * kB * kKP];
    int   si[2 * kB * kKP];
    float u[2 * kB * 512];
    float up[2 * kB * 6 * 512];
    int rpf0[2][kNI + 1], rpf1[2][kND + 1], rpr0[2][kNI + 1], rpr1[2][kND + 1], rph[2][kNT + 1];
    int ef0[2][kEC + kEI + kEK], ef1[2][kEO], er0[2][kEC + kEO + kEK], er1[2][kEI];
    int eh[2][kEC + kEI + kEO + kEK + kNT];
    int cnt[CNT_TOT], cur[CNT_TOT];
};
__device__ Scratch SC;

// ------------------------- reductions -------------------------
__device__ __forceinline__ float wsum(float v) {
#pragma unroll
    for (int o = 16; o; o >>= 1) v += __shfl_xor_sync(0xffffffffu, v, o);
    return v;
}
__device__ __forceinline__ float bsum(float v) {
    __shared__ float sh[32];
    int lane = threadIdx.x & 31, w = threadIdx.x >> 5;
    v = wsum(v);
    if (!lane) sh[w] = v;
    __syncthreads();
    int nw = blockDim.x >> 5;
    float s = (threadIdx.x < nw) ? sh[threadIdx.x] : 0.f;
    if (w == 0) s = wsum(s);
    if (threadIdx.x == 0) sh[0] = s;
    __syncthreads();
    float r = sh[0];
    __syncthreads();
    return r;
}
__device__ __forceinline__ float bmax(float v) {
    __shared__ float sh[32];
    int lane = threadIdx.x & 31, w = threadIdx.x >> 5;
#pragma unroll
    for (int o = 16; o; o >>= 1) v = fmaxf(v, __shfl_xor_sync(0xffffffffu, v, o));
    if (!lane) sh[w] = v;
    __syncthreads();
    int nw = blockDim.x >> 5;
    float s = (threadIdx.x < nw) ? sh[threadIdx.x] : -INFINITY;
    if (w == 0)
#pragma unroll
        for (int o = 16; o; o >>= 1) s = fmaxf(s, __shfl_xor_sync(0xffffffffu, s, o));
    if (threadIdx.x == 0) sh[0] = s;
    __syncthreads();
    float r = sh[0];
    __syncthreads();
    return r;
}

// ------------------------- bf16 tensor-core GEMM (cp.async pipelined) --------
// A [m][k] row-major bf16; B [n][k] row-major bf16 (weights pre-transposed).
__device__ __forceinline__ void mma_bf16(float* c, const uint32_t* a,
                                         uint32_t b0, uint32_t b1) {
    asm volatile(
        "mma.sync.aligned.m16n8k16.row.col.f32.bf16.bf16.f32 "
        "{%0,%1,%2,%3}, {%4,%5,%6,%7}, {%8,%9}, {%0,%1,%2,%3};"
        : "+f"(c[0]), "+f"(c[1]), "+f"(c[2]), "+f"(c[3])
        : "r"(a[0]), "r"(a[1]), "r"(a[2]), "r"(a[3]), "r"(b0), "r"(b1));
}
__device__ __forceinline__ void cpa16(void* dst, const void* src) {
    unsigned d = (unsigned)__cvta_generic_to_shared(dst);
    asm volatile("cp.async.cg.shared.global [%0], [%1], 16;\n" :: "r"(d), "l"(src));
}
#define CP_COMMIT() asm volatile("cp.async.commit_group;\n" ::: "memory")
#define CP_WAIT1()  asm volatile("cp.async.wait_group 1;\n" ::: "memory")
#define CP_WAIT0()  asm volatile("cp.async.wait_group 0;\n" ::: "memory")

// blockIdx.z -> (z2 = z/ZT, zb = (z%ZT)/ZH, zh = z%ZH). Strides in bf16 elems.
// A offset: z2*A2 + zb*Ab + zh*Ah (+Aalt if zmask bit zb; +Valt if zb>=zsplit).
// B offset: z2*B2 + zb*Bb + zh*Bh.  C/Add/Add2 offset: z2*C2 + zb*Cb + zh*Ch.
// If zmask bit zb set, M = Malt. g = sigmoid(gptr[zb]).
// mode 0: C=v | 1: C=g*v+(1-g)*Add | 2: C=v+Add | 3: C=relu(.5*(g*v+(1-g)*Add)+.5*Add2)
template <int BN>
__global__ void __launch_bounds__(256, 2) hgemm_k(
    const bf16* __restrict__ A, int lda, long A2, long Ab, long Ah,
    const bf16* __restrict__ Bm, int ldb, long B2, long Bb, long Bh,
    bf16* __restrict__ C, int ldc, long C2, long Cb, long Ch,
    const bf16* __restrict__ Add, int ldadd, const bf16* __restrict__ Add2,
    const float* __restrict__ gptr,
    int Kdim, int ZH, int ZT, float alpha, int mode,
    unsigned zmask, long Aalt, int Malt, int Mdef, long Valt, int zsplit)
{
    constexpr int BM = 128, BK = 32;
    constexpr int STR = 40;                       // bf16; 80B rows (16B aligned, no conflicts)
    constexpr int TN = (BN == 128) ? 8 : 4;
    extern __shared__ bf16 smh_[];
    bf16* As = smh_;                              // [2][BM][STR]
    bf16* Bs = smh_ + 2 * BM * STR;               // [2][BN][STR]

    int z = blockIdx.z;
    int z2 = z / ZT, rz = z - z2 * ZT;
    int zb = rz / ZH, zh = rz - zb * ZH;
    int msk = (zmask >> zb) & 1;
    int Mz = msk ? Malt : Mdef;
    int m0 = blockIdx.x * BM;
    if (m0 >= Mz) return;
    const bf16* Ax = A + z2 * A2 + zb * Ab + zh * Ah + (msk ? Aalt : 0)
                       + (zb >= zsplit ? Valt : 0);
    const bf16* Bx = Bm + z2 * B2 + zb * Bb + zh * Bh;
    long coff = z2 * C2 + zb * Cb + zh * Ch;
    C += coff;
    if (Add)  Add  += coff;
    if (Add2) Add2 += coff;
    int n0 = blockIdx.y * BN;
    int tid = threadIdx.x, lane = tid & 31, warp = tid >> 5;
    int wm = warp >> 1, wn = warp & 1;
    int g = lane >> 2, tg = lane & 3;

    float acc[2][TN][4];
#pragma unroll
    for (int i = 0; i < 2; i++)
#pragma unroll
        for (int j = 0; j < TN; j++)
#pragma unroll
            for (int q = 0; q < 4; q++) acc[i][j][q] = 0.f;

    int nt = Kdim / BK;

#define ISSUE(K0, Sg) do {                                                     \
        bf16* Ad = As + (Sg) * BM * STR;                                       \
        _Pragma("unroll")                                                      \
        for (int q = 0; q < 2; q++) {                                          \
            int f = tid + q * 256, row = f >> 2, kc = (f & 3) * 8;             \
            cpa16(Ad + row * STR + kc,                                         \
                  Ax + (long)(m0 + row) * lda + (K0) + kc);                    \
        }                                                                      \
        bf16* Bd = Bs + (Sg) * BN * STR;                                       \
        _Pragma("unroll")                                                      \
        for (int q = 0; q < BN / 64; q++) {                                    \
            int f = tid + q * 256, row = f >> 2, kc = (f & 3) * 8;             \
            cpa16(Bd + row * STR + kc,                                         \
                  Bx + (long)(n0 + row) * ldb + (K0) + kc);                    \
        }                                                                      \
    } while (0)

    ISSUE(0, 0);
    CP_COMMIT();

    for (int t = 0; t < nt; t++) {
        if (t + 1 < nt) {
            ISSUE((t + 1) * BK, (t + 1) & 1);
            CP_COMMIT();
            CP_WAIT1();
        } else {
            CP_WAIT0();
        }
        __syncthreads();
        const bf16* Ap = As + (size_t)(t & 1) * BM * STR;
        const bf16* Bp = Bs + (size_t)(t & 1) * BN * STR;
#pragma unroll
        for (int k16 = 0; k16 < 2; k16++) {
            int kb = k16 * 16;
            uint32_t a[2][4];
#pragma unroll
            for (int tm = 0; tm < 2; tm++) {
                int mr = wm * 32 + tm * 16;
                a[tm][0] = *(const uint32_t*)(Ap + (mr + g) * STR + kb + 2 * tg);
                a[tm][1] = *(const uint32_t*)(Ap + (mr + 8 + g) * STR + kb + 2 * tg);
                a[tm][2] = *(const uint32_t*)(Ap + (mr + g) * STR + kb + 2 * tg + 8);
                a[tm][3] = *(const uint32_t*)(Ap + (mr + 8 + g) * STR + kb + 2 * tg + 8);
            }
#pragma unroll
            for (int tn = 0; tn < TN; tn++) {
                int nc = wn * (TN * 8) + tn * 8 + g;
                uint32_t b0 = *(const uint32_t*)(Bp + nc * STR + kb + 2 * tg);
                uint32_t b1 = *(const uint32_t*)(Bp + nc * STR + kb + 2 * tg + 8);
#pragma unroll
                for (int tm = 0; tm < 2; tm++)
                    mma_bf16(acc[tm][tn], a[tm], b0, b1);
            }
        }
        __syncthreads();
    }
#undef ISSUE

    float gg = 1.f;
    if (mode == 1 || mode == 3) gg = 1.f / (1.f + expf(-gptr[zb]));
#pragma unroll
    for (int tm = 0; tm < 2; tm++) {
        long row0 = m0 + wm * 32 + tm * 16 + g;
#pragma unroll
        for (int tn = 0; tn < TN; tn++) {
            long col = n0 + wn * (TN * 8) + tn * 8 + tg * 2;
#pragma unroll
            for (int half = 0; half < 2; half++) {
                long r = row0 + half * 8;
                float vx = alpha * acc[tm][tn][half * 2 + 0];
                float vy = alpha * acc[tm][tn][half * 2 + 1];
                if (mode == 1) {
                    float2 ad = __bfloat1622float2(*(const bf162*)(Add + r * ldadd + col));
                    vx = gg * vx + (1.f - gg) * ad.x;
                    vy = gg * vy + (1.f - gg) * ad.y;
                } else if (mode == 2) {
                    float2 ad = __bfloat1622float2(*(const bf162*)(Add + r * ldadd + col));
                    vx += ad.x; vy += ad.y;
                } else if (mode == 3) {
                    float2 ad = __bfloat1622float2(*(const bf162*)(Add + r * ldadd + col));
                    float2 a2 = __bfloat1622float2(*(const bf162*)(Add2 + r * ldadd + col));
                    vx = 0.5f * (gg * vx + (1.f - gg) * ad.x) + 0.5f * a2.x;
                    vy = 0.5f * (gg * vy + (1.f - gg) * ad.y) + 0.5f * a2.y;
                    vx = vx > 0.f ? vx : 0.f;
                    vy = vy > 0.f ? vy : 0.f;
                }
                *(bf162*)(C + r * ldc + col) = __floats2bfloat162_rn(vx, vy);
            }
        }
    }
}

// ------------------------- fused weight packing (all -> bf16, [n][k]) -------
constexpr long PW = 8L * 768 * 256;
constexpr long PT = 768L * 256;
constexpr long PR = 4L * 8 * 4 * 4096;
constexpr long PO = 8L * 256 * 256;
constexpr long P2 = 256L * 256;
__global__ void pack_all_k(const float* __restrict__ Wk, const float* __restrict__ Wq,
                           const float* __restrict__ Wv, const float* __restrict__ tWq,
                           const float* __restrict__ tWk, const float* __restrict__ tWv,
                           const float* __restrict__ arel, const float* __restrict__ mrel,
                           const float* __restrict__ Wo, const float* __restrict__ tWo,
                           Scratch* sp) {
    long i = (long)blockIdx.x * 256 + threadIdx.x;
    if (i < PW) {
        long c = i / (768 * 256), r = i % (768 * 256);
        int n = (int)(r / 256), k = (int)(r % 256);
        int sel = n >> 8, nn = n & 255;
        const float* W = (sel == 0) ? Wk : (sel == 1) ? Wq : Wv;
        sp->pW[i] = __float2bfloat16(W[c * 65536 + (long)k * 256 + nn]);
    } else if (i < PW + PT) {
        long j = i - PW;
        int n = (int)(j / 256), k = (int)(j % 256);
        int sel = n >> 8, nn = n & 255;
        const float* W = (sel == 0) ? tWq : (sel == 1) ? tWk : tWv;
        sp->pTw[j] = __float2bfloat16(W[(long)k * 256 + nn]);
    } else if (i < PW + PT + PR) {
        long j = i - PW - PT;
        int k  = (int)(j & 63);
        int n  = (int)((j >> 6) & 63);
        int hh = (int)((j >> 12) & 3);
        int zr = (int)((j >> 14) & 7);
        int c  = (int)(j >> 17);
        const float* src = (zr < 4) ? arel : mrel;
        int rr = zr & 3;
        sp->pRel[j] = __float2bfloat16(src[(((long)(c * 4 + rr) * 4 + hh) << 12) + k * 64 + n]);
    } else if (i < PW + PT + PR + PO) {
        long j = i - PW - PT - PR;
        long c = j / 65536, r = j % 65536;
        int n = (int)(r / 256), k = (int)(r % 256);
        sp->pWo[j] = __float2bfloat16(Wo[c * 65536 + (long)k * 256 + n]);
    } else if (i < PW + PT + PR + PO + P2) {
        long j = i - PW - PT - PR - PO;
        int n = (int)(j / 256), k = (int)(j % 256);
        sp->pTwo[j] = __float2bfloat16(tWo[(long)k * 256 + n]);
    }
}

// ------------------------- elementwise -------------------------
__global__ void assemble_x_k(const float* __restrict__ xi0, const float* __restrict__ xd0,
                             const float* __restrict__ xi1, const float* __restrict__ xd1,
                             Scratch* sp) {
    long i = ((long)blockIdx.x * blockDim.x + threadIdx.x) * 4;
    if (i < 2 * LXD) {
        const long T1 = (long)kNI * kD;
        int br = i >= LXD;
        long loc = i - (long)br * LXD;
        const float* xi = br ? xi1 : xi0;
        const float* xd = br ? xd1 : xd0;
        float4 v = (loc < T1) ? *(const float4*)(xi + loc) : *(const float4*)(xd + (loc - T1));
        bf162 h0 = __floats2bfloat162_rn(v.x, v.y);
        bf162 h1 = __floats2bfloat162_rn(v.z, v.w);
        *(bf162*)(&sp->x[0][0] + i) = h0;
        *(bf162*)(&sp->x[0][0] + i + 2) = h1;
    }
}
// vT[b][h][dh][key] <- qkvp[(b*768+key)*768 + 512 + h*64 + dh]
__global__ void vtrans_k(Scratch* sp) {
    long i = (long)blockIdx.x * blockDim.x + threadIdx.x;
    if (i >= 2L * kB * kH * 64 * kKP) return;
    int key = (int)(i % kKP);
    long r = i / kKP;
    int dh = (int)(r & 63);
    long r2 = r >> 6;
    int h = (int)(r2 & 3);
    long r3 = r2 >> 2;
    int b = (int)(r3 & 7);
    int br = (int)(r3 >> 3);
    sp->vT[br][(((long)b * 4 + h) * 64 + dh) * kKP + key] =
        sp->qkvp[br][((long)b * kKP + key) * 768 + 512 + h * 64 + dh];
}

// ------------------------- fused CSR construction -------------------------
struct Slot { int idx; int ent; int arr; };
__device__ __forceinline__ Slot decode_slot(
    int i, const int* rc, const int* cc, const int* ri, const int* ci,
    const int* ro, const int* co, const int* rk, const int* ck)
{
    Slot s;
    if (i < BB0)       { s.idx = O0 + cc[i];            s.ent = (0 << 16) | rc[i];            s.arr = 0; }
    else if (i < BB1)  { int j = i - BB0;  s.idx = O0 + ci[j]; s.ent = (1 << 16) | ri[j];     s.arr = 0; }
    else if (i < BB2)  { int j = i - BB1;  s.idx = O0 + ck[j]; s.ent = (3 << 16) | rk[j];     s.arr = 0; }
    else if (i < BB3)  { int j = i - BB2;  s.idx = O1 + co[j]; s.ent = (2 << 16) | ro[j];     s.arr = 1; }
    else if (i < BB4)  { int j = i - BB3;  s.idx = O2 + rc[j]; s.ent = (0 << 16) | cc[j];     s.arr = 2; }
    else if (i < BB5)  { int j = i - BB4;  s.idx = O2 + ro[j]; s.ent = (2 << 16) | co[j];     s.arr = 2; }
    else if (i < BB6)  { int j = i - BB5;  s.idx = O2 + rk[j]; s.ent = (3 << 16) | ck[j];     s.arr = 2; }
    else if (i < BB7)  { int j = i - BB6;  s.idx = O3 + ri[j]; s.ent = (1 << 16) | ci[j];     s.arr = 3; }
    else if (i < BB8)  { int j = i - BB7;  s.idx = O4 + cc[j]; s.ent = rc[j];                 s.arr = 4; }
    else if (i < BB9)  { int j = i - BB8;  s.idx = O4 + ci[j]; s.ent = ri[j] + kNI;           s.arr = 4; }
    else if (i < BB10) { int j = i - BB9;  s.idx = O4 + co[j] + kNI; s.ent = ro[j];           s.arr = 4; }
    else               { int j = i - BB10; s.idx = O4 + ck[j]; s.ent = rk[j];                 s.arr = 4; }
    return s;
}

__global__ void csr_count_k(Scratch* sp, const int* rc, const int* cc,
                            const int* ri, const int* ci, const int* ro, const int* co,
                            const int* rk, const int* ck) {
    int i = blockIdx.x * blockDim.x + threadIdx.x;
    if (i < BB11) {
        Slot s = decode_slot(i, rc, cc, ri, ci, ro, co, rk, ck);
        atomicAdd(&sp->cnt[s.idx], 1);
    }
}
__global__ void csr_scan_k(Scratch* sp, int br) {
    __shared__ int sh[1024];
    int region = blockIdx.x, t = threadIdx.x;
    int off, n, extra = 0;
    int* rp;
    switch (region) {
        case 0: off = O0; n = kNI; rp = sp->rpf0[br]; break;
        case 1: off = O1; n = kND; rp = sp->rpf1[br]; break;
        case 2: off = O2; n = kNI; rp = sp->rpr0[br]; break;
        case 3: off = O3; n = kND; rp = sp->rpr1[br]; break;
        default: off = O4; n = kNT; rp = sp->rph[br]; extra = 1; break;
    }
    int c = (n + 1023) >> 10;
    int beg = t * c, end = min(beg + c, n);
    int s = 0;
    for (int i = beg; i < end; i++) s += sp->cnt[off + i] + extra;
    sh[t] = s;
    __syncthreads();
    for (int o = 1; o < 1024; o <<= 1) {
        int v = (t >= o) ? sh[t - o] : 0;
        __syncthreads();
        sh[t] += v;
        __syncthreads();
    }
    int run = t ? sh[t - 1] : 0;
    for (int i = beg; i < end; i++) {
        int cv = sp->cnt[off + i];
        sp->cnt[off + i] = 0;
        rp[i] = run;
        sp->cur[off + i] = run;
        run += cv + extra;
    }
    if (t == 1023) rp[n] = sh[1023];
}
__global__ void csr_fill_k(Scratch* sp, int br, const int* rc, const int* cc,
                           const int* ri, const int* ci, const int* ro, const int* co,
                           const int* rk, const int* ck) {
    int i = blockIdx.x * blockDim.x + threadIdx.x;
    if (i >= BB12) return;
    if (i < BB11) {
        Slot s = decode_slot(i, rc, cc, ri, ci, ro, co, rk, ck);
        int pos = atomicAdd(&sp->cur[s.idx], 1);
        switch (s.arr) {
            case 0: sp->ef0[br][pos] = s.ent; break;
            case 1: sp->ef1[br][pos] = s.ent; break;
            case 2: sp->er0[br][pos] = s.ent; break;
            case 3: sp->er1[br][pos] = s.ent; break;
            default: sp->eh[br][pos] = s.ent; break;
        }
    } else {
        int node = i - BB11;
        int pos = atomicAdd(&sp->cur[O4 + node], 1);
        sp->eh[br][pos] = node;
    }
}

// ------------------- HGT softmax aggregation (bf16 everywhere) --------------
__global__ void hgt_agg_k(Scratch* sp, int dir, const float* __restrict__ prel) {
    int nb = blockIdx.x;
    int branch = nb >= kNT;
    int node = nb - branch * kNT;
    const int *rp, *ent; int idx;
    if (dir == 0) {
        if (node < kNI) { rp = sp->rpf0[branch]; ent = sp->ef0[branch]; idx = node; }
        else            { rp = sp->rpf1[branch]; ent = sp->ef1[branch]; idx = node - kNI; }
    } else {
        if (node < kNI) { rp = sp->rpr0[branch]; ent = sp->er0[branch]; idx = node; }
        else            { rp = sp->rpr1[branch]; ent = sp->er1[branch]; idx = node - kNI; }
    }
    int h = threadIdx.x >> 5, lane = threadIdx.x & 31;
    long hoff = h * 64 + 2 * lane;
    float2 qq = __bfloat1622float2(
        *(const bf162*)(sp->kqv[branch] + (long)node * 768 + 256 + hoff));
    float q0 = qq.x, q1 = qq.y;
    const bf16* krv = sp->krv[branch];
    float pr0 = prel[0 * kH + h], pr1 = prel[1 * kH + h];
    float pr2 = prel[2 * kH + h], pr3 = prel[3 * kH + h];
    int s = rp[idx], eend = rp[idx + 1];
    float m = -INFINITY, den = 0.f, a0 = 0.f, a1 = 0.f;
    int e = s;
    for (; e + 1 < eend; e += 2) {
        int pkA = ent[e], pkB = ent[e + 1];
        int rA = pkA >> 16, sA = pkA & 0xffff;
        int rB = pkB >> 16, sB = pkB & 0xffff;
        float2 kA = __bfloat1622float2(
            *(const bf162*)(krv + ((long)rA * kNI + sA) * 256 + hoff));
        float2 kB2 = __bfloat1622float2(
            *(const bf162*)(krv + ((long)rB * kNI + sB) * 256 + hoff));
        float2 vA = __bfloat1622float2(
            *(const bf162*)(krv + ((long)(rA + 4) * kNI + sA) * 256 + hoff));
        float2 vB = __bfloat1622float2(
            *(const bf162*)(krv + ((long)(rB + 4) * kNI + sB) * 256 + hoff));
        float dA = q0 * kA.x + q1 * kA.y;
        float dB = q0 * kB2.x + q1 * kB2.y;
#pragma unroll
        for (int o = 16; o; o >>= 1) {
            dA += __shfl_xor_sync(0xffffffffu, dA, o);
            dB += __shfl_xor_sync(0xffffffffu, dB, o);
        }
        float prA = (rA == 0) ? pr0 : (rA == 1) ? pr1 : (rA == 2) ? pr2 : pr3;
        float prB = (rB == 0) ? pr0 : (rB == 1) ? pr1 : (rB == 2) ? pr2 : pr3;
        float scA = dA * prA * 0.125f, scB = dB * prB * 0.125f;
        float mn = fmaxf(m, fmaxf(scA, scB));
        float cc = expf(m - mn), wA = expf(scA - mn), wB = expf(scB - mn);
        den = den * cc + wA + wB;
        a0 = a0 * cc + wA * vA.x + wB * vB.x;
        a1 = a1 * cc + wA * vA.y + wB * vB.y;
        m = mn;
    }
    if (e < eend) {
        int pk = ent[e];
        int r = pk >> 16, src = pk & 0xffff;
        float2 kk = __bfloat1622float2(
            *(const bf162*)(krv + ((long)r * kNI + src) * 256 + hoff));
        float2 vv = __bfloat1622float2(
            *(const bf162*)(krv + ((long)(r + 4) * kNI + src) * 256 + hoff));
        float d0 = q0 * kk.x + q1 * kk.y;
        d0 = wsum(d0);
        float pr = (r == 0) ? pr0 : (r == 1) ? pr1 : (r == 2) ? pr2 : pr3;
        float sc2 = d0 * pr * 0.125f;
        float mn = fmaxf(m, sc2);
        float cc = expf(m - mn), w = expf(sc2 - mn);
        den = den * cc + w;
        a0 = a0 * cc + w * vv.x;
        a1 = a1 * cc + w * vv.y;
        m = mn;
    }
    float inv = 1.f / (den + 1e-16f);
    float r0 = a0 * inv, r1 = a1 * inv;
    float g0 = 0.5f * r0 * (1.f + erff(r0 * 0.7071067811865475f));
    float g1 = 0.5f * r1 * (1.f + erff(r1 * 0.7071067811865475f));
    *(bf162*)(sp->agg[branch] + (long)node * kD + hoff) = __floats2bfloat162_rn(g0, g1);
}

// ------------------------- pooling -------------------------
__global__ void hv_k(Scratch* sp, const float* __restrict__ pw) {
    int nb = blockIdx.x * 8 + (threadIdx.x >> 5);
    int lane = threadIdx.x & 31;
    if (nb >= 2 * kNT) return;
    const bf16* x = &sp->x[0][0];
    float s = 0.f;
    for (int d = lane * 2; d < kD; d += 64) {
        float2 v = __bfloat1622float2(*(const bf162*)(x + (long)nb * kD + d));
        s += v.x * pw[d] + v.y * pw[d + 1];
    }
    s = wsum(s);
    if (!lane) sp->hv[nb] = s;
}
__global__ void gat_score_k(Scratch* sp, const float* __restrict__ att,
                            const float* __restrict__ bias) {
    int i = blockIdx.x * blockDim.x + threadIdx.x;
    if (i >= 2 * kNT) return;
    int branch = i / kNT, ii = i - branch * kNT;
    const int* rp = sp->rph[branch];
    const int* ent = sp->eh[branch];
    float A0 = att[0], A1 = att[1];
    float hi = sp->hv[i];
    int s = rp[ii], e1 = rp[ii + 1];
    float m = -INFINITY, den = 0.f, acc = 0.f;
    int hb = branch * kNT;
    for (int e = s; e < e1; e++) {
        int src = ent[e] & 0xffff;
        float hs = sp->hv[hb + src];
        float ee = A0 * hs + A1 * hi;
        ee = ee >= 0.f ? ee : 0.2f * ee;
        float mn = fmaxf(m, ee);
        float c = expf(m - mn), w = expf(ee - mn);
        den = den * c + w;
        acc = acc * c + w * hs;
        m = mn;
    }
    sp->sc[i] = acc / (den + 1e-16f) + bias[0];
}

__global__ void topk_sort_k(Scratch* sp) {
    int bi = blockIdx.x;
    int branch = bi >> 3, b = bi & 7;
    int t = threadIdx.x;
    const float* sc = sp->sc + branch * kNT;
    __shared__ float v[2048];
    __shared__ int ix[2048];
    for (int p = t; p < 2048; p += 1024) {
        float val = -INFINITY;
        if (p < 1536) {
            int node = p < 1024 ? b * 1024 + p : kNI + b * 512 + (p - 1024);
            val = sc[node];
        }
        v[p] = val;
        ix[p] = p;
    }
    __syncthreads();
    for (int k = 2; k <= 2048; k <<= 1)
        for (int j = k >> 1; j > 0; j >>= 1) {
#pragma unroll
            for (int pass = 0; pass < 2; pass++) {
                int i = t + pass * 1024;
                int l = i ^ j;
                if (l > i) {
                    bool up = ((i & k) == 0);
                    float vi = v[i], vl = v[l];
                    int ii = ix[i], il = ix[l];
                    bool before = (vi > vl) || (vi == vl && ii < il);
                    if (up != before) {
                        v[i] = vl; v[l] = vi;
                        ix[i] = il; ix[l] = ii;
                    }
                }
            }
            __syncthreads();
        }
    if (t < kKP) {
        sp->sv[bi * kKP + t] = v[t];
        sp->si[bi * kKP + t] = ix[t];
    }
}
__global__ void gather_k(Scratch* sp) {
    int q = blockIdx.x, bi = blockIdx.y, d = threadIdx.x;
    int branch = bi >> 3, b = bi & 7;
    int j = sp->si[bi * kKP + q];
    float tv = tanhf(sp->sv[bi * kKP + q]);
    int node = j < 1024 ? b * 1024 + j : kNI + b * 512 + (j - 1024);
    float vv = __bfloat162float(sp->x[branch][(long)node * kD + d]) * tv;
    sp->xp[branch][((long)(b * kKP + q)) * kD + d] = __float2bfloat16(vv);
}

// ------------------------- transformer pieces -------------------------
__global__ void softmax_k(bf16* __restrict__ S) {
    long row = blockIdx.x;
    bf16* p = S + row * kKP;
    int t = threadIdx.x;
    float v0 = __bfloat162float(p[t]);
    float v1 = __bfloat162float(p[t + 256]);
    float v2 = __bfloat162float(p[t + 512]);
    float m = bmax(fmaxf(v0, fmaxf(v1, v2)));
    v0 = expf(v0 - m); v1 = expf(v1 - m); v2 = expf(v2 - m);
    float s = bsum(v0 + v1 + v2);
    float inv = 1.f / s;
    p[t] = __float2bfloat16(v0 * inv);
    p[t + 256] = __float2bfloat16(v1 * inv);
    p[t + 512] = __float2bfloat16(v2 * inv);
}
__global__ void ln_k(const bf16* __restrict__ y, const float* __restrict__ g,
                     const float* __restrict__ bta, bf16* __restrict__ out) {
    long row = blockIdx.x;
    int d = threadIdx.x;
    float v = __bfloat162float(y[row * kD + d]);
    float mu = bsum(v) * (1.f / kD);
    float df = v - mu;
    float var = bsum(df * df) * (1.f / kD);
    out[row * kD + d] = __float2bfloat16(g[d] * df * rsqrtf(var + 1e-5f) + bta[d]);
}
__global__ void featsum_part_k(Scratch* sp) {
    int bi = blockIdx.x, ch = blockIdx.y, d = threadIdx.x;
    int branch = bi >> 3, b = bi & 7;
    const bf16* xp = sp->xp[branch];
    const bf16* ga = sp->ga[branch];
    float s1 = 0.f, s2 = 0.f;
    int q0 = ch * 128;
    for (int q = q0; q < q0 + 128; q++) {
        long o = ((long)(b * kKP + q)) * kD + d;
        s1 += __bfloat162float(xp[o]);
        s2 += __bfloat162float(ga[o]);
    }
    sp->up[(bi * 6 + ch) * 512 + d] = s1;
    sp->up[(bi * 6 + ch) * 512 + 256 + d] = s2;
}
__global__ void featsum_red_k(Scratch* sp) {
    int bi = blockIdx.x, d = threadIdx.x;
    float s = 0.f;
    for (int ch = 0; ch < 6; ch++) s += sp->up[(bi * 6 + ch) * 512 + d];
    sp->u[bi * 512 + d] = s;
}
__global__ void cos_k(const float* __restrict__ u, float* __restrict__ out) {
    int b = blockIdx.x, t = threadIdx.x;
    float a = u[b * 512 + t];
    float c = u[(kB + b) * 512 + t];
    float dot = bsum(a * c);
    float na = bsum(a * a);
    float nc = bsum(c * c);
    if (t == 0)
        out[b] = dot / (fmaxf(sqrtf(na), 1e-8f) * fmaxf(sqrtf(nc), 1e-8f));
}

// ------------------------- host orchestration -------------------------
static void gemm(const bf16* A, int lda, long A2, long Ab, long Ah,
                 const bf16* Bm, int ldb, long B2, long Bb, long Bh,
                 bf16* C, int ldc, long C2, long Cb, long Ch,
                 const bf16* Add, int ldadd, const bf16* Add2, const float* gptr,
                 int M, int N, int K, int ZC, int ZB, int ZH, float alpha, int mode,
                 unsigned zmask = 0, long Aalt = 0, int Malt = 0,
                 long Valt = 0, int zsplit = 1 << 30) {
    int ZT = ZB * ZH;
    if (N % 128 == 0) {
        int sm = (2 * 128 * 40 + 2 * 128 * 40) * 2;
        dim3 g(M / 128, N / 128, ZC * ZT), blk(256);
        cudaFuncSetAttribute(hgemm_k<128>, cudaFuncAttributeMaxDynamicSharedMemorySize, sm);
        hgemm_k<128><<<g, blk, sm>>>(A, lda, A2, Ab, Ah, Bm, ldb, B2, Bb, Bh,
                                     C, ldc, C2, Cb, Ch, Add, ldadd, Add2, gptr,
                                     K, ZH, ZT, alpha, mode, zmask, Aalt, Malt, M,
                                     Valt, zsplit);
    } else {
        int sm = (2 * 128 * 40 + 2 * 64 * 40) * 2;
        dim3 g(M / 128, N / 64, ZC * ZT), blk(256);
        cudaFuncSetAttribute(hgemm_k<64>, cudaFuncAttributeMaxDynamicSharedMemorySize, sm);
        hgemm_k<64><<<g, blk, sm>>>(A, lda, A2, Ab, Ah, Bm, ldb, B2, Bb, Bh,
                                    C, ldc, C2, Cb, Ch, Add, ldadd, Add2, gptr,
                                    K, ZH, ZT, alpha, mode, zmask, Aalt, Malt, M,
                                    Valt, zsplit);
    }
}

extern "C" void kernel_launch(void* const* d_in, const int* in_sizes, int n_in,
                              void* d_out, int out_size) {
    Scratch* sp = nullptr;
    cudaGetSymbolAddress((void**)&sp, SC);

    const float* Wk    = (const float*)d_in[12];
    const float* Wq    = (const float*)d_in[13];
    const float* Wv    = (const float*)d_in[14];
    const float* Wo    = (const float*)d_in[15];
    const float* arel  = (const float*)d_in[16];
    const float* mrel  = (const float*)d_in[17];
    const float* prel  = (const float*)d_in[18];
    const float* skip  = (const float*)d_in[19];
    const float* poolW = (const float*)d_in[20];
    const float* poolA = (const float*)d_in[21];
    const float* poolB = (const float*)d_in[22];
    const float* tWq   = (const float*)d_in[23];
    const float* tWk   = (const float*)d_in[24];
    const float* tWv   = (const float*)d_in[25];
    const float* tWo   = (const float*)d_in[26];
    const float* lng   = (const float*)d_in[27];
    const float* lnb   = (const float*)d_in[28];

    const long T1 = (long)kNI * kD;
    const long KQVB = 3 * LXD;

    pack_all_k<<<(int)((PW + PT + PR + PO + P2 + 255) / 256), 256>>>(
        Wk, Wq, Wv, tWq, tWk, tWv, arel, mrel, Wo, tWo, sp);
    assemble_x_k<<<(int)(2 * LXD / 4 + 255) / 256, 256>>>(
        (const float*)d_in[0], (const float*)d_in[1],
        (const float*)d_in[6], (const float*)d_in[7], sp);

    bool csr_done = false;

    for (int l = 0; l < 2; l++) {
        for (int dir = 0; dir < 2; dir++) {
            int combo = l * 2 + dir;
            // QKV: z = (branch:2) x (type:2 via zb mask)
            gemm(&sp->x[0][0], kD, LXD, 0, 0,
                 sp->pW + (long)(combo * 2) * 768 * 256, 256, 0, 768 * 256, 0,
                 &sp->kqv[0][0], 768, KQVB, (long)kNI * 768, 0,
                 nullptr, 0, nullptr, nullptr,
                 kNI, 768, kD, 2, 2, 1, 1.f, 0,
                 0x2u, T1, kND);
            // Krel+Vrel: z = (branch:2) x (relslot:8) x (head:4)
            unsigned mask = dir ? 0x44u : 0x22u;
            gemm(&sp->kqv[0][0], 768, KQVB, 0, 64,
                 sp->pRel + (long)combo * 8 * 4 * 4096, 64, 0, (long)4 * 4096, 4096,
                 &sp->krv[0][0], 256, KRVB, (long)kNI * 256, 64,
                 nullptr, 0, nullptr, nullptr,
                 kNI, kDH, kDH, 2, 8, kH, 1.f, 0,
                 mask, (long)kNI * 768, kND, 512, 4);
            if (!csr_done) {
                for (int br = 0; br < 2; br++) {
                    const int* e = (const int*)d_in[br * 6 + 2];
                    const int *rc = e, *cc = e + kEC;
                    const int* e2 = (const int*)d_in[br * 6 + 3];
                    const int *ri = e2, *ci = e2 + kEI;
                    const int* e3 = (const int*)d_in[br * 6 + 4];
                    const int *ro = e3, *co = e3 + kEO;
                    const int* e4 = (const int*)d_in[br * 6 + 5];
                    const int *rk = e4, *ck = e4 + kEK;
                    csr_count_k<<<(BB11 + 255) / 256, 256>>>(sp, rc, cc, ri, ci, ro, co, rk, ck);
                    csr_scan_k<<<5, 1024>>>(sp, br);
                    csr_fill_k<<<(BB12 + 255) / 256, 256>>>(sp, br, rc, cc, ri, ci, ro, co, rk, ck);
                }
                csr_done = true;
            }
            hgt_agg_k<<<2 * kNT, 128>>>(sp, dir, prel + (long)(combo * 4) * kH);
            // Wo: z = (branch:2) x (type:2 via zb mask)
            const float* gp = skip + combo * 2;
            if (dir == 0)
                gemm(&sp->agg[0][0], kD, LXD, 0, 0,
                     sp->pWo + (long)(combo * 2) * 65536, 256, 0, 65536, 0,
                     &sp->yF[0][0], kD, LXD, T1, 0, &sp->x[0][0], kD, nullptr, gp,
                     kNI, kD, kD, 2, 2, 1, 1.f, 1,
                     0x2u, T1, kND);
            else
                gemm(&sp->agg[0][0], kD, LXD, 0, 0,
                     sp->pWo + (long)(combo * 2) * 65536, 256, 0, 65536, 0,
                     &sp->x[0][0], kD, LXD, T1, 0, &sp->x[0][0], kD, &sp->yF[0][0], gp,
                     kNI, kD, kD, 2, 2, 1, 1.f, 3,
                     0x2u, T1, kND);
        }
    }

    // pooling (both branches)
    hv_k<<<2 * kNT / 8, 256>>>(sp, poolW);
    gat_score_k<<<(2 * kNT + 255) / 256, 256>>>(sp, poolA, poolB);
    topk_sort_k<<<16, 1024>>>(sp);
    gather_k<<<dim3(kKP, 16), kD>>>(sp);

    // transformer attention (both branches)
    int Mp = kB * kKP;
    long pq = (long)kKP * 768;
    gemm(&sp->xp[0][0], kD, LPD, 0, 0, sp->pTw, 256, 0, 0, 0,
         &sp->qkvp[0][0], 768, 3 * LPD, 0, 0,
         nullptr, 0, nullptr, nullptr, Mp, 768, kD, 2, 1, 1, 1.f, 0);
    // S = Q K^T / 8 : A = Q rows, B = K rows (both [n][k] natural)
    gemm(&sp->qkvp[0][0], 768, 3 * LPD, pq, kDH,
         &sp->qkvp[0][0] + 256, 768, 3 * LPD, pq, kDH,
         &sp->S[0][0], kKP, SLEN, (long)kH * kKP * kKP, (long)kKP * kKP,
         nullptr, 0, nullptr, nullptr,
         kKP, kKP, kDH, 2, kB, kH, 0.125f, 0);
    softmax_k<<<2 * kB * kH * kKP, 256>>>(&sp->S[0][0]);
    vtrans_k<<<(int)((2L * kB * kH * 64 * kKP + 255) / 256), 256>>>(sp);
    // O = S @ V : B = vT [dh][key]
    gemm(&sp->S[0][0], kKP, SLEN, (long)kH * kKP * kKP, (long)kKP * kKP,
         &sp->vT[0][0], kKP, (long)kB * kH * 64 * kKP, (long)kH * 64 * kKP, (long)64 * kKP,
         &sp->oh[0][0], kD, LPD, (long)kKP * kD, kDH,
         nullptr, 0, nullptr, nullptr,
         kKP, kDH, kKP, 2, kB, kH, 1.f, 0);
    gemm(&sp->oh[0][0], kD, LPD, 0, 0, sp->pTwo, 256, 0, 0, 0,
         &sp->yb[0][0], kD, LPD, 0, 0,
         &sp->xp[0][0], kD, nullptr, nullptr, Mp, kD, kD, 2, 1, 1, 1.f, 2);
    ln_k<<<2 * Mp, kD>>>(&sp->yb[0][0], lng, lnb, &sp->ga[0][0]);
    featsum_part_k<<<dim3(16, 6), 256>>>(sp);
    featsum_red_k<<<16, 512>>>(sp);
    cos_k<<<kB, 512>>>(sp->u, (float*)d_out);
}

// round 14
// speedup vs baseline: 5.4336x; 1.0418x over previous
#include <cuda_runtime.h>
#include <cuda_bf16.h>
#include <math.h>
#include <stdint.h>

// ------------------------- problem constants -------------------------
constexpr int kNI = 8192, kND = 4096, kNT = 12288, kD = 256, kH = 4, kDH = 64;
constexpr int kB = 8, kKP = 768;
constexpr int kEC = 65536, kEI = 32768, kEO = 32768, kEK = 8192;
constexpr long LXD = (long)kNT * kD;
constexpr long LPD = (long)kB * kKP * kD;
constexpr long KRVB = 8L * kNI * 256;          // bf16 elems per branch (K rels 0-3, V 4-7)
constexpr long SLEN = (long)kB * kH * kKP * kKP;

constexpr int O0 = 0;
constexpr int O1 = kNI;
constexpr int O2 = kNI + kND;
constexpr int O3 = 2 * kNI + kND;
constexpr int O4 = 2 * kNI + 2 * kND;
constexpr int CNT_TOT = O4 + kNT;

constexpr int BB0 = kEC;
constexpr int BB1 = BB0 + kEI;
constexpr int BB2 = BB1 + kEK;
constexpr int BB3 = BB2 + kEO;
constexpr int BB4 = BB3 + kEC;
constexpr int BB5 = BB4 + kEO;
constexpr int BB6 = BB5 + kEK;
constexpr int BB7 = BB6 + kEI;
constexpr int BB8 = BB7 + kEC;
constexpr int BB9 = BB8 + kEI;
constexpr int BB10 = BB9 + kEO;
constexpr int BB11 = BB10 + kEK;
constexpr int BB12 = BB11 + kNT;

typedef __nv_bfloat16 bf16;
typedef __nv_bfloat162 bf162;

// ------------------------- scratch -------------------------
struct Scratch {
    bf16 x[2][LXD], yF[2][LXD], agg[2][LXD];
    bf16 kqv[2][3 * LXD];                     // [branch][node][768] K|Q|V
    bf16 krv[2][KRVB];                        // [relslot 0-7][node][256]
    bf16 S[2][SLEN];
    bf16 xp[2][LPD], qkvp[2][3 * LPD], oh[2][LPD], yb[2][LPD], ga[2][LPD];
    bf16 vT[2][(long)kB * kH * 64 * kKP];     // V transposed [b][h][dh][key]
    bf16 pW[8L * 768 * 256];                  // [combo*2+t][n][k]
    bf16 pTw[768L * 256];
    bf16 pRel[4L * 8 * 4 * 64 * 64];          // [combo][relslot][h][n][k]
    bf16 pWo[8L * 256 * 256];
    bf16 pTwo[256L * 256];
    float hv[2 * kNT], sc[2 * kNT];
    float sv[2 * kB * kKP];
    int   si[2 * kB * kKP];
    float u[2 * kB * 512];
    float up[2 * kB * 6 * 512];
    int rpf0[2][kNI + 1], rpf1[2][kND + 1], rpr0[2][kNI + 1], rpr1[2][kND + 1], rph[2][kNT + 1];
    int ef0[2][kEC + kEI + kEK], ef1[2][kEO], er0[2][kEC + kEO + kEK], er1[2][kEI];
    int eh[2][kEC + kEI + kEO + kEK + kNT];
    int cnt[CNT_TOT], cur[CNT_TOT];
};
__device__ Scratch SC;

// ------------------------- reductions -------------------------
__device__ __forceinline__ float wsum(float v) {
#pragma unroll
    for (int o = 16; o; o >>= 1) v += __shfl_xor_sync(0xffffffffu, v, o);
    return v;
}
__device__ __forceinline__ float bsum(float v) {
    __shared__ float sh[32];
    int lane = threadIdx.x & 31, w = threadIdx.x >> 5;
    v = wsum(v);
    if (!lane) sh[w] = v;
    __syncthreads();
    int nw = blockDim.x >> 5;
    float s = (threadIdx.x < nw) ? sh[threadIdx.x] : 0.f;
    if (w == 0) s = wsum(s);
    if (threadIdx.x == 0) sh[0] = s;
    __syncthreads();
    float r = sh[0];
    __syncthreads();
    return r;
}
__device__ __forceinline__ float bmax(float v) {
    __shared__ float sh[32];
    int lane = threadIdx.x & 31, w = threadIdx.x >> 5;
#pragma unroll
    for (int o = 16; o; o >>= 1) v = fmaxf(v, __shfl_xor_sync(0xffffffffu, v, o));
    if (!lane) sh[w] = v;
    __syncthreads();
    int nw = blockDim.x >> 5;
    float s = (threadIdx.x < nw) ? sh[threadIdx.x] : -INFINITY;
    if (w == 0)
#pragma unroll
        for (int o = 16; o; o >>= 1) s = fmaxf(s, __shfl_xor_sync(0xffffffffu, s, o));
    if (threadIdx.x == 0) sh[0] = s;
    __syncthreads();
    float r = sh[0];
    __syncthreads();
    return r;
}

// ------------------------- bf16 mma helpers -------------------------
__device__ __forceinline__ void mma_bf16(float* c, const uint32_t* a,
                                         uint32_t b0, uint32_t b1) {
    asm volatile(
        "mma.sync.aligned.m16n8k16.row.col.f32.bf16.bf16.f32 "
        "{%0,%1,%2,%3}, {%4,%5,%6,%7}, {%8,%9}, {%0,%1,%2,%3};"
        : "+f"(c[0]), "+f"(c[1]), "+f"(c[2]), "+f"(c[3])
        : "r"(a[0]), "r"(a[1]), "r"(a[2]), "r"(a[3]), "r"(b0), "r"(b1));
}
__device__ __forceinline__ void cpa16(void* dst, const void* src) {
    unsigned d = (unsigned)__cvta_generic_to_shared(dst);
    asm volatile("cp.async.cg.shared.global [%0], [%1], 16;\n" :: "r"(d), "l"(src));
}
#define CP_COMMIT() asm volatile("cp.async.commit_group;\n" ::: "memory")
#define CP_WAIT1()  asm volatile("cp.async.wait_group 1;\n" ::: "memory")
#define CP_WAIT0()  asm volatile("cp.async.wait_group 0;\n" ::: "memory")

// ------------------------- generic bf16 GEMM (cp.async pipelined) --------
template <int BN>
__global__ void __launch_bounds__(256, 2) hgemm_k(
    const bf16* __restrict__ A, int lda, long A2, long Ab, long Ah,
    const bf16* __restrict__ Bm, int ldb, long B2, long Bb, long Bh,
    bf16* __restrict__ C, int ldc, long C2, long Cb, long Ch,
    const bf16* __restrict__ Add, int ldadd, const bf16* __restrict__ Add2,
    const float* __restrict__ gptr,
    int Kdim, int ZH, int ZT, float alpha, int mode,
    unsigned zmask, long Aalt, int Malt, int Mdef, long Valt, int zsplit)
{
    constexpr int BM = 128, BK = 32;
    constexpr int STR = 40;
    constexpr int TN = (BN == 128) ? 8 : 4;
    extern __shared__ bf16 smh_[];
    bf16* As = smh_;
    bf16* Bs = smh_ + 2 * BM * STR;

    int z = blockIdx.z;
    int z2 = z / ZT, rz = z - z2 * ZT;
    int zb = rz / ZH, zh = rz - zb * ZH;
    int msk = (zmask >> zb) & 1;
    int Mz = msk ? Malt : Mdef;
    int m0 = blockIdx.x * BM;
    if (m0 >= Mz) return;
    const bf16* Ax = A + z2 * A2 + zb * Ab + zh * Ah + (msk ? Aalt : 0)
                       + (zb >= zsplit ? Valt : 0);
    const bf16* Bx = Bm + z2 * B2 + zb * Bb + zh * Bh;
    long coff = z2 * C2 + zb * Cb + zh * Ch;
    C += coff;
    if (Add)  Add  += coff;
    if (Add2) Add2 += coff;
    int n0 = blockIdx.y * BN;
    int tid = threadIdx.x, lane = tid & 31, warp = tid >> 5;
    int wm = warp >> 1, wn = warp & 1;
    int g = lane >> 2, tg = lane & 3;

    float acc[2][TN][4];
#pragma unroll
    for (int i = 0; i < 2; i++)
#pragma unroll
        for (int j = 0; j < TN; j++)
#pragma unroll
            for (int q = 0; q < 4; q++) acc[i][j][q] = 0.f;

    int nt = Kdim / BK;

#define ISSUE(K0, Sg) do {                                                     \
        bf16* Ad = As + (Sg) * BM * STR;                                       \
        _Pragma("unroll")                                                      \
        for (int q = 0; q < 2; q++) {                                          \
            int f = tid + q * 256, row = f >> 2, kc = (f & 3) * 8;             \
            cpa16(Ad + row * STR + kc,                                         \
                  Ax + (long)(m0 + row) * lda + (K0) + kc);                    \
        }                                                                      \
        bf16* Bd = Bs + (Sg) * BN * STR;                                       \
        _Pragma("unroll")                                                      \
        for (int q = 0; q < BN / 64; q++) {                                    \
            int f = tid + q * 256, row = f >> 2, kc = (f & 3) * 8;             \
            cpa16(Bd + row * STR + kc,                                         \
                  Bx + (long)(n0 + row) * ldb + (K0) + kc);                    \
        }                                                                      \
    } while (0)

    ISSUE(0, 0);
    CP_COMMIT();

    for (int t = 0; t < nt; t++) {
        if (t + 1 < nt) {
            ISSUE((t + 1) * BK, (t + 1) & 1);
            CP_COMMIT();
            CP_WAIT1();
        } else {
            CP_WAIT0();
        }
        __syncthreads();
        const bf16* Ap = As + (size_t)(t & 1) * BM * STR;
        const bf16* Bp = Bs + (size_t)(t & 1) * BN * STR;
#pragma unroll
        for (int k16 = 0; k16 < 2; k16++) {
            int kb = k16 * 16;
            uint32_t a[2][4];
#pragma unroll
            for (int tm = 0; tm < 2; tm++) {
                int mr = wm * 32 + tm * 16;
                a[tm][0] = *(const uint32_t*)(Ap + (mr + g) * STR + kb + 2 * tg);
                a[tm][1] = *(const uint32_t*)(Ap + (mr + 8 + g) * STR + kb + 2 * tg);
                a[tm][2] = *(const uint32_t*)(Ap + (mr + g) * STR + kb + 2 * tg + 8);
                a[tm][3] = *(const uint32_t*)(Ap + (mr + 8 + g) * STR + kb + 2 * tg + 8);
            }
#pragma unroll
            for (int tn = 0; tn < TN; tn++) {
                int nc = wn * (TN * 8) + tn * 8 + g;
                uint32_t b0 = *(const uint32_t*)(Bp + nc * STR + kb + 2 * tg);
                uint32_t b1 = *(const uint32_t*)(Bp + nc * STR + kb + 2 * tg + 8);
#pragma unroll
                for (int tm = 0; tm < 2; tm++)
                    mma_bf16(acc[tm][tn], a[tm], b0, b1);
            }
        }
        __syncthreads();
    }
#undef ISSUE

    float gg = 1.f;
    if (mode == 1 || mode == 3) gg = 1.f / (1.f + expf(-gptr[zb]));
#pragma unroll
    for (int tm = 0; tm < 2; tm++) {
        long row0 = m0 + wm * 32 + tm * 16 + g;
#pragma unroll
        for (int tn = 0; tn < TN; tn++) {
            long col = n0 + wn * (TN * 8) + tn * 8 + tg * 2;
#pragma unroll
            for (int half = 0; half < 2; half++) {
                long r = row0 + half * 8;
                float vx = alpha * acc[tm][tn][half * 2 + 0];
                float vy = alpha * acc[tm][tn][half * 2 + 1];
                if (mode == 1) {
                    float2 ad = __bfloat1622float2(*(const bf162*)(Add + r * ldadd + col));
                    vx = gg * vx + (1.f - gg) * ad.x;
                    vy = gg * vy + (1.f - gg) * ad.y;
                } else if (mode == 2) {
                    float2 ad = __bfloat1622float2(*(const bf162*)(Add + r * ldadd + col));
                    vx += ad.x; vy += ad.y;
                } else if (mode == 3) {
                    float2 ad = __bfloat1622float2(*(const bf162*)(Add + r * ldadd + col));
                    float2 a2 = __bfloat1622float2(*(const bf162*)(Add2 + r * ldadd + col));
                    vx = 0.5f * (gg * vx + (1.f - gg) * ad.x) + 0.5f * a2.x;
                    vy = 0.5f * (gg * vy + (1.f - gg) * ad.y) + 0.5f * a2.y;
                    vx = vx > 0.f ? vx : 0.f;
                    vy = vy > 0.f ? vy : 0.f;
                }
                *(bf162*)(C + r * ldc + col) = __floats2bfloat162_rn(vx, vy);
            }
        }
    }
}

// ---------------- specialized Krel/Vrel kernel: A-tile reuse over 4 relations ----
// grid (96, 1, 16): z -> branch(2) x kv(2) x head(4). Block: 128 rows of kqv.
// For each relation r, B = pRel[combo][kv*4+r][h]; output krv[branch][(slot*kNI+crow)*256 + h*64].
__global__ void __launch_bounds__(256) krel_k(Scratch* sp, int combo, int dir) {
    constexpr int STR = 72;
    extern __shared__ bf16 smk_[];
    bf16* As = smk_;                 // [128][STR]
    bf16* Bs = smk_ + 128 * STR;     // [4][64][STR]
    int z = blockIdx.z;
    int branch = z >> 3, rem = z & 7;
    int kv = rem >> 2, h = rem & 3;
    int m0 = blockIdx.x * 128;
    int tid = threadIdx.x;
    const bf16* Aptr = sp->kqv[branch] + (long)m0 * 768 + kv * 512 + h * 64;
#pragma unroll
    for (int q = 0; q < 4; q++) {
        int f = tid + q * 256;
        int row = f >> 3, kc = (f & 7) * 8;
        cpa16(As + row * STR + kc, Aptr + (long)row * 768 + kc);
    }
#pragma unroll
    for (int r = 0; r < 4; r++) {
        const bf16* Bp = sp->pRel + (long)combo * 131072
                         + (((long)(kv * 4 + r) * 4 + h) * 4096);
        bf16* Bd = Bs + r * 64 * STR;
#pragma unroll
        for (int q = 0; q < 2; q++) {
            int f = tid + q * 256;
            int row = f >> 3, kc = (f & 7) * 8;
            cpa16(Bd + row * STR + kc, Bp + (long)row * 64 + kc);
        }
    }
    CP_COMMIT();
    CP_WAIT0();
    __syncthreads();
    int lane = tid & 31, warp = tid >> 5;
    int wm = warp >> 1, wn = warp & 1;
    int g = lane >> 2, tg = lane & 3;
    // preload A fragments for full K=64, shared across relations
    uint32_t a[2][4][4];
#pragma unroll
    for (int k16 = 0; k16 < 4; k16++) {
        int kb = k16 * 16;
#pragma unroll
        for (int tm = 0; tm < 2; tm++) {
            int mr = wm * 32 + tm * 16;
            a[tm][k16][0] = *(const uint32_t*)(As + (mr + g) * STR + kb + 2 * tg);
            a[tm][k16][1] = *(const uint32_t*)(As + (mr + 8 + g) * STR + kb + 2 * tg);
            a[tm][k16][2] = *(const uint32_t*)(As + (mr + g) * STR + kb + 2 * tg + 8);
            a[tm][k16][3] = *(const uint32_t*)(As + (mr + 8 + g) * STR + kb + 2 * tg + 8);
        }
    }
#pragma unroll
    for (int r = 0; r < 4; r++) {
        int srcData = (dir == 0) ? (r == 1) : (r == 2);
        if (srcData ? (m0 < 8192) : (m0 >= 8192)) continue;
        const bf16* Bp = Bs + r * 64 * STR;
        float acc[2][4][4];
#pragma unroll
        for (int i = 0; i < 2; i++)
#pragma unroll
            for (int j = 0; j < 4; j++)
#pragma unroll
                for (int q = 0; q < 4; q++) acc[i][j][q] = 0.f;
#pragma unroll
        for (int k16 = 0; k16 < 4; k16++) {
            int kb = k16 * 16;
#pragma unroll
            for (int tn = 0; tn < 4; tn++) {
                int nc = wn * 32 + tn * 8 + g;
                uint32_t b0 = *(const uint32_t*)(Bp + nc * STR + kb + 2 * tg);
                uint32_t b1 = *(const uint32_t*)(Bp + nc * STR + kb + 2 * tg + 8);
                mma_bf16(acc[0][tn], a[0][k16], b0, b1);
                mma_bf16(acc[1][tn], a[1][k16], b0, b1);
            }
        }
        int slot = kv * 4 + r;
        long crow0 = m0 - (srcData ? 8192 : 0);
        bf16* C = sp->krv[branch] + ((long)slot * kNI + crow0) * 256 + h * 64;
#pragma unroll
        for (int tm = 0; tm < 2; tm++) {
            long row0 = wm * 32 + tm * 16 + g;
#pragma unroll
            for (int tn = 0; tn < 4; tn++) {
                long col = wn * 32 + tn * 8 + tg * 2;
#pragma unroll
                for (int half = 0; half < 2; half++) {
                    long rr = row0 + half * 8;
                    *(bf162*)(C + rr * 256 + col) =
                        __floats2bfloat162_rn(acc[tm][tn][half * 2 + 0],
                                              acc[tm][tn][half * 2 + 1]);
                }
            }
        }
    }
}

// ------------------------- fused weight packing (all -> bf16, [n][k]) -------
constexpr long PW = 8L * 768 * 256;
constexpr long PT = 768L * 256;
constexpr long PR = 4L * 8 * 4 * 4096;
constexpr long PO = 8L * 256 * 256;
constexpr long P2 = 256L * 256;
__global__ void pack_all_k(const float* __restrict__ Wk, const float* __restrict__ Wq,
                           const float* __restrict__ Wv, const float* __restrict__ tWq,
                           const float* __restrict__ tWk, const float* __restrict__ tWv,
                           const float* __restrict__ arel, const float* __restrict__ mrel,
                           const float* __restrict__ Wo, const float* __restrict__ tWo,
                           Scratch* sp) {
    long i = (long)blockIdx.x * 256 + threadIdx.x;
    if (i < PW) {
        long c = i / (768 * 256), r = i % (768 * 256);
        int n = (int)(r / 256), k = (int)(r % 256);
        int sel = n >> 8, nn = n & 255;
        const float* W = (sel == 0) ? Wk : (sel == 1) ? Wq : Wv;
        sp->pW[i] = __float2bfloat16(W[c * 65536 + (long)k * 256 + nn]);
    } else if (i < PW + PT) {
        long j = i - PW;
        int n = (int)(j / 256), k = (int)(j % 256);
        int sel = n >> 8, nn = n & 255;
        const float* W = (sel == 0) ? tWq : (sel == 1) ? tWk : tWv;
        sp->pTw[j] = __float2bfloat16(W[(long)k * 256 + nn]);
    } else if (i < PW + PT + PR) {
        long j = i - PW - PT;
        int k  = (int)(j & 63);
        int n  = (int)((j >> 6) & 63);
        int hh = (int)((j >> 12) & 3);
        int zr = (int)((j >> 14) & 7);
        int c  = (int)(j >> 17);
        const float* src = (zr < 4) ? arel : mrel;
        int rr = zr & 3;
        sp->pRel[j] = __float2bfloat16(src[(((long)(c * 4 + rr) * 4 + hh) << 12) + k * 64 + n]);
    } else if (i < PW + PT + PR + PO) {
        long j = i - PW - PT - PR;
        long c = j / 65536, r = j % 65536;
        int n = (int)(r / 256), k = (int)(r % 256);
        sp->pWo[j] = __float2bfloat16(Wo[c * 65536 + (long)k * 256 + n]);
    } else if (i < PW + PT + PR + PO + P2) {
        long j = i - PW - PT - PR - PO;
        int n = (int)(j / 256), k = (int)(j % 256);
        sp->pTwo[j] = __float2bfloat16(tWo[(long)k * 256 + n]);
    }
}

// ------------------------- elementwise -------------------------
__global__ void assemble_x_k(const float* __restrict__ xi0, const float* __restrict__ xd0,
                             const float* __restrict__ xi1, const float* __restrict__ xd1,
                             Scratch* sp) {
    long i = ((long)blockIdx.x * blockDim.x + threadIdx.x) * 4;
    if (i < 2 * LXD) {
        const long T1 = (long)kNI * kD;
        int br = i >= LXD;
        long loc = i - (long)br * LXD;
        const float* xi = br ? xi1 : xi0;
        const float* xd = br ? xd1 : xd0;
        float4 v = (loc < T1) ? *(const float4*)(xi + loc) : *(const float4*)(xd + (loc - T1));
        bf162 h0 = __floats2bfloat162_rn(v.x, v.y);
        bf162 h1 = __floats2bfloat162_rn(v.z, v.w);
        *(bf162*)(&sp->x[0][0] + i) = h0;
        *(bf162*)(&sp->x[0][0] + i + 2) = h1;
    }
}
__global__ void vtrans_k(Scratch* sp) {
    long i = (long)blockIdx.x * blockDim.x + threadIdx.x;
    if (i >= 2L * kB * kH * 64 * kKP) return;
    int key = (int)(i % kKP);
    long r = i / kKP;
    int dh = (int)(r & 63);
    long r2 = r >> 6;
    int h = (int)(r2 & 3);
    long r3 = r2 >> 2;
    int b = (int)(r3 & 7);
    int br = (int)(r3 >> 3);
    sp->vT[br][(((long)b * 4 + h) * 64 + dh) * kKP + key] =
        sp->qkvp[br][((long)b * kKP + key) * 768 + 512 + h * 64 + dh];
}

// ------------------------- fused CSR construction -------------------------
struct Slot { int idx; int ent; int arr; };
__device__ __forceinline__ Slot decode_slot(
    int i, const int* rc, const int* cc, const int* ri, const int* ci,
    const int* ro, const int* co, const int* rk, const int* ck)
{
    Slot s;
    if (i < BB0)       { s.idx = O0 + cc[i];            s.ent = (0 << 16) | rc[i];            s.arr = 0; }
    else if (i < BB1)  { int j = i - BB0;  s.idx = O0 + ci[j]; s.ent = (1 << 16) | ri[j];     s.arr = 0; }
    else if (i < BB2)  { int j = i - BB1;  s.idx = O0 + ck[j]; s.ent = (3 << 16) | rk[j];     s.arr = 0; }
    else if (i < BB3)  { int j = i - BB2;  s.idx = O1 + co[j]; s.ent = (2 << 16) | ro[j];     s.arr = 1; }
    else if (i < BB4)  { int j = i - BB3;  s.idx = O2 + rc[j]; s.ent = (0 << 16) | cc[j];     s.arr = 2; }
    else if (i < BB5)  { int j = i - BB4;  s.idx = O2 + ro[j]; s.ent = (2 << 16) | co[j];     s.arr = 2; }
    else if (i < BB6)  { int j = i - BB5;  s.idx = O2 + rk[j]; s.ent = (3 << 16) | ck[j];     s.arr = 2; }
    else if (i < BB7)  { int j = i - BB6;  s.idx = O3 + ri[j]; s.ent = (1 << 16) | ci[j];     s.arr = 3; }
    else if (i < BB8)  { int j = i - BB7;  s.idx = O4 + cc[j]; s.ent = rc[j];                 s.arr = 4; }
    else if (i < BB9)  { int j = i - BB8;  s.idx = O4 + ci[j]; s.ent = ri[j] + kNI;           s.arr = 4; }
    else if (i < BB10) { int j = i - BB9;  s.idx = O4 + co[j] + kNI; s.ent = ro[j];           s.arr = 4; }
    else               { int j = i - BB10; s.idx = O4 + ck[j]; s.ent = rk[j];                 s.arr = 4; }
    return s;
}

__global__ void csr_count_k(Scratch* sp, const int* rc, const int* cc,
                            const int* ri, const int* ci, const int* ro, const int* co,
                            const int* rk, const int* ck) {
    int i = blockIdx.x * blockDim.x + threadIdx.x;
    if (i < BB11) {
        Slot s = decode_slot(i, rc, cc, ri, ci, ro, co, rk, ck);
        atomicAdd(&sp->cnt[s.idx], 1);
    }
}
__global__ void csr_scan_k(Scratch* sp, int br) {
    __shared__ int sh[1024];
    int region = blockIdx.x, t = threadIdx.x;
    int off, n, extra = 0;
    int* rp;
    switch (region) {
        case 0: off = O0; n = kNI; rp = sp->rpf0[br]; break;
        case 1: off = O1; n = kND; rp = sp->rpf1[br]; break;
        case 2: off = O2; n = kNI; rp = sp->rpr0[br]; break;
        case 3: off = O3; n = kND; rp = sp->rpr1[br]; break;
        default: off = O4; n = kNT; rp = sp->rph[br]; extra = 1; break;
    }
    int c = (n + 1023) >> 10;
    int beg = t * c, end = min(beg + c, n);
    int s = 0;
    for (int i = beg; i < end; i++) s += sp->cnt[off + i] + extra;
    sh[t] = s;
    __syncthreads();
    for (int o = 1; o < 1024; o <<= 1) {
        int v = (t >= o) ? sh[t - o] : 0;
        __syncthreads();
        sh[t] += v;
        __syncthreads();
    }
    int run = t ? sh[t - 1] : 0;
    for (int i = beg; i < end; i++) {
        int cv = sp->cnt[off + i];
        sp->cnt[off + i] = 0;
        rp[i] = run;
        sp->cur[off + i] = run;
        run += cv + extra;
    }
    if (t == 1023) rp[n] = sh[1023];
}
__global__ void csr_fill_k(Scratch* sp, int br, const int* rc, const int* cc,
                           const int* ri, const int* ci, const int* ro, const int* co,
                           const int* rk, const int* ck) {
    int i = blockIdx.x * blockDim.x + threadIdx.x;
    if (i >= BB12) return;
    if (i < BB11) {
        Slot s = decode_slot(i, rc, cc, ri, ci, ro, co, rk, ck);
        int pos = atomicAdd(&sp->cur[s.idx], 1);
        switch (s.arr) {
            case 0: sp->ef0[br][pos] = s.ent; break;
            case 1: sp->ef1[br][pos] = s.ent; break;
            case 2: sp->er0[br][pos] = s.ent; break;
            case 3: sp->er1[br][pos] = s.ent; break;
            default: sp->eh[br][pos] = s.ent; break;
        }
    } else {
        int node = i - BB11;
        int pos = atomicAdd(&sp->cur[O4 + node], 1);
        sp->eh[br][pos] = node;
    }
}

// ------------------- HGT softmax aggregation (bf16 everywhere) --------------
__global__ void hgt_agg_k(Scratch* sp, int dir, const float* __restrict__ prel) {
    int nb = blockIdx.x;
    int branch = nb >= kNT;
    int node = nb - branch * kNT;
    const int *rp, *ent; int idx;
    if (dir == 0) {
        if (node < kNI) { rp = sp->rpf0[branch]; ent = sp->ef0[branch]; idx = node; }
        else            { rp = sp->rpf1[branch]; ent = sp->ef1[branch]; idx = node - kNI; }
    } else {
        if (node < kNI) { rp = sp->rpr0[branch]; ent = sp->er0[branch]; idx = node; }
        else            { rp = sp->rpr1[branch]; ent = sp->er1[branch]; idx = node - kNI; }
    }
    int h = threadIdx.x >> 5, lane = threadIdx.x & 31;
    long hoff = h * 64 + 2 * lane;
    float2 qq = __bfloat1622float2(
        *(const bf162*)(sp->kqv[branch] + (long)node * 768 + 256 + hoff));
    float q0 = qq.x, q1 = qq.y;
    const bf16* krv = sp->krv[branch];
    float pr0 = prel[0 * kH + h], pr1 = prel[1 * kH + h];
    float pr2 = prel[2 * kH + h], pr3 = prel[3 * kH + h];
    int s = rp[idx], eend = rp[idx + 1];
    float m = -INFINITY, den = 0.f, a0 = 0.f, a1 = 0.f;
    int e = s;
    for (; e + 1 < eend; e += 2) {
        int pkA = ent[e], pkB = ent[e + 1];
        int rA = pkA >> 16, sA = pkA & 0xffff;
        int rB = pkB >> 16, sB = pkB & 0xffff;
        float2 kA = __bfloat1622float2(
            *(const bf162*)(krv + ((long)rA * kNI + sA) * 256 + hoff));
        float2 kB2 = __bfloat1622float2(
            *(const bf162*)(krv + ((long)rB * kNI + sB) * 256 + hoff));
        float2 vA = __bfloat1622float2(
            *(const bf162*)(krv + ((long)(rA + 4) * kNI + sA) * 256 + hoff));
        float2 vB = __bfloat1622float2(
            *(const bf162*)(krv + ((long)(rB + 4) * kNI + sB) * 256 + hoff));
        float dA = q0 * kA.x + q1 * kA.y;
        float dB = q0 * kB2.x + q1 * kB2.y;
#pragma unroll
        for (int o = 16; o; o >>= 1) {
            dA += __shfl_xor_sync(0xffffffffu, dA, o);
            dB += __shfl_xor_sync(0xffffffffu, dB, o);
        }
        float prA = (rA == 0) ? pr0 : (rA == 1) ? pr1 : (rA == 2) ? pr2 : pr3;
        float prB = (rB == 0) ? pr0 : (rB == 1) ? pr1 : (rB == 2) ? pr2 : pr3;
        float scA = dA * prA * 0.125f, scB = dB * prB * 0.125f;
        float mn = fmaxf(m, fmaxf(scA, scB));
        float cc = expf(m - mn), wA = expf(scA - mn), wB = expf(scB - mn);
        den = den * cc + wA + wB;
        a0 = a0 * cc + wA * vA.x + wB * vB.x;
        a1 = a1 * cc + wA * vA.y + wB * vB.y;
        m = mn;
    }
    if (e < eend) {
        int pk = ent[e];
        int r = pk >> 16, src = pk & 0xffff;
        float2 kk = __bfloat1622float2(
            *(const bf162*)(krv + ((long)r * kNI + src) * 256 + hoff));
        float2 vv = __bfloat1622float2(
            *(const bf162*)(krv + ((long)(r + 4) * kNI + src) * 256 + hoff));
        float d0 = q0 * kk.x + q1 * kk.y;
        d0 = wsum(d0);
        float pr = (r == 0) ? pr0 : (r == 1) ? pr1 : (r == 2) ? pr2 : pr3;
        float sc2 = d0 * pr * 0.125f;
        float mn = fmaxf(m, sc2);
        float cc = expf(m - mn), w = expf(sc2 - mn);
        den = den * cc + w;
        a0 = a0 * cc + w * vv.x;
        a1 = a1 * cc + w * vv.y;
        m = mn;
    }
    float inv = 1.f / (den + 1e-16f);
    float r0 = a0 * inv, r1 = a1 * inv;
    float g0 = 0.5f * r0 * (1.f + erff(r0 * 0.7071067811865475f));
    float g1 = 0.5f * r1 * (1.f + erff(r1 * 0.7071067811865475f));
    *(bf162*)(sp->agg[branch] + (long)node * kD + hoff) = __floats2bfloat162_rn(g0, g1);
}

// ------------------------- pooling -------------------------
__global__ void hv_k(Scratch* sp, const float* __restrict__ pw) {
    int nb = blockIdx.x * 8 + (threadIdx.x >> 5);
    int lane = threadIdx.x & 31;
    if (nb >= 2 * kNT) return;
    const bf16* x = &sp->x[0][0];
    float s = 0.f;
    for (int d = lane * 2; d < kD; d += 64) {
        float2 v = __bfloat1622float2(*(const bf162*)(x + (long)nb * kD + d));
        s += v.x * pw[d] + v.y * pw[d + 1];
    }
    s = wsum(s);
    if (!lane) sp->hv[nb] = s;
}
__global__ void gat_score_k(Scratch* sp, const float* __restrict__ att,
                            const float* __restrict__ bias) {
    int i = blockIdx.x * blockDim.x + threadIdx.x;
    if (i >= 2 * kNT) return;
    int branch = i / kNT, ii = i - branch * kNT;
    const int* rp = sp->rph[branch];
    const int* ent = sp->eh[branch];
    float A0 = att[0], A1 = att[1];
    float hi = sp->hv[i];
    int s = rp[ii], e1 = rp[ii + 1];
    float m = -INFINITY, den = 0.f, acc = 0.f;
    int hb = branch * kNT;
    for (int e = s; e < e1; e++) {
        int src = ent[e] & 0xffff;
        float hs = sp->hv[hb + src];
        float ee = A0 * hs + A1 * hi;
        ee = ee >= 0.f ? ee : 0.2f * ee;
        float mn = fmaxf(m, ee);
        float c = expf(m - mn), w = expf(ee - mn);
        den = den * c + w;
        acc = acc * c + w * hs;
        m = mn;
    }
    sp->sc[i] = acc / (den + 1e-16f) + bias[0];
}

__global__ void topk_sort_k(Scratch* sp) {
    int bi = blockIdx.x;
    int branch = bi >> 3, b = bi & 7;
    int t = threadIdx.x;
    const float* sc = sp->sc + branch * kNT;
    __shared__ float v[2048];
    __shared__ int ix[2048];
    for (int p = t; p < 2048; p += 1024) {
        float val = -INFINITY;
        if (p < 1536) {
            int node = p < 1024 ? b * 1024 + p : kNI + b * 512 + (p - 1024);
            val = sc[node];
        }
        v[p] = val;
        ix[p] = p;
    }
    __syncthreads();
    for (int k = 2; k <= 2048; k <<= 1)
        for (int j = k >> 1; j > 0; j >>= 1) {
#pragma unroll
            for (int pass = 0; pass < 2; pass++) {
                int i = t + pass * 1024;
                int l = i ^ j;
                if (l > i) {
                    bool up = ((i & k) == 0);
                    float vi = v[i], vl = v[l];
                    int ii = ix[i], il = ix[l];
                    bool before = (vi > vl) || (vi == vl && ii < il);
                    if (up != before) {
                        v[i] = vl; v[l] = vi;
                        ix[i] = il; ix[l] = ii;
                    }
                }
            }
            __syncthreads();
        }
    if (t < kKP) {
        sp->sv[bi * kKP + t] = v[t];
        sp->si[bi * kKP + t] = ix[t];
    }
}
__global__ void gather_k(Scratch* sp) {
    int q = blockIdx.x, bi = blockIdx.y, d = threadIdx.x;
    int branch = bi >> 3, b = bi & 7;
    int j = sp->si[bi * kKP + q];
    float tv = tanhf(sp->sv[bi * kKP + q]);
    int node = j < 1024 ? b * 1024 + j : kNI + b * 512 + (j - 1024);
    float vv = __bfloat162float(sp->x[branch][(long)node * kD + d]) * tv;
    sp->xp[branch][((long)(b * kKP + q)) * kD + d] = __float2bfloat16(vv);
}

// ------------------------- transformer pieces -------------------------
__global__ void softmax_k(bf16* __restrict__ S) {
    long row = blockIdx.x;
    bf16* p = S + row * kKP;
    int t = threadIdx.x;
    float v0 = __bfloat162float(p[t]);
    float v1 = __bfloat162float(p[t + 256]);
    float v2 = __bfloat162float(p[t + 512]);
    float m = bmax(fmaxf(v0, fmaxf(v1, v2)));
    v0 = expf(v0 - m); v1 = expf(v1 - m); v2 = expf(v2 - m);
    float s = bsum(v0 + v1 + v2);
    float inv = 1.f / s;
    p[t] = __float2bfloat16(v0 * inv);
    p[t + 256] = __float2bfloat16(v1 * inv);
    p[t + 512] = __float2bfloat16(v2 * inv);
}
__global__ void ln_k(const bf16* __restrict__ y, const float* __restrict__ g,
                     const float* __restrict__ bta, bf16* __restrict__ out) {
    long row = blockIdx.x;
    int d = threadIdx.x;
    float v = __bfloat162float(y[row * kD + d]);
    float mu = bsum(v) * (1.f / kD);
    float df = v - mu;
    float var = bsum(df * df) * (1.f / kD);
    out[row * kD + d] = __float2bfloat16(g[d] * df * rsqrtf(var + 1e-5f) + bta[d]);
}
__global__ void featsum_part_k(Scratch* sp) {
    int bi = blockIdx.x, ch = blockIdx.y, d = threadIdx.x;
    int branch = bi >> 3, b = bi & 7;
    const bf16* xp = sp->xp[branch];
    const bf16* ga = sp->ga[branch];
    float s1 = 0.f, s2 = 0.f;
    int q0 = ch * 128;
    for (int q = q0; q < q0 + 128; q++) {
        long o = ((long)(b * kKP + q)) * kD + d;
        s1 += __bfloat162float(xp[o]);
        s2 += __bfloat162float(ga[o]);
    }
    sp->up[(bi * 6 + ch) * 512 + d] = s1;
    sp->up[(bi * 6 + ch) * 512 + 256 + d] = s2;
}
__global__ void featsum_red_k(Scratch* sp) {
    int bi = blockIdx.x, d = threadIdx.x;
    float s = 0.f;
    for (int ch = 0; ch < 6; ch++) s += sp->up[(bi * 6 + ch) * 512 + d];
    sp->u[bi * 512 + d] = s;
}
__global__ void cos_k(const float* __restrict__ u, float* __restrict__ out) {
    int b = blockIdx.x, t = threadIdx.x;
    float a = u[b * 512 + t];
    float c = u[(kB + b) * 512 + t];
    float dot = bsum(a * c);
    float na = bsum(a * a);
    float nc = bsum(c * c);
    if (t == 0)
        out[b] = dot / (fmaxf(sqrtf(na), 1e-8f) * fmaxf(sqrtf(nc), 1e-8f));
}

// ------------------------- host orchestration -------------------------
static void gemm(const bf16* A, int lda, long A2, long Ab, long Ah,
                 const bf16* Bm, int ldb, long B2, long Bb, long Bh,
                 bf16* C, int ldc, long C2, long Cb, long Ch,
                 const bf16* Add, int ldadd, const bf16* Add2, const float* gptr,
                 int M, int N, int K, int ZC, int ZB, int ZH, float alpha, int mode,
                 unsigned zmask = 0, long Aalt = 0, int Malt = 0,
                 long Valt = 0, int zsplit = 1 << 30) {
    int ZT = ZB * ZH;
    if (N % 128 == 0) {
        int sm = (2 * 128 * 40 + 2 * 128 * 40) * 2;
        dim3 g(M / 128, N / 128, ZC * ZT), blk(256);
        cudaFuncSetAttribute(hgemm_k<128>, cudaFuncAttributeMaxDynamicSharedMemorySize, sm);
        hgemm_k<128><<<g, blk, sm>>>(A, lda, A2, Ab, Ah, Bm, ldb, B2, Bb, Bh,
                                     C, ldc, C2, Cb, Ch, Add, ldadd, Add2, gptr,
                                     K, ZH, ZT, alpha, mode, zmask, Aalt, Malt, M,
                                     Valt, zsplit);
    } else {
        int sm = (2 * 128 * 40 + 2 * 64 * 40) * 2;
        dim3 g(M / 128, N / 64, ZC * ZT), blk(256);
        cudaFuncSetAttribute(hgemm_k<64>, cudaFuncAttributeMaxDynamicSharedMemorySize, sm);
        hgemm_k<64><<<g, blk, sm>>>(A, lda, A2, Ab, Ah, Bm, ldb, B2, Bb, Bh,
                                    C, ldc, C2, Cb, Ch, Add, ldadd, Add2, gptr,
                                    K, ZH, ZT, alpha, mode, zmask, Aalt, Malt, M,
                                    Valt, zsplit);
    }
}

extern "C" void kernel_launch(void* const* d_in, const int* in_sizes, int n_in,
                              void* d_out, int out_size) {
    Scratch* sp = nullptr;
    cudaGetSymbolAddress((void**)&sp, SC);

    const float* Wk    = (const float*)d_in[12];
    const float* Wq    = (const float*)d_in[13];
    const float* Wv    = (const float*)d_in[14];
    const float* Wo    = (const float*)d_in[15];
    const float* arel  = (const float*)d_in[16];
    const float* mrel  = (const float*)d_in[17];
    const float* prel  = (const float*)d_in[18];
    const float* skip  = (const float*)d_in[19];
    const float* poolW = (const float*)d_in[20];
    const float* poolA = (const float*)d_in[21];
    const float* poolB = (const float*)d_in[22];
    const float* tWq   = (const float*)d_in[23];
    const float* tWk   = (const float*)d_in[24];
    const float* tWv   = (const float*)d_in[25];
    const float* tWo   = (const float*)d_in[26];
    const float* lng   = (const float*)d_in[27];
    const float* lnb   = (const float*)d_in[28];

    const long T1 = (long)kNI * kD;
    const long KQVB = 3 * LXD;

    pack_all_k<<<(int)((PW + PT + PR + PO + P2 + 255) / 256), 256>>>(
        Wk, Wq, Wv, tWq, tWk, tWv, arel, mrel, Wo, tWo, sp);
    assemble_x_k<<<(int)(2 * LXD / 4 + 255) / 256, 256>>>(
        (const float*)d_in[0], (const float*)d_in[1],
        (const float*)d_in[6], (const float*)d_in[7], sp);

    const int krel_smem = (128 * 72 + 4 * 64 * 72) * 2;
    cudaFuncSetAttribute(krel_k, cudaFuncAttributeMaxDynamicSharedMemorySize, krel_smem);

    bool csr_done = false;

    for (int l = 0; l < 2; l++) {
        for (int dir = 0; dir < 2; dir++) {
            int combo = l * 2 + dir;
            // QKV: z = (branch:2) x (type:2 via zb mask)
            gemm(&sp->x[0][0], kD, LXD, 0, 0,
                 sp->pW + (long)(combo * 2) * 768 * 256, 256, 0, 768 * 256, 0,
                 &sp->kqv[0][0], 768, KQVB, (long)kNI * 768, 0,
                 nullptr, 0, nullptr, nullptr,
                 kNI, 768, kD, 2, 2, 1, 1.f, 0,
                 0x2u, T1, kND);
            // Krel+Vrel: specialized A-reuse kernel
            krel_k<<<dim3(96, 1, 16), 256, krel_smem>>>(sp, combo, dir);
            if (!csr_done) {
                for (int br = 0; br < 2; br++) {
                    const int* e = (const int*)d_in[br * 6 + 2];
                    const int *rc = e, *cc = e + kEC;
                    const int* e2 = (const int*)d_in[br * 6 + 3];
                    const int *ri = e2, *ci = e2 + kEI;
                    const int* e3 = (const int*)d_in[br * 6 + 4];
                    const int *ro = e3, *co = e3 + kEO;
                    const int* e4 = (const int*)d_in[br * 6 + 5];
                    const int *rk = e4, *ck = e4 + kEK;
                    csr_count_k<<<(BB11 + 255) / 256, 256>>>(sp, rc, cc, ri, ci, ro, co, rk, ck);
                    csr_scan_k<<<5, 1024>>>(sp, br);
                    csr_fill_k<<<(BB12 + 255) / 256, 256>>>(sp, br, rc, cc, ri, ci, ro, co, rk, ck);
                }
                csr_done = true;
            }
            hgt_agg_k<<<2 * kNT, 128>>>(sp, dir, prel + (long)(combo * 4) * kH);
            // Wo: z = (branch:2) x (type:2 via zb mask)
            const float* gp = skip + combo * 2;
            if (dir == 0)
                gemm(&sp->agg[0][0], kD, LXD, 0, 0,
                     sp->pWo + (long)(combo * 2) * 65536, 256, 0, 65536, 0,
                     &sp->yF[0][0], kD, LXD, T1, 0, &sp->x[0][0], kD, nullptr, gp,
                     kNI, kD, kD, 2, 2, 1, 1.f, 1,
                     0x2u, T1, kND);
            else
                gemm(&sp->agg[0][0], kD, LXD, 0, 0,
                     sp->pWo + (long)(combo * 2) * 65536, 256, 0, 65536, 0,
                     &sp->x[0][0], kD, LXD, T1, 0, &sp->x[0][0], kD, &sp->yF[0][0], gp,
                     kNI, kD, kD, 2, 2, 1, 1.f, 3,
                     0x2u, T1, kND);
        }
    }

    // pooling (both branches)
    hv_k<<<2 * kNT / 8, 256>>>(sp, poolW);
    gat_score_k<<<(2 * kNT + 255) / 256, 256>>>(sp, poolA, poolB);
    topk_sort_k<<<16, 1024>>>(sp);
    gather_k<<<dim3(kKP, 16), kD>>>(sp);

    // transformer attention (both branches)
    int Mp = kB * kKP;
    long pq = (long)kKP * 768;
    gemm(&sp->xp[0][0], kD, LPD, 0, 0, sp->pTw, 256, 0, 0, 0,
         &sp->qkvp[0][0], 768, 3 * LPD, 0, 0,
         nullptr, 0, nullptr, nullptr, Mp, 768, kD, 2, 1, 1, 1.f, 0);
    gemm(&sp->qkvp[0][0], 768, 3 * LPD, pq, kDH,
         &sp->qkvp[0][0] + 256, 768, 3 * LPD, pq, kDH,
         &sp->S[0][0], kKP, SLEN, (long)kH * kKP * kKP, (long)kKP * kKP,
         nullptr, 0, nullptr, nullptr,
         kKP, kKP, kDH, 2, kB, kH, 0.125f, 0);
    softmax_k<<<2 * kB * kH * kKP, 256>>>(&sp->S[0][0]);
    vtrans_k<<<(int)((2L * kB * kH * 64 * kKP + 255) / 256), 256>>>(sp);
    gemm(&sp->S[0][0], kKP, SLEN, (long)kH * kKP * kKP, (long)kKP * kKP,
         &sp->vT[0][0], kKP, (long)kB * kH * 64 * kKP, (long)kH * 64 * kKP, (long)64 * kKP,
         &sp->oh[0][0], kD, LPD, (long)kKP * kD, kDH,
         nullptr, 0, nullptr, nullptr,
         kKP, kDH, kKP, 2, kB, kH, 1.f, 0);
    gemm(&sp->oh[0][0], kD, LPD, 0, 0, sp->pTwo, 256, 0, 0, 0,
         &sp->yb[0][0], kD, LPD, 0, 0,
         &sp->xp[0][0], kD, nullptr, nullptr, Mp, kD, kD, 2, 1, 1, 1.f, 2);
    ln_k<<<2 * Mp, kD>>>(&sp->yb[0][0], lng, lnb, &sp->ga[0][0]);
    featsum_part_k<<<dim3(16, 6), 256>>>(sp);
    featsum_red_k<<<16, 512>>>(sp);
    cos_k<<<kB, 512>>>(sp->u, (float*)d_out);
}